// round 1
// baseline (speedup 1.0000x reference)
#include <cuda_runtime.h>
#include <math.h>
#include <stdint.h>

// Problem constants
#define Hd    256
#define Wdim  256
#define HWd   65536
#define Cd    192
#define Bd    4
#define NHd   6
#define HDd   32
#define NWINd 4096      // B * 32 * 32
#define MTOKd 262144    // B*H*W
#define HIDd  768
#define QSCALE 0.17677669529663687f  // 32^-0.5

// -------- scratch (device globals; no allocation allowed) --------
__device__ float g_xt  [(size_t)MTOKd * Cd];            // x in (b,h,w,c) token-major
__device__ float g_q   [(size_t)NWINd * NHd * 64 * HDd];
__device__ float g_kk  [(size_t)NWINd * NHd * 64 * HDd];
__device__ float g_vv  [(size_t)NWINd * NHd * 64 * HDd];
__device__ float g_attn[(size_t)NWINd * 64 * Cd];       // attention out, window layout
__device__ float g_proj[(size_t)MTOKd * Cd];            // proj out, pixel layout
__device__ float g_x1  [(size_t)MTOKd * Cd];            // after merge-LN + shortcut
__device__ float g_h1  [(size_t)MTOKd * HIDd];          // gelu(fc1)

__device__ __forceinline__ float warp_sum(float v) {
#pragma unroll
    for (int o = 16; o; o >>= 1) v += __shfl_xor_sync(0xffffffffu, v, o);
    return v;
}
__device__ __forceinline__ float warp_max(float v) {
#pragma unroll
    for (int o = 16; o; o >>= 1) v = fmaxf(v, __shfl_xor_sync(0xffffffffu, v, o));
    return v;
}

// ======================= K0: transpose x -> xt =======================
// x: (B, C, H, W) -> xt: (B, H*W, C)
__global__ void k_transpose(const float* __restrict__ x) {
    __shared__ float t[32][33];
    int b  = blockIdx.z;
    int c0 = blockIdx.x << 5;
    int p0 = blockIdx.y << 5;
    const float* src = x    + (size_t)b * Cd * HWd;
    float*       dst = g_xt + (size_t)b * HWd * Cd;
    int tx = threadIdx.x, ty = threadIdx.y;
#pragma unroll
    for (int i = ty; i < 32; i += 8)
        t[i][tx] = src[(size_t)(c0 + i) * HWd + p0 + tx];
    __syncthreads();
#pragma unroll
    for (int i = ty; i < 32; i += 8)
        dst[(size_t)(p0 + i) * Cd + c0 + tx] = t[tx][i];
}

// ======================= K1: gather + QKV GEMM =======================
// grid: (6 chunks, 2048 window-pairs). BM=128 (2 windows), BN=96, K=192.
// chunk 0,1 -> Q from x; 2,3 -> K from feat; 4,5 -> V from feat.
__global__ void __launch_bounds__(256, 1) k_qkv(
    const float* __restrict__ x, const float* __restrict__ feat,
    const float* __restrict__ q_w, const float* __restrict__ q_b,
    const float* __restrict__ kv_w, const float* __restrict__ kv_b)
{
    extern __shared__ float sm[];
    float* sA = sm;               // [128][194]
    float* sB = sm + 128 * 194;   // [96][193]
    int tid = threadIdx.x;
    int colbase = blockIdx.x * 96;
    int winbase = blockIdx.y * 2;
    const float* src  = (colbase < 192) ? x : feat;
    const float* Wsrc = (colbase < 192) ? (q_w + colbase * 192)
                                        : (kv_w + (colbase - 192) * 192);
    // gather A tile: 128 tokens x 192 channels (shifted-window source pixel)
    {
        int m  = tid & 127;
        int k0 = tid >> 7;
        int win = winbase + (m >> 6), n = m & 63;
        int b = win >> 10, wh = (win >> 5) & 31, ww = win & 31;
        int h = (wh * 8 + (n >> 3) + 4) & 255;
        int w = (ww * 8 + (n & 7) + 4) & 255;
        const float* sp = src + (size_t)b * Cd * HWd + h * Wdim + w;
        float* ap = sA + m * 194;
        for (int k = k0; k < 192; k += 2)
            ap[k] = sp[(size_t)k << 16];
    }
    // weights tile: 96 x 192
    for (int idx = tid; idx < 96 * 192; idx += 256) {
        int j = idx / 192, k = idx - j * 192;
        sB[j * 193 + k] = Wsrc[idx];
    }
    __syncthreads();

    int cx = tid & 15, ry = tid >> 4;
    int m0 = ry * 8;
    float acc[8][6];
#pragma unroll
    for (int v = 0; v < 8; v++)
#pragma unroll
        for (int u = 0; u < 6; u++) acc[v][u] = 0.f;

#pragma unroll 4
    for (int k = 0; k < 192; ++k) {
        float a[8], bb[6];
#pragma unroll
        for (int v = 0; v < 8; v++) a[v] = sA[(m0 + v) * 194 + k];
#pragma unroll
        for (int u = 0; u < 6; u++) bb[u] = sB[(cx + 16 * u) * 193 + k];
#pragma unroll
        for (int v = 0; v < 8; v++)
#pragma unroll
            for (int u = 0; u < 6; u++)
                acc[v][u] = fmaf(a[v], bb[u], acc[v][u]);
    }
    __syncthreads();
    // stage (bias / scale applied)
    float* St = sA;  // 128*96 fits
#pragma unroll
    for (int v = 0; v < 8; v++)
#pragma unroll
        for (int u = 0; u < 6; u++) {
            int j = cx + 16 * u;
            int col = colbase + j;
            float val = acc[v][u];
            if (colbase < 192) val = (val + q_b[col]) * QSCALE;
            else               val = val + kv_b[col - 192];
            St[(m0 + v) * 96 + j] = val;
        }
    __syncthreads();
    // coalesced scatter to q/k/v head layout
    for (int idx = tid; idx < 128 * 96; idx += 256) {
        int m = idx / 96, j = idx - m * 96;
        int col = colbase + j;
        int win = winbase + (m >> 6), n = m & 63;
        float val = St[idx];
        float* dp; int c;
        if      (col < 192) { dp = g_q;  c = col; }
        else if (col < 384) { dp = g_kk; c = col - 192; }
        else                { dp = g_vv; c = col - 384; }
        dp[(((size_t)win * NHd + (c >> 5)) * 64 + n) * HDd + (c & 31)] = val;
    }
}

// ======================= K2: attention =======================
// one CTA per (window, head). 256 threads = 8 warps, 8 rows each.
__global__ void __launch_bounds__(256, 1) k_attn(
    const float* __restrict__ mask, const int* __restrict__ relidx,
    const float* __restrict__ table)
{
    __shared__ float Qs[64][33], Ks[64][33], Vs[64][33], Ps[64][64];
    int cta  = blockIdx.x;
    int win  = cta / NHd, head = cta - win * NHd;
    int tid = threadIdx.x, wp = tid >> 5, l = tid & 31;
    size_t base = (size_t)cta * 64 * HDd;
    const float* qb = g_q  + base;
    const float* kb = g_kk + base;
    const float* vb = g_vv + base;
    for (int idx = tid; idx < 2048; idx += 256) {
        int r = idx >> 5, c = idx & 31;
        Qs[r][c] = qb[idx]; Ks[r][c] = kb[idx]; Vs[r][c] = vb[idx];
    }
    __syncthreads();
    const float* mrow = mask + (size_t)(win & 1023) * 4096;
#pragma unroll 1
    for (int r = 0; r < 8; r++) {
        int i = wp * 8 + r;
        int j0 = l, j1 = l + 32;
        float a0 = 0.f, a1 = 0.f;
#pragma unroll
        for (int d = 0; d < 32; d++) {
            float qd = Qs[i][d];
            a0 = fmaf(qd, Ks[j0][d], a0);
            a1 = fmaf(qd, Ks[j1][d], a1);
        }
        a0 += table[relidx[i * 64 + j0] * NHd + head] + mrow[i * 64 + j0];
        a1 += table[relidx[i * 64 + j1] * NHd + head] + mrow[i * 64 + j1];
        float mx = warp_max(fmaxf(a0, a1));
        float e0 = __expf(a0 - mx), e1 = __expf(a1 - mx);
        float s  = warp_sum(e0 + e1);
        float inv = 1.f / s;
        Ps[i][j0] = e0 * inv;
        Ps[i][j1] = e1 * inv;
    }
    __syncthreads();
    float* ob = g_attn + (size_t)win * 64 * Cd + head * HDd;
#pragma unroll 1
    for (int r = 0; r < 8; r++) {
        int i = wp * 8 + r;
        float acc = 0.f;
#pragma unroll 8
        for (int j = 0; j < 64; j++) acc = fmaf(Ps[i][j], Vs[j][l], acc);
        ob[i * Cd + l] = acc;
    }
}

// ======================= K3: proj + window-reverse scatter =======================
// grid: (2 chunks, 2048 window-pairs). BM=128, BN=96, K=192.
__global__ void __launch_bounds__(256, 1) k_proj(
    const float* __restrict__ pw, const float* __restrict__ pb)
{
    extern __shared__ float sm[];
    float* sA = sm;
    float* sB = sm + 128 * 194;
    __shared__ int ppix[128];
    int tid = threadIdx.x;
    int colbase = blockIdx.x * 96;
    size_t mbase = (size_t)blockIdx.y * 128;
    if (tid < 128) {
        int win = blockIdx.y * 2 + (tid >> 6);
        int n = tid & 63;
        int b = win >> 10, wh = (win >> 5) & 31, ww = win & 31;
        int h = (wh * 8 + (n >> 3) + 4) & 255;
        int w = (ww * 8 + (n & 7) + 4) & 255;
        ppix[tid] = (b << 16) | (h << 8) | w;
    }
    for (int idx = tid; idx < 128 * 192; idx += 256) {
        int m = idx / 192, k = idx - m * 192;
        sA[m * 194 + k] = g_attn[(mbase + m) * Cd + k];
    }
    for (int idx = tid; idx < 96 * 192; idx += 256) {
        int j = idx / 192, k = idx - j * 192;
        sB[j * 193 + k] = pw[(size_t)(colbase + j) * 192 + k];
    }
    __syncthreads();
    int cx = tid & 15, ry = tid >> 4;
    int m0 = ry * 8;
    float acc[8][6];
#pragma unroll
    for (int v = 0; v < 8; v++)
#pragma unroll
        for (int u = 0; u < 6; u++) acc[v][u] = 0.f;
#pragma unroll 4
    for (int k = 0; k < 192; ++k) {
        float a[8], bb[6];
#pragma unroll
        for (int v = 0; v < 8; v++) a[v] = sA[(m0 + v) * 194 + k];
#pragma unroll
        for (int u = 0; u < 6; u++) bb[u] = sB[(cx + 16 * u) * 193 + k];
#pragma unroll
        for (int v = 0; v < 8; v++)
#pragma unroll
            for (int u = 0; u < 6; u++)
                acc[v][u] = fmaf(a[v], bb[u], acc[v][u]);
    }
    __syncthreads();
    float* St = sA;
#pragma unroll
    for (int v = 0; v < 8; v++)
#pragma unroll
        for (int u = 0; u < 6; u++) {
            int j = cx + 16 * u;
            St[(m0 + v) * 96 + j] = acc[v][u] + pb[colbase + j];
        }
    __syncthreads();
    for (int idx = tid; idx < 128 * 96; idx += 256) {
        int m = idx / 96, j = idx - m * 96;
        g_proj[(size_t)ppix[m] * Cd + colbase + j] = St[idx];
    }
}

// ======================= K4: merge GEMM + LN(norm1) + shortcut =======================
// grid: 4096 CTAs. BM=64, BN=192 (full row -> LN in-CTA), K=192.
__global__ void __launch_bounds__(256, 1) k_merge(
    const float* __restrict__ mw, const float* __restrict__ g1,
    const float* __restrict__ b1)
{
    extern __shared__ float sm[];
    float* sA = sm;               // [64][194]
    float* sB = sm + 64 * 194;    // [192][193]
    int tid = threadIdx.x;
    size_t mbase = (size_t)blockIdx.x * 64;
    for (int idx = tid; idx < 64 * 192; idx += 256) {
        int m = idx / 192, k = idx - m * 192;
        sA[m * 194 + k] = g_proj[(mbase + m) * Cd + k];
    }
    for (int idx = tid; idx < 192 * 192; idx += 256) {
        int j = idx / 192, k = idx - j * 192;
        sB[j * 193 + k] = mw[idx];
    }
    __syncthreads();
    int cx = tid & 31, ry = tid >> 5;
    int m0 = ry * 8;
    float acc[8][6];
#pragma unroll
    for (int v = 0; v < 8; v++)
#pragma unroll
        for (int u = 0; u < 6; u++) acc[v][u] = 0.f;
#pragma unroll 4
    for (int k = 0; k < 192; ++k) {
        float a[8], bb[6];
#pragma unroll
        for (int v = 0; v < 8; v++) a[v] = sA[(m0 + v) * 194 + k];
#pragma unroll
        for (int u = 0; u < 6; u++) bb[u] = sB[(cx + 32 * u) * 193 + k];
#pragma unroll
        for (int v = 0; v < 8; v++)
#pragma unroll
            for (int u = 0; u < 6; u++)
                acc[v][u] = fmaf(a[v], bb[u], acc[v][u]);
    }
    __syncthreads();
    float* St = sA;  // 64*192 fits in 64*194
#pragma unroll
    for (int v = 0; v < 8; v++)
#pragma unroll
        for (int u = 0; u < 6; u++)
            St[(m0 + v) * 192 + cx + 32 * u] = acc[v][u];
    __syncthreads();
    int wp = tid >> 5, l = tid & 31;
#pragma unroll 1
    for (int rr = 0; rr < 8; rr++) {
        int r = wp * 8 + rr;
        float vv[6];
        float s = 0.f;
#pragma unroll
        for (int u = 0; u < 6; u++) { vv[u] = St[r * 192 + l + 32 * u]; s += vv[u]; }
        s = warp_sum(s);
        float mean = s * (1.f / 192.f);
        float sq = 0.f;
#pragma unroll
        for (int u = 0; u < 6; u++) { float d = vv[u] - mean; sq += d * d; }
        sq = warp_sum(sq);
        float rstd = rsqrtf(sq * (1.f / 192.f) + 1e-5f);
        size_t row = (mbase + r) * Cd;
#pragma unroll
        for (int u = 0; u < 6; u++) {
            int c = l + 32 * u;
            g_x1[row + c] = (vv[u] - mean) * rstd * g1[c] + b1[c] + g_xt[row + c];
        }
    }
}

// ======================= K5a: fc1 + exact GELU =======================
// grid: (8 chunks, 2048). BM=128, BN=96, K=192.
__global__ void __launch_bounds__(256, 1) k_fc1(
    const float* __restrict__ w1, const float* __restrict__ b1h)
{
    extern __shared__ float sm[];
    float* sA = sm;
    float* sB = sm + 128 * 194;
    int tid = threadIdx.x;
    int colbase = blockIdx.x * 96;
    size_t mbase = (size_t)blockIdx.y * 128;
    for (int idx = tid; idx < 128 * 192; idx += 256) {
        int m = idx / 192, k = idx - m * 192;
        sA[m * 194 + k] = g_x1[(mbase + m) * Cd + k];
    }
    for (int idx = tid; idx < 96 * 192; idx += 256) {
        int j = idx / 192, k = idx - j * 192;
        sB[j * 193 + k] = w1[(size_t)(colbase + j) * 192 + k];
    }
    __syncthreads();
    int cx = tid & 15, ry = tid >> 4;
    int m0 = ry * 8;
    float acc[8][6];
#pragma unroll
    for (int v = 0; v < 8; v++)
#pragma unroll
        for (int u = 0; u < 6; u++) acc[v][u] = 0.f;
#pragma unroll 4
    for (int k = 0; k < 192; ++k) {
        float a[8], bb[6];
#pragma unroll
        for (int v = 0; v < 8; v++) a[v] = sA[(m0 + v) * 194 + k];
#pragma unroll
        for (int u = 0; u < 6; u++) bb[u] = sB[(cx + 16 * u) * 193 + k];
#pragma unroll
        for (int v = 0; v < 8; v++)
#pragma unroll
            for (int u = 0; u < 6; u++)
                acc[v][u] = fmaf(a[v], bb[u], acc[v][u]);
    }
    __syncthreads();
    float* St = sA;
#pragma unroll
    for (int v = 0; v < 8; v++)
#pragma unroll
        for (int u = 0; u < 6; u++) {
            int j = cx + 16 * u;
            float val = acc[v][u] + b1h[colbase + j];
            val = 0.5f * val * (1.f + erff(val * 0.70710678118654752f));
            St[(m0 + v) * 96 + j] = val;
        }
    __syncthreads();
    for (int idx = tid; idx < 128 * 96; idx += 256) {
        int m = idx / 96, j = idx - m * 96;
        g_h1[(mbase + m) * HIDd + colbase + j] = St[idx];
    }
}

// ======================= K5b: fc2 + LN(norm2) + residual -> out =======================
// grid: 4096. BM=64, BN=192, K=768 in 4 chunks.
__global__ void __launch_bounds__(256, 1) k_fc2(
    const float* __restrict__ w2, const float* __restrict__ b2,
    const float* __restrict__ g2, const float* __restrict__ bb2,
    float* __restrict__ out)
{
    extern __shared__ float sm[];
    float* sA = sm;               // [64][194]
    float* sB = sm + 64 * 194;    // [192][193]
    int tid = threadIdx.x;
    size_t mbase = (size_t)blockIdx.x * 64;
    int cx = tid & 31, ry = tid >> 5;
    int m0 = ry * 8;
    float acc[8][6];
#pragma unroll
    for (int v = 0; v < 8; v++)
#pragma unroll
        for (int u = 0; u < 6; u++) acc[v][u] = 0.f;

    for (int kc = 0; kc < 4; kc++) {
        __syncthreads();
        for (int idx = tid; idx < 64 * 192; idx += 256) {
            int m = idx / 192, k = idx - m * 192;
            sA[m * 194 + k] = g_h1[(mbase + m) * HIDd + kc * 192 + k];
        }
        for (int idx = tid; idx < 192 * 192; idx += 256) {
            int j = idx / 192, k = idx - j * 192;
            sB[j * 193 + k] = w2[(size_t)j * HIDd + kc * 192 + k];
        }
        __syncthreads();
#pragma unroll 4
        for (int k = 0; k < 192; ++k) {
            float a[8], bb[6];
#pragma unroll
            for (int v = 0; v < 8; v++) a[v] = sA[(m0 + v) * 194 + k];
#pragma unroll
            for (int u = 0; u < 6; u++) bb[u] = sB[(cx + 32 * u) * 193 + k];
#pragma unroll
            for (int v = 0; v < 8; v++)
#pragma unroll
                for (int u = 0; u < 6; u++)
                    acc[v][u] = fmaf(a[v], bb[u], acc[v][u]);
        }
    }
    __syncthreads();
    float* St = sA;
#pragma unroll
    for (int v = 0; v < 8; v++)
#pragma unroll
        for (int u = 0; u < 6; u++) {
            int c = cx + 32 * u;
            St[(m0 + v) * 192 + c] = acc[v][u] + b2[c];
        }
    __syncthreads();
    int wp = tid >> 5, l = tid & 31;
#pragma unroll 1
    for (int rr = 0; rr < 8; rr++) {
        int r = wp * 8 + rr;
        float vv[6];
        float s = 0.f;
#pragma unroll
        for (int u = 0; u < 6; u++) { vv[u] = St[r * 192 + l + 32 * u]; s += vv[u]; }
        s = warp_sum(s);
        float mean = s * (1.f / 192.f);
        float sq = 0.f;
#pragma unroll
        for (int u = 0; u < 6; u++) { float d = vv[u] - mean; sq += d * d; }
        sq = warp_sum(sq);
        float rstd = rsqrtf(sq * (1.f / 192.f) + 1e-5f);
        size_t row = (mbase + r) * Cd;
#pragma unroll
        for (int u = 0; u < 6; u++) {
            int c = l + 32 * u;
            out[row + c] = g_x1[row + c] + (vv[u] - mean) * rstd * g2[c] + bb2[c];
        }
    }
}

// ======================= host =======================
extern "C" void kernel_launch(void* const* d_in, const int* in_sizes, int n_in,
                              void* d_out, int out_size)
{
    const float* x    = (const float*)d_in[0];
    const float* feat = (const float*)d_in[1];
    const float* mask = (const float*)d_in[2];
    const int*   ridx = (const int*)  d_in[3];
    const float* rtab = (const float*)d_in[4];
    const float* q_w  = (const float*)d_in[5];
    const float* q_b  = (const float*)d_in[6];
    const float* kv_w = (const float*)d_in[7];
    const float* kv_b = (const float*)d_in[8];
    const float* p_w  = (const float*)d_in[9];
    const float* p_b  = (const float*)d_in[10];
    const float* m_w  = (const float*)d_in[11];
    const float* n1g  = (const float*)d_in[12];
    const float* n1b  = (const float*)d_in[13];
    const float* n2g  = (const float*)d_in[14];
    const float* n2b  = (const float*)d_in[15];
    const float* f1w  = (const float*)d_in[16];
    const float* f1b  = (const float*)d_in[17];
    const float* f2w  = (const float*)d_in[18];
    const float* f2b  = (const float*)d_in[19];
    float* out = (float*)d_out;

    const int smBig  = (128 * 194 + 96 * 193) * (int)sizeof(float);   // 173440
    const int smWide = (64 * 194 + 192 * 193) * (int)sizeof(float);   // 197888
    cudaFuncSetAttribute(k_qkv,   cudaFuncAttributeMaxDynamicSharedMemorySize, smBig);
    cudaFuncSetAttribute(k_proj,  cudaFuncAttributeMaxDynamicSharedMemorySize, smBig);
    cudaFuncSetAttribute(k_fc1,   cudaFuncAttributeMaxDynamicSharedMemorySize, smBig);
    cudaFuncSetAttribute(k_merge, cudaFuncAttributeMaxDynamicSharedMemorySize, smWide);
    cudaFuncSetAttribute(k_fc2,   cudaFuncAttributeMaxDynamicSharedMemorySize, smWide);

    k_transpose<<<dim3(6, 2048, 4), dim3(32, 8)>>>(x);
    k_qkv  <<<dim3(6, 2048), 256, smBig>>>(x, feat, q_w, q_b, kv_w, kv_b);
    k_attn <<<NWINd * NHd, 256>>>(mask, ridx, rtab);
    k_proj <<<dim3(2, 2048), 256, smBig>>>(p_w, p_b);
    k_merge<<<4096, 256, smWide>>>(m_w, n1g, n1b);
    k_fc1  <<<dim3(8, 2048), 256, smBig>>>(f1w, f1b);
    k_fc2  <<<4096, 256, smWide>>>(f2w, f2b, n2g, n2b, out);
}

// round 2
// speedup vs baseline: 4.0290x; 4.0290x over previous
#include <cuda_runtime.h>
#include <math.h>
#include <stdint.h>

#define Hd    256
#define Wdim  256
#define HWd   65536
#define Cd    192
#define Bd    4
#define NHd   6
#define HDd   32
#define NWINd 4096
#define MTOKd 262144
#define HIDd  768
#define QSCALE 0.17677669529663687f

// -------- scratch --------
__device__ float g_xt  [(size_t)MTOKd * Cd];
__device__ float g_ft  [(size_t)MTOKd * Cd];
__device__ float g_q   [(size_t)NWINd * NHd * 64 * HDd];
__device__ float g_kk  [(size_t)NWINd * NHd * 64 * HDd];
__device__ float g_vv  [(size_t)NWINd * NHd * 64 * HDd];
__device__ float g_attn[(size_t)NWINd * 64 * Cd];
__device__ float g_proj[(size_t)MTOKd * Cd];
__device__ float g_x1  [(size_t)MTOKd * Cd];
__device__ float g_h1  [(size_t)MTOKd * HIDd];

__device__ __forceinline__ float warp_sum(float v) {
#pragma unroll
    for (int o = 16; o; o >>= 1) v += __shfl_xor_sync(0xffffffffu, v, o);
    return v;
}

__device__ __forceinline__ float tf32r(float v) {
    unsigned u;
    asm("cvt.rna.tf32.f32 %0, %1;" : "=r"(u) : "f"(v));
    return __uint_as_float(u);
}

__device__ __forceinline__ void sts_tf32(float* p, float4 v) {
    float4 t;
    t.x = tf32r(v.x); t.y = tf32r(v.y); t.z = tf32r(v.z); t.w = tf32r(v.w);
    *(float4*)p = t;
}

__device__ __forceinline__ void mma8(float* c, const float* a, const float* b) {
    asm volatile(
        "mma.sync.aligned.m16n8k8.row.col.f32.tf32.tf32.f32 "
        "{%0,%1,%2,%3}, {%4,%5,%6,%7}, {%8,%9}, {%0,%1,%2,%3};"
        : "+f"(c[0]), "+f"(c[1]), "+f"(c[2]), "+f"(c[3])
        : "r"(__float_as_uint(a[0])), "r"(__float_as_uint(a[1])),
          "r"(__float_as_uint(a[2])), "r"(__float_as_uint(a[3])),
          "r"(__float_as_uint(b[0])), "r"(__float_as_uint(b[1])));
}

// ======================= tf32 GEMM core =======================
// BM x BN CTA tile, 8 warps as (BM/32) x (BN/48) grid of 32x48 warp tiles.
// K chunks of 32, double-buffered via register staging (LDG -> cvt -> STS).
template<int BM, int BN, int NC>
__device__ __forceinline__ void gemm_core(
    const float* const* aP, const float* const* bP,
    float* sm, float (&acc)[2][6][4], int tid)
{
    constexpr int nA  = BM / 32;
    constexpr int nB  = BN / 32;
    constexpr int BUF = (BM + BN) * 36;
    const int lane = tid & 31, w = tid >> 5;
    const int g = lane >> 2, tg = lane & 3;
    const int wr = (BM == 128) ? (w & 3) * 32 : (w & 1) * 32;
    const int wc = (BM == 128) ? (w >> 2) * 48 : (w >> 1) * 48;
    const int stsO = (tid >> 3) * 36 + 4 * (tid & 7);

    float4 ra[nA], rb[nB];
#pragma unroll
    for (int i = 0; i < nA; i++) ra[i] = *(const float4*)(aP[i]);
#pragma unroll
    for (int i = 0; i < nB; i++) rb[i] = *(const float4*)(bP[i]);
#pragma unroll
    for (int i = 0; i < nA; i++) sts_tf32(sm + stsO + 1152 * i, ra[i]);
#pragma unroll
    for (int i = 0; i < nB; i++) sts_tf32(sm + BM * 36 + stsO + 1152 * i, rb[i]);
    __syncthreads();

#pragma unroll 1
    for (int c = 0; c < NC; c++) {
        if (c + 1 < NC) {
#pragma unroll
            for (int i = 0; i < nA; i++) ra[i] = *(const float4*)(aP[i] + (c + 1) * 32);
#pragma unroll
            for (int i = 0; i < nB; i++) rb[i] = *(const float4*)(bP[i] + (c + 1) * 32);
        }
        const float* A  = sm + (c & 1) * BUF;
        const float* Bs = A + BM * 36;
#pragma unroll
        for (int kk = 0; kk < 32; kk += 8) {
            float af[2][4], bf[6][2];
#pragma unroll
            for (int mi = 0; mi < 2; mi++) {
                const float* Ar = A + (wr + 16 * mi + g) * 36 + kk + tg;
                af[mi][0] = Ar[0];   af[mi][1] = Ar[288];
                af[mi][2] = Ar[4];   af[mi][3] = Ar[292];
            }
#pragma unroll
            for (int ni = 0; ni < 6; ni++) {
                const float* Br = Bs + (wc + 8 * ni + g) * 36 + kk + tg;
                bf[ni][0] = Br[0];   bf[ni][1] = Br[4];
            }
#pragma unroll
            for (int mi = 0; mi < 2; mi++)
#pragma unroll
                for (int ni = 0; ni < 6; ni++)
                    mma8(acc[mi][ni], af[mi], bf[ni]);
        }
        if (c + 1 < NC) {
            float* dA = sm + ((c + 1) & 1) * BUF;
#pragma unroll
            for (int i = 0; i < nA; i++) sts_tf32(dA + stsO + 1152 * i, ra[i]);
#pragma unroll
            for (int i = 0; i < nB; i++) sts_tf32(dA + BM * 36 + stsO + 1152 * i, rb[i]);
        }
        __syncthreads();
    }
}

template<int BM, int PST>
__device__ __forceinline__ void frag_store(float* St, float (&acc)[2][6][4], int tid) {
    const int lane = tid & 31, w = tid >> 5;
    const int g = lane >> 2, tg = lane & 3;
    const int wr = (BM == 128) ? (w & 3) * 32 : (w & 1) * 32;
    const int wc = (BM == 128) ? (w >> 2) * 48 : (w >> 1) * 48;
#pragma unroll
    for (int mi = 0; mi < 2; mi++)
#pragma unroll
        for (int ni = 0; ni < 6; ni++) {
            int row = wr + 16 * mi + g;
            int col = wc + 8 * ni + 2 * tg;
            St[row * PST + col]           = acc[mi][ni][0];
            St[row * PST + col + 1]       = acc[mi][ni][1];
            St[(row + 8) * PST + col]     = acc[mi][ni][2];
            St[(row + 8) * PST + col + 1] = acc[mi][ni][3];
        }
}

// ======================= K0: transpose x,feat -> token-major =======================
__global__ void k_transpose(const float* __restrict__ x, const float* __restrict__ feat) {
    __shared__ float t[32][33];
    int z = blockIdx.z;
    int b = z & 3, which = z >> 2;
    int c0 = blockIdx.x << 5;
    int p0 = blockIdx.y << 5;
    const float* src = (which ? feat : x) + (size_t)b * Cd * HWd;
    float*       dst = (which ? g_ft : g_xt) + (size_t)b * HWd * Cd;
    int tx = threadIdx.x, ty = threadIdx.y;
#pragma unroll
    for (int i = ty; i < 32; i += 8)
        t[i][tx] = src[(size_t)(c0 + i) * HWd + p0 + tx];
    __syncthreads();
#pragma unroll
    for (int i = ty; i < 32; i += 8)
        dst[(size_t)(p0 + i) * Cd + c0 + tx] = t[tx][i];
}

// ======================= K1: gathered QKV GEMM (tf32) =======================
__global__ void __launch_bounds__(256, 2) k_qkv(
    const float* __restrict__ q_w, const float* __restrict__ q_b,
    const float* __restrict__ kv_w, const float* __restrict__ kv_b)
{
    extern __shared__ float sm[];
    __shared__ int tok[128];
    int tid = threadIdx.x;
    int colbase = blockIdx.x * 96;
    int winbase = blockIdx.y * 2;
    if (tid < 128) {
        int win = winbase + (tid >> 6), n = tid & 63;
        int b = win >> 10, wh = (win >> 5) & 31, ww = win & 31;
        int h = (wh * 8 + (n >> 3) + 4) & 255;
        int w = (ww * 8 + (n & 7) + 4) & 255;
        tok[tid] = (b << 16) | (h << 8) | w;
    }
    __syncthreads();
    const float* src  = (blockIdx.x < 2) ? g_xt : g_ft;
    const float* Wsrc = (blockIdx.x < 2) ? (q_w + colbase * 192)
                                         : (kv_w + (size_t)(colbase - 192) * 192);
    const int r0 = tid >> 3, c4 = 4 * (tid & 7);
    const float* aP[4]; const float* bP[3];
#pragma unroll
    for (int i = 0; i < 4; i++) aP[i] = src + (size_t)tok[r0 + 32 * i] * 192 + c4;
#pragma unroll
    for (int i = 0; i < 3; i++) bP[i] = Wsrc + (size_t)(r0 + 32 * i) * 192 + c4;

    float acc[2][6][4];
#pragma unroll
    for (int a = 0; a < 2; a++)
#pragma unroll
        for (int b2 = 0; b2 < 6; b2++)
#pragma unroll
            for (int cc = 0; cc < 4; cc++) acc[a][b2][cc] = 0.f;
    gemm_core<128, 96, 6>(aP, bP, sm, acc, tid);

    float* St = sm;
    frag_store<128, 104>(St, acc, tid);
    __syncthreads();
    bool isq = (blockIdx.x < 2);
#pragma unroll 1
    for (int idx = tid; idx < 128 * 96; idx += 256) {
        int m = idx / 96, j = idx - m * 96;
        int col = colbase + j;
        float val = St[m * 104 + j];
        if (isq) val = (val + q_b[col]) * QSCALE;
        else     val = val + kv_b[col - 192];
        int win = winbase + (m >> 6), n = m & 63;
        float* dp; int cc;
        if      (col < 192) { dp = g_q;  cc = col; }
        else if (col < 384) { dp = g_kk; cc = col - 192; }
        else                { dp = g_vv; cc = col - 384; }
        dp[(((size_t)win * NHd + (cc >> 5)) * 64 + n) * HDd + (cc & 31)] = val;
    }
}

// ======================= K2: attention (register-blocked fp32) =======================
__global__ void __launch_bounds__(256) k_attn(
    const float* __restrict__ mask, const int* __restrict__ relidx,
    const float* __restrict__ table)
{
    extern __shared__ float sm[];
    float* Qt = sm;              // [32][68]
    float* Kt = Qt + 32 * 68;    // [32][68]
    float* Vs = Kt + 32 * 68;    // [64][36]
    float* Ps = Vs + 64 * 36;    // [64][68]
    float* tb = Ps + 64 * 68;    // 1350
    int cta = blockIdx.x, win = cta / NHd, head = cta - win * NHd;
    int tid = threadIdx.x;
    size_t base = (size_t)cta * 2048;
#pragma unroll
    for (int i = tid; i < 2048; i += 256) {
        int n = i >> 5, d = i & 31;
        Qt[d * 68 + n] = g_q [base + i];
        Kt[d * 68 + n] = g_kk[base + i];
        Vs[n * 36 + d] = g_vv[base + i];
    }
    for (int i = tid; i < 1350; i += 256) tb[i] = table[i];
    __syncthreads();

    int ti = tid >> 4, tj = tid & 15;
    float s[4][4];
#pragma unroll
    for (int r = 0; r < 4; r++)
#pragma unroll
        for (int c = 0; c < 4; c++) s[r][c] = 0.f;
#pragma unroll 4
    for (int d = 0; d < 32; d++) {
        float4 qv = *(const float4*)(Qt + d * 68 + 4 * ti);
        float4 kv = *(const float4*)(Kt + d * 68 + 4 * tj);
        float qa[4] = {qv.x, qv.y, qv.z, qv.w};
        float kb[4] = {kv.x, kv.y, kv.z, kv.w};
#pragma unroll
        for (int r = 0; r < 4; r++)
#pragma unroll
            for (int c = 0; c < 4; c++)
                s[r][c] = fmaf(qa[r], kb[c], s[r][c]);
    }
    const float* mrow = mask + (size_t)(win & 1023) * 4096;
#pragma unroll
    for (int r = 0; r < 4; r++) {
        int i = 4 * ti + r;
#pragma unroll
        for (int c = 0; c < 4; c++) {
            int j = 4 * tj + c;
            s[r][c] += tb[relidx[i * 64 + j] * NHd + head] + mrow[i * 64 + j];
        }
    }
#pragma unroll
    for (int r = 0; r < 4; r++) {
        float mx = fmaxf(fmaxf(s[r][0], s[r][1]), fmaxf(s[r][2], s[r][3]));
#pragma unroll
        for (int o = 1; o < 16; o <<= 1) mx = fmaxf(mx, __shfl_xor_sync(0xffffffffu, mx, o));
        float e0 = __expf(s[r][0] - mx), e1 = __expf(s[r][1] - mx);
        float e2 = __expf(s[r][2] - mx), e3 = __expf(s[r][3] - mx);
        float su = e0 + e1 + e2 + e3;
#pragma unroll
        for (int o = 1; o < 16; o <<= 1) su += __shfl_xor_sync(0xffffffffu, su, o);
        float inv = 1.f / su;
        float4 st = make_float4(e0 * inv, e1 * inv, e2 * inv, e3 * inv);
        *(float4*)(Ps + (4 * ti + r) * 68 + 4 * tj) = st;
    }
    __syncthreads();

    int rg = tid >> 3;      // rows 2rg, 2rg+1
    int c8 = tid & 7;       // cols 4c8..4c8+3
    float o0[4] = {0.f, 0.f, 0.f, 0.f};
    float o1[4] = {0.f, 0.f, 0.f, 0.f};
#pragma unroll 4
    for (int j = 0; j < 64; j++) {
        float p0 = Ps[(2 * rg) * 68 + j];
        float p1 = Ps[(2 * rg + 1) * 68 + j];
        float4 v = *(const float4*)(Vs + j * 36 + 4 * c8);
        o0[0] = fmaf(p0, v.x, o0[0]); o0[1] = fmaf(p0, v.y, o0[1]);
        o0[2] = fmaf(p0, v.z, o0[2]); o0[3] = fmaf(p0, v.w, o0[3]);
        o1[0] = fmaf(p1, v.x, o1[0]); o1[1] = fmaf(p1, v.y, o1[1]);
        o1[2] = fmaf(p1, v.z, o1[2]); o1[3] = fmaf(p1, v.w, o1[3]);
    }
    float* ob = g_attn + (size_t)win * 64 * Cd + head * HDd + 4 * c8;
    *(float4*)(ob + (2 * rg) * Cd)     = make_float4(o0[0], o0[1], o0[2], o0[3]);
    *(float4*)(ob + (2 * rg + 1) * Cd) = make_float4(o1[0], o1[1], o1[2], o1[3]);
}

// ======================= K3: proj GEMM + scatter (tf32) =======================
__global__ void __launch_bounds__(256, 2) k_proj(
    const float* __restrict__ pw, const float* __restrict__ pb)
{
    extern __shared__ float sm[];
    __shared__ int ppix[128];
    int tid = threadIdx.x;
    int colbase = blockIdx.x * 96;
    size_t mbase = (size_t)blockIdx.y * 128;
    if (tid < 128) {
        int win = blockIdx.y * 2 + (tid >> 6);
        int n = tid & 63;
        int b = win >> 10, wh = (win >> 5) & 31, ww = win & 31;
        int h = (wh * 8 + (n >> 3) + 4) & 255;
        int w = (ww * 8 + (n & 7) + 4) & 255;
        ppix[tid] = (b << 16) | (h << 8) | w;
    }
    const int r0 = tid >> 3, c4 = 4 * (tid & 7);
    const float* aP[4]; const float* bP[3];
#pragma unroll
    for (int i = 0; i < 4; i++) aP[i] = g_attn + (mbase + r0 + 32 * i) * 192 + c4;
#pragma unroll
    for (int i = 0; i < 3; i++) bP[i] = pw + (size_t)(colbase + r0 + 32 * i) * 192 + c4;
    float acc[2][6][4];
#pragma unroll
    for (int a = 0; a < 2; a++)
#pragma unroll
        for (int b2 = 0; b2 < 6; b2++)
#pragma unroll
            for (int cc = 0; cc < 4; cc++) acc[a][b2][cc] = 0.f;
    gemm_core<128, 96, 6>(aP, bP, sm, acc, tid);
    float* St = sm;
    frag_store<128, 104>(St, acc, tid);
    __syncthreads();
#pragma unroll 1
    for (int idx = tid; idx < 128 * 96; idx += 256) {
        int m = idx / 96, j = idx - m * 96;
        g_proj[(size_t)ppix[m] * Cd + colbase + j] = St[m * 104 + j] + pb[colbase + j];
    }
}

// ======================= K4: merge GEMM + LN + shortcut (tf32) =======================
__global__ void __launch_bounds__(256, 2) k_merge(
    const float* __restrict__ mw, const float* __restrict__ g1,
    const float* __restrict__ b1)
{
    extern __shared__ float sm[];
    int tid = threadIdx.x;
    size_t mbase = (size_t)blockIdx.x * 64;
    const int r0 = tid >> 3, c4 = 4 * (tid & 7);
    const float* aP[2]; const float* bP[6];
#pragma unroll
    for (int i = 0; i < 2; i++) aP[i] = g_proj + (mbase + r0 + 32 * i) * 192 + c4;
#pragma unroll
    for (int i = 0; i < 6; i++) bP[i] = mw + (size_t)(r0 + 32 * i) * 192 + c4;
    float acc[2][6][4];
#pragma unroll
    for (int a = 0; a < 2; a++)
#pragma unroll
        for (int b2 = 0; b2 < 6; b2++)
#pragma unroll
            for (int cc = 0; cc < 4; cc++) acc[a][b2][cc] = 0.f;
    gemm_core<64, 192, 6>(aP, bP, sm, acc, tid);
    float* St = sm;
    frag_store<64, 200>(St, acc, tid);
    __syncthreads();
    int wp = tid >> 5, l = tid & 31;
#pragma unroll 1
    for (int rr = 0; rr < 8; rr++) {
        int r = wp * 8 + rr;
        float vv[6]; float su = 0.f;
#pragma unroll
        for (int u = 0; u < 6; u++) { vv[u] = St[r * 200 + l + 32 * u]; su += vv[u]; }
        su = warp_sum(su);
        float mean = su * (1.f / 192.f);
        float sq = 0.f;
#pragma unroll
        for (int u = 0; u < 6; u++) { float d = vv[u] - mean; sq += d * d; }
        sq = warp_sum(sq);
        float rstd = rsqrtf(sq * (1.f / 192.f) + 1e-5f);
        size_t row = (mbase + r) * Cd;
#pragma unroll
        for (int u = 0; u < 6; u++) {
            int c = l + 32 * u;
            g_x1[row + c] = (vv[u] - mean) * rstd * g1[c] + b1[c] + g_xt[row + c];
        }
    }
}

// ======================= K5a: fc1 + GELU (tf32) =======================
__global__ void __launch_bounds__(256, 2) k_fc1(
    const float* __restrict__ w1, const float* __restrict__ b1h)
{
    extern __shared__ float sm[];
    int tid = threadIdx.x;
    int colbase = blockIdx.x * 96;
    size_t mbase = (size_t)blockIdx.y * 128;
    const int r0 = tid >> 3, c4 = 4 * (tid & 7);
    const float* aP[4]; const float* bP[3];
#pragma unroll
    for (int i = 0; i < 4; i++) aP[i] = g_x1 + (mbase + r0 + 32 * i) * 192 + c4;
#pragma unroll
    for (int i = 0; i < 3; i++) bP[i] = w1 + (size_t)(colbase + r0 + 32 * i) * 192 + c4;
    float acc[2][6][4];
#pragma unroll
    for (int a = 0; a < 2; a++)
#pragma unroll
        for (int b2 = 0; b2 < 6; b2++)
#pragma unroll
            for (int cc = 0; cc < 4; cc++) acc[a][b2][cc] = 0.f;
    gemm_core<128, 96, 6>(aP, bP, sm, acc, tid);
    float* St = sm;
    frag_store<128, 104>(St, acc, tid);
    __syncthreads();
#pragma unroll 1
    for (int idx = tid; idx < 128 * 96; idx += 256) {
        int m = idx / 96, j = idx - m * 96;
        float val = St[m * 104 + j] + b1h[colbase + j];
        val = 0.5f * val * (1.f + erff(val * 0.70710678118654752f));
        g_h1[(mbase + m) * HIDd + colbase + j] = val;
    }
}

// ======================= K5b: fc2 + LN + residual (tf32) =======================
__global__ void __launch_bounds__(256, 2) k_fc2(
    const float* __restrict__ w2, const float* __restrict__ b2,
    const float* __restrict__ g2, const float* __restrict__ bb2,
    float* __restrict__ out)
{
    extern __shared__ float sm[];
    int tid = threadIdx.x;
    size_t mbase = (size_t)blockIdx.x * 64;
    const int r0 = tid >> 3, c4 = 4 * (tid & 7);
    const float* aP[2]; const float* bP[6];
#pragma unroll
    for (int i = 0; i < 2; i++) aP[i] = g_h1 + (mbase + r0 + 32 * i) * 768 + c4;
#pragma unroll
    for (int i = 0; i < 6; i++) bP[i] = w2 + (size_t)(r0 + 32 * i) * 768 + c4;
    float acc[2][6][4];
#pragma unroll
    for (int a = 0; a < 2; a++)
#pragma unroll
        for (int b2i = 0; b2i < 6; b2i++)
#pragma unroll
            for (int cc = 0; cc < 4; cc++) acc[a][b2i][cc] = 0.f;
    gemm_core<64, 192, 24>(aP, bP, sm, acc, tid);
    float* St = sm;
    frag_store<64, 200>(St, acc, tid);
    __syncthreads();
    int wp = tid >> 5, l = tid & 31;
#pragma unroll 1
    for (int rr = 0; rr < 8; rr++) {
        int r = wp * 8 + rr;
        float vv[6]; float su = 0.f;
#pragma unroll
        for (int u = 0; u < 6; u++) {
            int c = l + 32 * u;
            vv[u] = St[r * 200 + c] + b2[c];
            su += vv[u];
        }
        su = warp_sum(su);
        float mean = su * (1.f / 192.f);
        float sq = 0.f;
#pragma unroll
        for (int u = 0; u < 6; u++) { float d = vv[u] - mean; sq += d * d; }
        sq = warp_sum(sq);
        float rstd = rsqrtf(sq * (1.f / 192.f) + 1e-5f);
        size_t row = (mbase + r) * Cd;
#pragma unroll
        for (int u = 0; u < 6; u++) {
            int c = l + 32 * u;
            out[row + c] = g_x1[row + c] + (vv[u] - mean) * rstd * g2[c] + bb2[c];
        }
    }
}

// ======================= host =======================
extern "C" void kernel_launch(void* const* d_in, const int* in_sizes, int n_in,
                              void* d_out, int out_size)
{
    const float* x    = (const float*)d_in[0];
    const float* feat = (const float*)d_in[1];
    const float* mask = (const float*)d_in[2];
    const int*   ridx = (const int*)  d_in[3];
    const float* rtab = (const float*)d_in[4];
    const float* q_w  = (const float*)d_in[5];
    const float* q_b  = (const float*)d_in[6];
    const float* kv_w = (const float*)d_in[7];
    const float* kv_b = (const float*)d_in[8];
    const float* p_w  = (const float*)d_in[9];
    const float* p_b  = (const float*)d_in[10];
    const float* m_w  = (const float*)d_in[11];
    const float* n1g  = (const float*)d_in[12];
    const float* n1b  = (const float*)d_in[13];
    const float* n2g  = (const float*)d_in[14];
    const float* n2b  = (const float*)d_in[15];
    const float* f1w  = (const float*)d_in[16];
    const float* f1b  = (const float*)d_in[17];
    const float* f2w  = (const float*)d_in[18];
    const float* f2b  = (const float*)d_in[19];
    float* out = (float*)d_out;

    const int smBig  = 2 * (224 * 36) * (int)sizeof(float);   // 64512
    const int smWide = 2 * (256 * 36) * (int)sizeof(float);   // 73728
    const int smAttn = (2 * 32 * 68 + 64 * 36 + 64 * 68 + 1352) * (int)sizeof(float);
    cudaFuncSetAttribute(k_qkv,   cudaFuncAttributeMaxDynamicSharedMemorySize, smBig);
    cudaFuncSetAttribute(k_proj,  cudaFuncAttributeMaxDynamicSharedMemorySize, smBig);
    cudaFuncSetAttribute(k_fc1,   cudaFuncAttributeMaxDynamicSharedMemorySize, smBig);
    cudaFuncSetAttribute(k_merge, cudaFuncAttributeMaxDynamicSharedMemorySize, smWide);
    cudaFuncSetAttribute(k_fc2,   cudaFuncAttributeMaxDynamicSharedMemorySize, smWide);
    cudaFuncSetAttribute(k_attn,  cudaFuncAttributeMaxDynamicSharedMemorySize, smAttn);

    k_transpose<<<dim3(6, 2048, 8), dim3(32, 8)>>>(x, feat);
    k_qkv  <<<dim3(6, 2048), 256, smBig>>>(q_w, q_b, kv_w, kv_b);
    k_attn <<<NWINd * NHd, 256, smAttn>>>(mask, ridx, rtab);
    k_proj <<<dim3(2, 2048), 256, smBig>>>(p_w, p_b);
    k_merge<<<4096, 256, smWide>>>(m_w, n1g, n1b);
    k_fc1  <<<dim3(8, 2048), 256, smBig>>>(f1w, f1b);
    k_fc2  <<<4096, 256, smWide>>>(f2w, f2b, n2g, n2b, out);
}

// round 3
// speedup vs baseline: 5.0937x; 1.2643x over previous
#include <cuda_runtime.h>
#include <cuda_fp16.h>
#include <math.h>
#include <stdint.h>

#define Hd    256
#define Wdim  256
#define HWd   65536
#define Cd    192
#define Bd    4
#define NHd   6
#define HDd   32
#define NWINd 4096
#define MTOKd 262144
#define HIDd  768
#define QSCALE 0.17677669529663687f

// -------- scratch --------
__device__ float  g_xt  [(size_t)MTOKd * Cd];
__device__ float  g_ft  [(size_t)MTOKd * Cd];
__device__ __half g_qh  [(size_t)NWINd * NHd * 64 * HDd];   // [win][h][n][d]
__device__ __half g_kh  [(size_t)NWINd * NHd * 64 * HDd];   // [win][h][n][d]
__device__ __half g_vh  [(size_t)NWINd * NHd * HDd * 64];   // [win][h][d][n]
__device__ float  g_bias[(size_t)NHd * 64 * 64];
__device__ float  g_attn[(size_t)NWINd * 64 * Cd];
__device__ float  g_proj[(size_t)MTOKd * Cd];
__device__ float  g_x1  [(size_t)MTOKd * Cd];
__device__ float  g_h1  [(size_t)MTOKd * HIDd];

__device__ __forceinline__ float warp_sum(float v) {
#pragma unroll
    for (int o = 16; o; o >>= 1) v += __shfl_xor_sync(0xffffffffu, v, o);
    return v;
}
__device__ __forceinline__ unsigned h2u(__half2 h) {
    return *reinterpret_cast<unsigned*>(&h);
}
__device__ __forceinline__ unsigned ldu(const __half* p) {
    return *reinterpret_cast<const unsigned*>(p);
}
__device__ __forceinline__ void sts4h(__half* p, float4 v) {
    __half2 lo = __floats2half2_rn(v.x, v.y);
    __half2 hi = __floats2half2_rn(v.z, v.w);
    *reinterpret_cast<uint2*>(p) = make_uint2(h2u(lo), h2u(hi));
}
__device__ __forceinline__ void mma16(float* c, const unsigned* a, unsigned b0, unsigned b1) {
    asm volatile(
        "mma.sync.aligned.m16n8k16.row.col.f32.f16.f16.f32 "
        "{%0,%1,%2,%3}, {%4,%5,%6,%7}, {%8,%9}, {%0,%1,%2,%3};"
        : "+f"(c[0]), "+f"(c[1]), "+f"(c[2]), "+f"(c[3])
        : "r"(a[0]), "r"(a[1]), "r"(a[2]), "r"(a[3]), "r"(b0), "r"(b1));
}

// ======================= fp16 GEMM core =======================
// BM x BN tile, 8 warps of 32x48 warp tiles, K in chunks of 32 (2 ksteps of 16).
// Staging rows: 40 halves (80B) -> conflict-free fragment LDS.
template<int BM, int BN, int NC>
__device__ __forceinline__ void gemm_core_h(
    const float* const* aP, const float* const* bP,
    __half* smh, float (&acc)[2][6][4], int tid)
{
    constexpr int nA  = BM / 32;
    constexpr int nB  = BN / 32;
    constexpr int BUF = (BM + BN) * 40;
    const int lane = tid & 31, w = tid >> 5;
    const int g = lane >> 2, tg = lane & 3;
    const int wr = (BM == 128) ? (w & 3) * 32 : (w & 1) * 32;
    const int wc = (BM == 128) ? (w >> 2) * 48 : (w >> 1) * 48;
    const int stsO = (tid >> 3) * 40 + 4 * (tid & 7);

    float4 ra[nA], rb[nB];
#pragma unroll
    for (int i = 0; i < nA; i++) ra[i] = *(const float4*)(aP[i]);
#pragma unroll
    for (int i = 0; i < nB; i++) rb[i] = *(const float4*)(bP[i]);
#pragma unroll
    for (int i = 0; i < nA; i++) sts4h(smh + stsO + 1280 * i, ra[i]);
#pragma unroll
    for (int i = 0; i < nB; i++) sts4h(smh + BM * 40 + stsO + 1280 * i, rb[i]);
    __syncthreads();

#pragma unroll 1
    for (int c = 0; c < NC; c++) {
        if (c + 1 < NC) {
#pragma unroll
            for (int i = 0; i < nA; i++) ra[i] = *(const float4*)(aP[i] + (c + 1) * 32);
#pragma unroll
            for (int i = 0; i < nB; i++) rb[i] = *(const float4*)(bP[i] + (c + 1) * 32);
        }
        const __half* A  = smh + (c & 1) * BUF;
        const __half* Bs = A + BM * 40;
#pragma unroll
        for (int kk = 0; kk < 32; kk += 16) {
            unsigned af[2][4], bf[6][2];
#pragma unroll
            for (int mi = 0; mi < 2; mi++) {
                const __half* Ar = A + (wr + 16 * mi + g) * 40 + kk + 2 * tg;
                af[mi][0] = ldu(Ar);       af[mi][1] = ldu(Ar + 320);
                af[mi][2] = ldu(Ar + 8);   af[mi][3] = ldu(Ar + 328);
            }
#pragma unroll
            for (int ni = 0; ni < 6; ni++) {
                const __half* Br = Bs + (wc + 8 * ni + g) * 40 + kk + 2 * tg;
                bf[ni][0] = ldu(Br);  bf[ni][1] = ldu(Br + 8);
            }
#pragma unroll
            for (int mi = 0; mi < 2; mi++)
#pragma unroll
                for (int ni = 0; ni < 6; ni++)
                    mma16(acc[mi][ni], af[mi], bf[ni][0], bf[ni][1]);
        }
        if (c + 1 < NC) {
            __half* dA = smh + ((c + 1) & 1) * BUF;
#pragma unroll
            for (int i = 0; i < nA; i++) sts4h(dA + stsO + 1280 * i, ra[i]);
#pragma unroll
            for (int i = 0; i < nB; i++) sts4h(dA + BM * 40 + stsO + 1280 * i, rb[i]);
        }
        __syncthreads();
    }
}

template<int BM, int PST>
__device__ __forceinline__ void frag_store(float* St, float (&acc)[2][6][4], int tid) {
    const int lane = tid & 31, w = tid >> 5;
    const int g = lane >> 2, tg = lane & 3;
    const int wr = (BM == 128) ? (w & 3) * 32 : (w & 1) * 32;
    const int wc = (BM == 128) ? (w >> 2) * 48 : (w >> 1) * 48;
#pragma unroll
    for (int mi = 0; mi < 2; mi++)
#pragma unroll
        for (int ni = 0; ni < 6; ni++) {
            int row = wr + 16 * mi + g;
            int col = wc + 8 * ni + 2 * tg;
            St[row * PST + col]           = acc[mi][ni][0];
            St[row * PST + col + 1]       = acc[mi][ni][1];
            St[(row + 8) * PST + col]     = acc[mi][ni][2];
            St[(row + 8) * PST + col + 1] = acc[mi][ni][3];
        }
}

// ======================= K-1: bias precompute =======================
__global__ void k_bias(const int* __restrict__ relidx, const float* __restrict__ table) {
    int idx = blockIdx.x * 256 + threadIdx.x;
    if (idx < NHd * 4096) {
        int h = idx >> 12, r = idx & 4095;
        g_bias[idx] = table[relidx[r] * NHd + h];
    }
}

// ======================= K0: transpose x,feat -> token-major =======================
__global__ void k_transpose(const float* __restrict__ x, const float* __restrict__ feat) {
    __shared__ float t[32][33];
    int z = blockIdx.z;
    int b = z & 3, which = z >> 2;
    int c0 = blockIdx.x << 5;
    int p0 = blockIdx.y << 5;
    const float* src = (which ? feat : x) + (size_t)b * Cd * HWd;
    float*       dst = (which ? g_ft : g_xt) + (size_t)b * HWd * Cd;
    int tx = threadIdx.x, ty = threadIdx.y;
#pragma unroll
    for (int i = ty; i < 32; i += 8)
        t[i][tx] = src[(size_t)(c0 + i) * HWd + p0 + tx];
    __syncthreads();
#pragma unroll
    for (int i = ty; i < 32; i += 8)
        dst[(size_t)(p0 + i) * Cd + c0 + tx] = t[tx][i];
}

// ======================= K1: gathered QKV GEMM (fp16 mma) =======================
__global__ void __launch_bounds__(256, 2) k_qkv(
    const float* __restrict__ q_w, const float* __restrict__ q_b,
    const float* __restrict__ kv_w, const float* __restrict__ kv_b)
{
    extern __shared__ float sm[];
    __half* smh = (__half*)sm;
    __shared__ int tok[128];
    int tid = threadIdx.x;
    int colbase = blockIdx.x * 96;
    int winbase = blockIdx.y * 2;
    if (tid < 128) {
        int win = winbase + (tid >> 6), n = tid & 63;
        int b = win >> 10, wh = (win >> 5) & 31, ww = win & 31;
        int h = (wh * 8 + (n >> 3) + 4) & 255;
        int w = (ww * 8 + (n & 7) + 4) & 255;
        tok[tid] = (b << 16) | (h << 8) | w;
    }
    __syncthreads();
    const float* src  = (blockIdx.x < 2) ? g_xt : g_ft;
    const float* Wsrc = (blockIdx.x < 2) ? (q_w + colbase * 192)
                                         : (kv_w + (size_t)(colbase - 192) * 192);
    const int r0 = tid >> 3, c4 = 4 * (tid & 7);
    const float* aP[4]; const float* bP[3];
#pragma unroll
    for (int i = 0; i < 4; i++) aP[i] = src + (size_t)tok[r0 + 32 * i] * 192 + c4;
#pragma unroll
    for (int i = 0; i < 3; i++) bP[i] = Wsrc + (size_t)(r0 + 32 * i) * 192 + c4;

    float acc[2][6][4];
#pragma unroll
    for (int a = 0; a < 2; a++)
#pragma unroll
        for (int b2 = 0; b2 < 6; b2++)
#pragma unroll
            for (int cc = 0; cc < 4; cc++) acc[a][b2][cc] = 0.f;
    gemm_core_h<128, 96, 6>(aP, bP, smh, acc, tid);

    float* St = sm;
    frag_store<128, 104>(St, acc, tid);
    __syncthreads();

    if (blockIdx.x < 4) {
        // Q or K chunk: pack 4 cols at a time
        bool isq = (blockIdx.x < 2);
        __half* dst = isq ? g_qh : g_kh;
        const float* bias = isq ? q_b : kv_b;
        int cb = isq ? colbase : (colbase - 192);
#pragma unroll 1
        for (int p = tid; p < 128 * 24; p += 256) {
            int m = p / 24, j = 4 * (p - (p / 24) * 24);
            int win = winbase + (m >> 6), n = m & 63;
            int c = cb + j;
            __half hv[4];
#pragma unroll
            for (int e = 0; e < 4; e++) {
                float val = St[m * 104 + j + e] + bias[c + e + (isq ? colbase - cb : 0)];
                if (isq) val = (St[m * 104 + j + e] + bias[colbase + j + e]) * QSCALE;
                else     val = St[m * 104 + j + e] + bias[c + e];
                hv[e] = __float2half_rn(val);
            }
            size_t didx = (((size_t)win * NHd + (c >> 5)) * 64 + n) * HDd + (c & 31);
            *reinterpret_cast<uint2*>(dst + didx) =
                *reinterpret_cast<uint2*>(hv);
        }
    } else {
        // V chunk: transpose-pack into [win][h][d][n], 8 n at a time
        int hbase = (colbase == 384) ? 0 : 3;
#pragma unroll 1
        for (int p = tid; p < 1536; p += 256) {
            int win_i = p / 768, rem = p - win_i * 768;
            int hl = rem >> 8, rem2 = rem & 255;
            int d = rem2 >> 3, ng = rem2 & 7;
            int j = hl * 32 + d;
            float bv = kv_b[colbase - 192 + j];
            __half hv[8];
#pragma unroll
            for (int r = 0; r < 8; r++)
                hv[r] = __float2half_rn(St[(win_i * 64 + ng * 8 + r) * 104 + j] + bv);
            int win = winbase + win_i;
            size_t didx = (((size_t)win * NHd + hbase + hl) * HDd + d) * 64 + ng * 8;
            *reinterpret_cast<uint4*>(g_vh + didx) = *reinterpret_cast<uint4*>(hv);
        }
    }
}

// ======================= K2: attention (fp16 mma, P in registers) =======================
__global__ void __launch_bounds__(256, 2) k_attn(const float* __restrict__ mask)
{
    extern __shared__ float smf[];
    __half* Qh = (__half*)smf;            // 6 heads * [64][40]
    __half* Kh = Qh + 15360;              // 6 heads * [64][40]
    __half* Vt = Kh + 15360;              // 6 heads * [32][72]
    int win = blockIdx.x;
    int tid = threadIdx.x;
    int lane = tid & 31, w = tid >> 5;
    int g = lane >> 2, tg = lane & 3;
    int mi = w & 3, hp = w >> 2;

    // load Q, K (packed [h][n][32]) and V ([h][d][64]) into padded smem
    size_t qkbase = (size_t)win * NHd * 64 * HDd;
    size_t vbase  = (size_t)win * NHd * HDd * 64;
#pragma unroll 1
    for (int p = tid; p < 1536; p += 256) {
        int h = p >> 8, rem = p & 255;
        int n = rem >> 2, u = rem & 3;
        uint4 v = *reinterpret_cast<const uint4*>(g_qh + qkbase + (h * 64 + n) * 32 + 8 * u);
        *reinterpret_cast<uint4*>(Qh + h * 2560 + n * 40 + 8 * u) = v;
    }
#pragma unroll 1
    for (int p = tid; p < 1536; p += 256) {
        int h = p >> 8, rem = p & 255;
        int n = rem >> 2, u = rem & 3;
        uint4 v = *reinterpret_cast<const uint4*>(g_kh + qkbase + (h * 64 + n) * 32 + 8 * u);
        *reinterpret_cast<uint4*>(Kh + h * 2560 + n * 40 + 8 * u) = v;
    }
#pragma unroll 1
    for (int p = tid; p < 1536; p += 256) {
        int h = p >> 8, rem = p & 255;
        int d = rem >> 3, u = rem & 7;
        uint4 v = *reinterpret_cast<const uint4*>(g_vh + vbase + (h * 32 + d) * 64 + 8 * u);
        *reinterpret_cast<uint4*>(Vt + h * 2304 + d * 72 + 8 * u) = v;
    }
    __syncthreads();

    const float* maskb = mask + (size_t)(win & 1023) * 4096;
    int i0 = 16 * mi + g;

#pragma unroll 1
    for (int t = 0; t < 3; t++) {
        int h = 2 * t + hp;
        // A fragments (Q rows 16mi..16mi+15)
        unsigned aq[2][4];
        const __half* Qb = Qh + h * 2560 + i0 * 40 + 2 * tg;
#pragma unroll
        for (int ks = 0; ks < 2; ks++) {
            aq[ks][0] = ldu(Qb + 16 * ks);
            aq[ks][1] = ldu(Qb + 16 * ks + 320);
            aq[ks][2] = ldu(Qb + 16 * ks + 8);
            aq[ks][3] = ldu(Qb + 16 * ks + 328);
        }
        float s[8][4];
#pragma unroll
        for (int ni = 0; ni < 8; ni++)
#pragma unroll
            for (int e = 0; e < 4; e++) s[ni][e] = 0.f;
        const __half* Kb = Kh + h * 2560 + g * 40 + 2 * tg;
#pragma unroll
        for (int ni = 0; ni < 8; ni++) {
            mma16(s[ni], aq[0], ldu(Kb + ni * 320),      ldu(Kb + ni * 320 + 8));
            mma16(s[ni], aq[1], ldu(Kb + ni * 320 + 16), ldu(Kb + ni * 320 + 24));
        }
        // bias + mask
#pragma unroll
        for (int ni = 0; ni < 8; ni++) {
            int j0 = 8 * ni + 2 * tg;
            float2 bz0 = *(const float2*)(g_bias + (h * 64 + i0) * 64 + j0);
            float2 bz1 = *(const float2*)(g_bias + (h * 64 + i0 + 8) * 64 + j0);
            float2 mk0 = *(const float2*)(maskb + i0 * 64 + j0);
            float2 mk1 = *(const float2*)(maskb + (i0 + 8) * 64 + j0);
            s[ni][0] += bz0.x + mk0.x;  s[ni][1] += bz0.y + mk0.y;
            s[ni][2] += bz1.x + mk1.x;  s[ni][3] += bz1.y + mk1.y;
        }
        // softmax (rows g and g+8; quad holds full 64 cols)
        float m0 = -1e30f, m1 = -1e30f;
#pragma unroll
        for (int ni = 0; ni < 8; ni++) {
            m0 = fmaxf(m0, fmaxf(s[ni][0], s[ni][1]));
            m1 = fmaxf(m1, fmaxf(s[ni][2], s[ni][3]));
        }
        m0 = fmaxf(m0, __shfl_xor_sync(0xffffffffu, m0, 1));
        m0 = fmaxf(m0, __shfl_xor_sync(0xffffffffu, m0, 2));
        m1 = fmaxf(m1, __shfl_xor_sync(0xffffffffu, m1, 1));
        m1 = fmaxf(m1, __shfl_xor_sync(0xffffffffu, m1, 2));
        float s0 = 0.f, s1 = 0.f;
#pragma unroll
        for (int ni = 0; ni < 8; ni++) {
            s[ni][0] = __expf(s[ni][0] - m0); s0 += s[ni][0];
            s[ni][1] = __expf(s[ni][1] - m0); s0 += s[ni][1];
            s[ni][2] = __expf(s[ni][2] - m1); s1 += s[ni][2];
            s[ni][3] = __expf(s[ni][3] - m1); s1 += s[ni][3];
        }
        s0 += __shfl_xor_sync(0xffffffffu, s0, 1);
        s0 += __shfl_xor_sync(0xffffffffu, s0, 2);
        s1 += __shfl_xor_sync(0xffffffffu, s1, 1);
        s1 += __shfl_xor_sync(0xffffffffu, s1, 2);
        float inv0 = 1.f / s0, inv1 = 1.f / s1;
        // pack P fragments (C-frag layout == A-frag layout)
        unsigned pv[4][4];
#pragma unroll
        for (int js = 0; js < 4; js++) {
            pv[js][0] = h2u(__floats2half2_rn(s[2*js][0]   * inv0, s[2*js][1]   * inv0));
            pv[js][1] = h2u(__floats2half2_rn(s[2*js][2]   * inv1, s[2*js][3]   * inv1));
            pv[js][2] = h2u(__floats2half2_rn(s[2*js+1][0] * inv0, s[2*js+1][1] * inv0));
            pv[js][3] = h2u(__floats2half2_rn(s[2*js+1][2] * inv1, s[2*js+1][3] * inv1));
        }
        // P @ V
        float o[4][4];
#pragma unroll
        for (int nd = 0; nd < 4; nd++)
#pragma unroll
            for (int e = 0; e < 4; e++) o[nd][e] = 0.f;
        const __half* Vb = Vt + h * 2304 + g * 72 + 2 * tg;
#pragma unroll
        for (int nd = 0; nd < 4; nd++)
#pragma unroll
            for (int js = 0; js < 4; js++)
                mma16(o[nd], pv[js], ldu(Vb + nd * 576 + 16 * js),
                                     ldu(Vb + nd * 576 + 16 * js + 8));
        // store to g_attn [win][token][192]
        float* ob = g_attn + ((size_t)win * 64) * Cd + h * HDd;
#pragma unroll
        for (int nd = 0; nd < 4; nd++) {
            int d0 = 8 * nd + 2 * tg;
            *(float2*)(ob + (size_t)i0 * Cd + d0)       = make_float2(o[nd][0], o[nd][1]);
            *(float2*)(ob + (size_t)(i0 + 8) * Cd + d0) = make_float2(o[nd][2], o[nd][3]);
        }
    }
}

// ======================= K3: proj GEMM + scatter =======================
__global__ void __launch_bounds__(256, 2) k_proj(
    const float* __restrict__ pw, const float* __restrict__ pb)
{
    extern __shared__ float sm[];
    __half* smh = (__half*)sm;
    __shared__ int ppix[128];
    int tid = threadIdx.x;
    int colbase = blockIdx.x * 96;
    size_t mbase = (size_t)blockIdx.y * 128;
    if (tid < 128) {
        int win = blockIdx.y * 2 + (tid >> 6);
        int n = tid & 63;
        int b = win >> 10, wh = (win >> 5) & 31, ww = win & 31;
        int h = (wh * 8 + (n >> 3) + 4) & 255;
        int w = (ww * 8 + (n & 7) + 4) & 255;
        ppix[tid] = (b << 16) | (h << 8) | w;
    }
    const int r0 = tid >> 3, c4 = 4 * (tid & 7);
    const float* aP[4]; const float* bP[3];
#pragma unroll
    for (int i = 0; i < 4; i++) aP[i] = g_attn + (mbase + r0 + 32 * i) * 192 + c4;
#pragma unroll
    for (int i = 0; i < 3; i++) bP[i] = pw + (size_t)(colbase + r0 + 32 * i) * 192 + c4;
    float acc[2][6][4];
#pragma unroll
    for (int a = 0; a < 2; a++)
#pragma unroll
        for (int b2 = 0; b2 < 6; b2++)
#pragma unroll
            for (int cc = 0; cc < 4; cc++) acc[a][b2][cc] = 0.f;
    gemm_core_h<128, 96, 6>(aP, bP, smh, acc, tid);
    float* St = sm;
    frag_store<128, 104>(St, acc, tid);
    __syncthreads();
#pragma unroll 1
    for (int idx = tid; idx < 128 * 96; idx += 256) {
        int m = idx / 96, j = idx - m * 96;
        g_proj[(size_t)ppix[m] * Cd + colbase + j] = St[m * 104 + j] + pb[colbase + j];
    }
}

// ======================= K4: merge GEMM + LN + shortcut =======================
__global__ void __launch_bounds__(256, 2) k_merge(
    const float* __restrict__ mw, const float* __restrict__ g1,
    const float* __restrict__ b1)
{
    extern __shared__ float sm[];
    __half* smh = (__half*)sm;
    int tid = threadIdx.x;
    size_t mbase = (size_t)blockIdx.x * 64;
    const int r0 = tid >> 3, c4 = 4 * (tid & 7);
    const float* aP[2]; const float* bP[6];
#pragma unroll
    for (int i = 0; i < 2; i++) aP[i] = g_proj + (mbase + r0 + 32 * i) * 192 + c4;
#pragma unroll
    for (int i = 0; i < 6; i++) bP[i] = mw + (size_t)(r0 + 32 * i) * 192 + c4;
    float acc[2][6][4];
#pragma unroll
    for (int a = 0; a < 2; a++)
#pragma unroll
        for (int b2 = 0; b2 < 6; b2++)
#pragma unroll
            for (int cc = 0; cc < 4; cc++) acc[a][b2][cc] = 0.f;
    gemm_core_h<64, 192, 6>(aP, bP, smh, acc, tid);
    float* St = sm;
    frag_store<64, 200>(St, acc, tid);
    __syncthreads();
    int wp = tid >> 5, l = tid & 31;
#pragma unroll 1
    for (int rr = 0; rr < 8; rr++) {
        int r = wp * 8 + rr;
        float vv[6]; float su = 0.f;
#pragma unroll
        for (int u = 0; u < 6; u++) { vv[u] = St[r * 200 + l + 32 * u]; su += vv[u]; }
        su = warp_sum(su);
        float mean = su * (1.f / 192.f);
        float sq = 0.f;
#pragma unroll
        for (int u = 0; u < 6; u++) { float d = vv[u] - mean; sq += d * d; }
        sq = warp_sum(sq);
        float rstd = rsqrtf(sq * (1.f / 192.f) + 1e-5f);
        size_t row = (mbase + r) * Cd;
#pragma unroll
        for (int u = 0; u < 6; u++) {
            int c = l + 32 * u;
            g_x1[row + c] = (vv[u] - mean) * rstd * g1[c] + b1[c] + g_xt[row + c];
        }
    }
}

// ======================= K5a: fc1 + GELU =======================
__global__ void __launch_bounds__(256, 2) k_fc1(
    const float* __restrict__ w1, const float* __restrict__ b1h)
{
    extern __shared__ float sm[];
    __half* smh = (__half*)sm;
    int tid = threadIdx.x;
    int colbase = blockIdx.x * 96;
    size_t mbase = (size_t)blockIdx.y * 128;
    const int r0 = tid >> 3, c4 = 4 * (tid & 7);
    const float* aP[4]; const float* bP[3];
#pragma unroll
    for (int i = 0; i < 4; i++) aP[i] = g_x1 + (mbase + r0 + 32 * i) * 192 + c4;
#pragma unroll
    for (int i = 0; i < 3; i++) bP[i] = w1 + (size_t)(colbase + r0 + 32 * i) * 192 + c4;
    float acc[2][6][4];
#pragma unroll
    for (int a = 0; a < 2; a++)
#pragma unroll
        for (int b2 = 0; b2 < 6; b2++)
#pragma unroll
            for (int cc = 0; cc < 4; cc++) acc[a][b2][cc] = 0.f;
    gemm_core_h<128, 96, 6>(aP, bP, smh, acc, tid);
    float* St = sm;
    frag_store<128, 104>(St, acc, tid);
    __syncthreads();
#pragma unroll 1
    for (int idx = tid; idx < 128 * 96; idx += 256) {
        int m = idx / 96, j = idx - m * 96;
        float val = St[m * 104 + j] + b1h[colbase + j];
        val = 0.5f * val * (1.f + erff(val * 0.70710678118654752f));
        g_h1[(mbase + m) * HIDd + colbase + j] = val;
    }
}

// ======================= K5b: fc2 + LN + residual =======================
__global__ void __launch_bounds__(256, 2) k_fc2(
    const float* __restrict__ w2, const float* __restrict__ b2,
    const float* __restrict__ g2, const float* __restrict__ bb2,
    float* __restrict__ out)
{
    extern __shared__ float sm[];
    __half* smh = (__half*)sm;
    int tid = threadIdx.x;
    size_t mbase = (size_t)blockIdx.x * 64;
    const int r0 = tid >> 3, c4 = 4 * (tid & 7);
    const float* aP[2]; const float* bP[6];
#pragma unroll
    for (int i = 0; i < 2; i++) aP[i] = g_h1 + (mbase + r0 + 32 * i) * 768 + c4;
#pragma unroll
    for (int i = 0; i < 6; i++) bP[i] = w2 + (size_t)(r0 + 32 * i) * 768 + c4;
    float acc[2][6][4];
#pragma unroll
    for (int a = 0; a < 2; a++)
#pragma unroll
        for (int b2i = 0; b2i < 6; b2i++)
#pragma unroll
            for (int cc = 0; cc < 4; cc++) acc[a][b2i][cc] = 0.f;
    gemm_core_h<64, 192, 24>(aP, bP, smh, acc, tid);
    float* St = sm;
    frag_store<64, 200>(St, acc, tid);
    __syncthreads();
    int wp = tid >> 5, l = tid & 31;
#pragma unroll 1
    for (int rr = 0; rr < 8; rr++) {
        int r = wp * 8 + rr;
        float vv[6]; float su = 0.f;
#pragma unroll
        for (int u = 0; u < 6; u++) {
            int c = l + 32 * u;
            vv[u] = St[r * 200 + c] + b2[c];
            su += vv[u];
        }
        su = warp_sum(su);
        float mean = su * (1.f / 192.f);
        float sq = 0.f;
#pragma unroll
        for (int u = 0; u < 6; u++) { float d = vv[u] - mean; sq += d * d; }
        sq = warp_sum(sq);
        float rstd = rsqrtf(sq * (1.f / 192.f) + 1e-5f);
        size_t row = (mbase + r) * Cd;
#pragma unroll
        for (int u = 0; u < 6; u++) {
            int c = l + 32 * u;
            out[row + c] = g_x1[row + c] + (vv[u] - mean) * rstd * g2[c] + bb2[c];
        }
    }
}

// ======================= host =======================
extern "C" void kernel_launch(void* const* d_in, const int* in_sizes, int n_in,
                              void* d_out, int out_size)
{
    const float* x    = (const float*)d_in[0];
    const float* feat = (const float*)d_in[1];
    const float* mask = (const float*)d_in[2];
    const int*   ridx = (const int*)  d_in[3];
    const float* rtab = (const float*)d_in[4];
    const float* q_w  = (const float*)d_in[5];
    const float* q_b  = (const float*)d_in[6];
    const float* kv_w = (const float*)d_in[7];
    const float* kv_b = (const float*)d_in[8];
    const float* p_w  = (const float*)d_in[9];
    const float* p_b  = (const float*)d_in[10];
    const float* m_w  = (const float*)d_in[11];
    const float* n1g  = (const float*)d_in[12];
    const float* n1b  = (const float*)d_in[13];
    const float* n2g  = (const float*)d_in[14];
    const float* n2b  = (const float*)d_in[15];
    const float* f1w  = (const float*)d_in[16];
    const float* f1b  = (const float*)d_in[17];
    const float* f2w  = (const float*)d_in[18];
    const float* f2b  = (const float*)d_in[19];
    float* out = (float*)d_out;

    const int smBig  = 128 * 104 * (int)sizeof(float);   // 53248 (>= 2*224*40*2)
    const int smWide = 64 * 200 * (int)sizeof(float);    // 51200 (>= 2*256*40*2)
    const int smAttn = (15360 + 15360 + 13824) * 2;      // 89088
    cudaFuncSetAttribute(k_qkv,   cudaFuncAttributeMaxDynamicSharedMemorySize, smBig);
    cudaFuncSetAttribute(k_proj,  cudaFuncAttributeMaxDynamicSharedMemorySize, smBig);
    cudaFuncSetAttribute(k_fc1,   cudaFuncAttributeMaxDynamicSharedMemorySize, smBig);
    cudaFuncSetAttribute(k_merge, cudaFuncAttributeMaxDynamicSharedMemorySize, smWide);
    cudaFuncSetAttribute(k_fc2,   cudaFuncAttributeMaxDynamicSharedMemorySize, smWide);
    cudaFuncSetAttribute(k_attn,  cudaFuncAttributeMaxDynamicSharedMemorySize, smAttn);

    k_bias     <<<96, 256>>>(ridx, rtab);
    k_transpose<<<dim3(6, 2048, 8), dim3(32, 8)>>>(x, feat);
    k_qkv  <<<dim3(6, 2048), 256, smBig>>>(q_w, q_b, kv_w, kv_b);
    k_attn <<<NWINd, 256, smAttn>>>(mask);
    k_proj <<<dim3(2, 2048), 256, smBig>>>(p_w, p_b);
    k_merge<<<4096, 256, smWide>>>(m_w, n1g, n1b);
    k_fc1  <<<dim3(8, 2048), 256, smBig>>>(f1w, f1b);
    k_fc2  <<<4096, 256, smWide>>>(f2w, f2b, n2g, n2b, out);
}

// round 4
// speedup vs baseline: 5.7446x; 1.1278x over previous
#include <cuda_runtime.h>
#include <cuda_fp16.h>
#include <math.h>
#include <stdint.h>

#define Hd    256
#define Wdim  256
#define HWd   65536
#define Cd    192
#define Bd    4
#define NHd   6
#define HDd   32
#define NWINd 4096
#define MTOKd 262144
#define HIDd  768
#define QSCALE 0.17677669529663687f

// -------- scratch --------
__device__ float  g_xt  [(size_t)MTOKd * Cd];           // fp32 (shortcut)
__device__ __half g_xth [(size_t)MTOKd * Cd];
__device__ __half g_fth [(size_t)MTOKd * Cd];
__device__ __half g_qh  [(size_t)NWINd * NHd * 64 * HDd];  // [win][h][n][d]
__device__ __half g_kh  [(size_t)NWINd * NHd * 64 * HDd];  // [win][h][n][d]
__device__ __half g_vh  [(size_t)NWINd * NHd * HDd * 64];  // [win][h][d][n]
__device__ __half g_biash[NHd * 64 * 64];
__device__ __half g_attnh[(size_t)NWINd * 64 * Cd];
__device__ __half g_projh[(size_t)MTOKd * Cd];
__device__ float  g_x1  [(size_t)MTOKd * Cd];           // fp32 (residual)
__device__ __half g_x1h [(size_t)MTOKd * Cd];
__device__ __half g_h1h [(size_t)MTOKd * HIDd];
__device__ __half w_qh [36864];
__device__ __half w_kvh[73728];
__device__ __half w_ph [36864];
__device__ __half w_mh [36864];
__device__ __half w_f1h[147456];
__device__ __half w_f2h[147456];

__device__ __forceinline__ float warp_sum(float v) {
#pragma unroll
    for (int o = 16; o; o >>= 1) v += __shfl_xor_sync(0xffffffffu, v, o);
    return v;
}
__device__ __forceinline__ unsigned h2u(__half2 h) {
    return *reinterpret_cast<unsigned*>(&h);
}
__device__ __forceinline__ unsigned ldu(const __half* p) {
    return *reinterpret_cast<const unsigned*>(p);
}
__device__ __forceinline__ void mma16(float* c, const unsigned* a, unsigned b0, unsigned b1) {
    asm volatile(
        "mma.sync.aligned.m16n8k16.row.col.f32.f16.f16.f32 "
        "{%0,%1,%2,%3}, {%4,%5,%6,%7}, {%8,%9}, {%0,%1,%2,%3};"
        : "+f"(c[0]), "+f"(c[1]), "+f"(c[2]), "+f"(c[3])
        : "r"(a[0]), "r"(a[1]), "r"(a[2]), "r"(a[3]), "r"(b0), "r"(b1));
}

// ======================= fp16-in fp16-staged GEMM core =======================
// A/B already fp16 in gmem. uint2 (4 halves) per thread per row-group, same
// STS addresses as before (conflict behavior unchanged), no cvt in mainloop.
template<int BM, int BN, int NC>
__device__ __forceinline__ void gemm_core_h2(
    const __half* const* aP, const __half* const* bP,
    __half* smh, float (&acc)[2][6][4], int tid)
{
    constexpr int nA  = BM / 32;
    constexpr int nB  = BN / 32;
    constexpr int BUF = (BM + BN) * 40;
    const int lane = tid & 31, w = tid >> 5;
    const int g = lane >> 2, tg = lane & 3;
    const int wr = (BM == 128) ? (w & 3) * 32 : (w & 1) * 32;
    const int wc = (BM == 128) ? (w >> 2) * 48 : (w >> 1) * 48;
    const int stsO = (tid >> 3) * 40 + 4 * (tid & 7);

    uint2 ra[nA], rb[nB];
#pragma unroll
    for (int i = 0; i < nA; i++) ra[i] = *(const uint2*)(aP[i]);
#pragma unroll
    for (int i = 0; i < nB; i++) rb[i] = *(const uint2*)(bP[i]);
#pragma unroll
    for (int i = 0; i < nA; i++) *(uint2*)(smh + stsO + 1280 * i) = ra[i];
#pragma unroll
    for (int i = 0; i < nB; i++) *(uint2*)(smh + BM * 40 + stsO + 1280 * i) = rb[i];
    __syncthreads();

#pragma unroll 1
    for (int c = 0; c < NC; c++) {
        if (c + 1 < NC) {
#pragma unroll
            for (int i = 0; i < nA; i++) ra[i] = *(const uint2*)(aP[i] + (c + 1) * 32);
#pragma unroll
            for (int i = 0; i < nB; i++) rb[i] = *(const uint2*)(bP[i] + (c + 1) * 32);
        }
        const __half* A  = smh + (c & 1) * BUF;
        const __half* Bs = A + BM * 40;
#pragma unroll
        for (int kk = 0; kk < 32; kk += 16) {
            unsigned af[2][4], bf[6][2];
#pragma unroll
            for (int mi = 0; mi < 2; mi++) {
                const __half* Ar = A + (wr + 16 * mi + g) * 40 + kk + 2 * tg;
                af[mi][0] = ldu(Ar);       af[mi][1] = ldu(Ar + 320);
                af[mi][2] = ldu(Ar + 8);   af[mi][3] = ldu(Ar + 328);
            }
#pragma unroll
            for (int ni = 0; ni < 6; ni++) {
                const __half* Br = Bs + (wc + 8 * ni + g) * 40 + kk + 2 * tg;
                bf[ni][0] = ldu(Br);  bf[ni][1] = ldu(Br + 8);
            }
#pragma unroll
            for (int mi = 0; mi < 2; mi++)
#pragma unroll
                for (int ni = 0; ni < 6; ni++)
                    mma16(acc[mi][ni], af[mi], bf[ni][0], bf[ni][1]);
        }
        if (c + 1 < NC) {
            __half* dA = smh + ((c + 1) & 1) * BUF;
#pragma unroll
            for (int i = 0; i < nA; i++) *(uint2*)(dA + stsO + 1280 * i) = ra[i];
#pragma unroll
            for (int i = 0; i < nB; i++) *(uint2*)(dA + BM * 40 + stsO + 1280 * i) = rb[i];
        }
        __syncthreads();
    }
}

template<int BM, int PST>
__device__ __forceinline__ void frag_store(float* St, float (&acc)[2][6][4], int tid) {
    const int lane = tid & 31, w = tid >> 5;
    const int g = lane >> 2, tg = lane & 3;
    const int wr = (BM == 128) ? (w & 3) * 32 : (w & 1) * 32;
    const int wc = (BM == 128) ? (w >> 2) * 48 : (w >> 1) * 48;
#pragma unroll
    for (int mi = 0; mi < 2; mi++)
#pragma unroll
        for (int ni = 0; ni < 6; ni++) {
            int row = wr + 16 * mi + g;
            int col = wc + 8 * ni + 2 * tg;
            St[row * PST + col]           = acc[mi][ni][0];
            St[row * PST + col + 1]       = acc[mi][ni][1];
            St[(row + 8) * PST + col]     = acc[mi][ni][2];
            St[(row + 8) * PST + col + 1] = acc[mi][ni][3];
        }
}

// ======================= tiny prep kernels =======================
__global__ void k_f2h(const float* __restrict__ src, __half* __restrict__ dst, int n) {
    int i = blockIdx.x * 256 + threadIdx.x;
    if (i < n) dst[i] = __float2half_rn(src[i]);
}

__global__ void k_bias(const int* __restrict__ relidx, const float* __restrict__ table) {
    int idx = blockIdx.x * 256 + threadIdx.x;
    if (idx < NHd * 4096) {
        int h = idx >> 12, r = idx & 4095;
        g_biash[idx] = __float2half_rn(table[relidx[r] * NHd + h]);
    }
}

// ======================= K0: transpose to token-major (fp32 xt + fp16 copies) ==
__global__ void k_transpose(const float* __restrict__ x, const float* __restrict__ feat) {
    __shared__ float t[32][33];
    int z = blockIdx.z;
    int b = z & 3, which = z >> 2;
    int c0 = blockIdx.x << 5;
    int p0 = blockIdx.y << 5;
    const float* src = (which ? feat : x) + (size_t)b * Cd * HWd;
    int tx = threadIdx.x, ty = threadIdx.y;
#pragma unroll
    for (int i = ty; i < 32; i += 8)
        t[i][tx] = src[(size_t)(c0 + i) * HWd + p0 + tx];
    __syncthreads();
    if (which) {
        __half* dh = g_fth + (size_t)b * HWd * Cd;
#pragma unroll
        for (int i = ty; i < 32; i += 8)
            dh[(size_t)(p0 + i) * Cd + c0 + tx] = __float2half_rn(t[tx][i]);
    } else {
        float*  df = g_xt  + (size_t)b * HWd * Cd;
        __half* dh = g_xth + (size_t)b * HWd * Cd;
#pragma unroll
        for (int i = ty; i < 32; i += 8) {
            float v = t[tx][i];
            df[(size_t)(p0 + i) * Cd + c0 + tx] = v;
            dh[(size_t)(p0 + i) * Cd + c0 + tx] = __float2half_rn(v);
        }
    }
}

// ======================= K1: gathered QKV GEMM =======================
// grid (3, 4096): x = 0->Q, 1->K, 2->V. BM=64 (1 window), BN=192.
__global__ void __launch_bounds__(256, 2) k_qkv(
    const float* __restrict__ q_b, const float* __restrict__ kv_b)
{
    extern __shared__ float sm[];
    __half* smh = (__half*)sm;
    __shared__ int tok[64];
    int tid = threadIdx.x;
    int which = blockIdx.x;
    int win = blockIdx.y;
    if (tid < 64) {
        int n = tid;
        int b = win >> 10, wh = (win >> 5) & 31, ww = win & 31;
        int h = (wh * 8 + (n >> 3) + 4) & 255;
        int w = (ww * 8 + (n & 7) + 4) & 255;
        tok[tid] = (b << 16) | (h << 8) | w;
    }
    __syncthreads();
    const __half* src = (which == 0) ? g_xth : g_fth;
    const __half* W   = (which == 0) ? w_qh : (which == 1 ? w_kvh : (w_kvh + 192 * 192));
    const int r0 = tid >> 3, c4 = 4 * (tid & 7);
    const __half* aP[2]; const __half* bP[6];
#pragma unroll
    for (int i = 0; i < 2; i++) aP[i] = src + (size_t)tok[r0 + 32 * i] * 192 + c4;
#pragma unroll
    for (int i = 0; i < 6; i++) bP[i] = W + (size_t)(r0 + 32 * i) * 192 + c4;

    float acc[2][6][4];
#pragma unroll
    for (int a = 0; a < 2; a++)
#pragma unroll
        for (int b2 = 0; b2 < 6; b2++)
#pragma unroll
            for (int cc = 0; cc < 4; cc++) acc[a][b2][cc] = 0.f;
    gemm_core_h2<64, 192, 6>(aP, bP, smh, acc, tid);

    float* St = sm;
    frag_store<64, 200>(St, acc, tid);
    __syncthreads();

    if (which < 2) {
        __half* dst = (which == 0) ? g_qh : g_kh;
        const float* bias = (which == 0) ? q_b : kv_b;
#pragma unroll 1
        for (int p = tid; p < 64 * 48; p += 256) {
            int m = p / 48, j4 = 4 * (p - (p / 48) * 48);
            __half hv[4];
#pragma unroll
            for (int e = 0; e < 4; e++) {
                float val = St[m * 200 + j4 + e] + bias[j4 + e];
                if (which == 0) val *= QSCALE;
                hv[e] = __float2half_rn(val);
            }
            size_t didx = (((size_t)win * NHd + (j4 >> 5)) * 64 + m) * HDd + (j4 & 31);
            *reinterpret_cast<uint2*>(dst + didx) = *reinterpret_cast<uint2*>(hv);
        }
    } else {
        // V: transpose to [win][h][d][n]
#pragma unroll 1
        for (int p = tid; p < 1536; p += 256) {
            int h = p >> 8, d = (p >> 3) & 31, ng = p & 7;
            int j = h * 32 + d;
            float bv = kv_b[192 + j];
            __half hv[8];
#pragma unroll
            for (int r = 0; r < 8; r++)
                hv[r] = __float2half_rn(St[(ng * 8 + r) * 200 + j] + bv);
            size_t didx = (((size_t)win * NHd + h) * HDd + d) * 64 + ng * 8;
            *reinterpret_cast<uint4*>(g_vh + didx) = *reinterpret_cast<uint4*>(hv);
        }
    }
}

// ======================= K2: attention =======================
// fp16 mma, Q fragments direct from gmem, analytic shift mask, fp16 bias/out.
__global__ void __launch_bounds__(256, 2) k_attn()
{
    extern __shared__ float smf[];
    __half* Kh = (__half*)smf;            // 6 heads * [64][40]
    __half* Vt = Kh + 15360;              // 6 heads * [32][72]
    int win = blockIdx.x;
    int tid = threadIdx.x;
    int lane = tid & 31, w = tid >> 5;
    int g = lane >> 2, tg = lane & 3;
    int mi = w & 3, hp = w >> 2;

    size_t qkbase = (size_t)win * NHd * 64 * HDd;
    size_t vbase  = (size_t)win * NHd * HDd * 64;
#pragma unroll 1
    for (int p = tid; p < 1536; p += 256) {
        int h = p >> 8, rem = p & 255;
        int n = rem >> 2, u = rem & 3;
        uint4 v = *reinterpret_cast<const uint4*>(g_kh + qkbase + (h * 64 + n) * 32 + 8 * u);
        *reinterpret_cast<uint4*>(Kh + h * 2560 + n * 40 + 8 * u) = v;
    }
#pragma unroll 1
    for (int p = tid; p < 1536; p += 256) {
        int h = p >> 8, rem = p & 255;
        int d = rem >> 3, u = rem & 7;
        uint4 v = *reinterpret_cast<const uint4*>(g_vh + vbase + (h * 32 + d) * 64 + 8 * u);
        *reinterpret_cast<uint4*>(Vt + h * 2304 + d * 72 + 8 * u) = v;
    }
    __syncthreads();

    int i0 = 16 * mi + g;
    // analytic shift-window mask regions
    int w10 = win & 1023;
    bool eh = ((w10 >> 5) == 31), ew = ((w10 & 31) == 31);
    bool edge = eh || ew;
    int ri0 = 0, ri1 = 0, rj0a[8], rj1a[8];
    if (edge) {
        auto region = [&](int n) {
            int a = eh ? (((n >> 3) >= 4) ? 2 : 1) : 0;
            int b = ew ? (((n & 7)  >= 4) ? 2 : 1) : 0;
            return a * 3 + b;
        };
        ri0 = region(i0); ri1 = region(i0 + 8);
#pragma unroll
        for (int ni = 0; ni < 8; ni++) {
            int j0 = 8 * ni + 2 * tg;
            rj0a[ni] = region(j0);
            rj1a[ni] = region(j0 + 1);
        }
    }

#pragma unroll 1
    for (int t = 0; t < 3; t++) {
        int h = 2 * t + hp;
        // Q fragments straight from gmem
        const __half* Qg = g_qh + qkbase + (size_t)h * 2048 + i0 * 32 + 2 * tg;
        unsigned aq[2][4];
#pragma unroll
        for (int ks = 0; ks < 2; ks++) {
            aq[ks][0] = ldu(Qg + 16 * ks);
            aq[ks][1] = ldu(Qg + 16 * ks + 256);
            aq[ks][2] = ldu(Qg + 16 * ks + 8);
            aq[ks][3] = ldu(Qg + 16 * ks + 264);
        }
        float s[8][4];
#pragma unroll
        for (int ni = 0; ni < 8; ni++)
#pragma unroll
            for (int e = 0; e < 4; e++) s[ni][e] = 0.f;
        const __half* Kb = Kh + h * 2560 + g * 40 + 2 * tg;
#pragma unroll
        for (int ni = 0; ni < 8; ni++) {
            mma16(s[ni], aq[0], ldu(Kb + ni * 320),      ldu(Kb + ni * 320 + 8));
            mma16(s[ni], aq[1], ldu(Kb + ni * 320 + 16), ldu(Kb + ni * 320 + 24));
        }
        // rel-pos bias (fp16 table)
        const __half* bb0 = g_biash + (h * 64 + i0) * 64;
#pragma unroll
        for (int ni = 0; ni < 8; ni++) {
            int j0 = 8 * ni + 2 * tg;
            float2 f0 = __half22float2(*(const __half2*)(bb0 + j0));
            float2 f1 = __half22float2(*(const __half2*)(bb0 + 512 + j0));
            s[ni][0] += f0.x; s[ni][1] += f0.y;
            s[ni][2] += f1.x; s[ni][3] += f1.y;
        }
        if (edge) {
#pragma unroll
            for (int ni = 0; ni < 8; ni++) {
                if (rj0a[ni] != ri0) s[ni][0] -= 100.f;
                if (rj1a[ni] != ri0) s[ni][1] -= 100.f;
                if (rj0a[ni] != ri1) s[ni][2] -= 100.f;
                if (rj1a[ni] != ri1) s[ni][3] -= 100.f;
            }
        }
        // softmax over 64 cols (quad = 4 lanes holds a full row pair)
        float m0 = -1e30f, m1 = -1e30f;
#pragma unroll
        for (int ni = 0; ni < 8; ni++) {
            m0 = fmaxf(m0, fmaxf(s[ni][0], s[ni][1]));
            m1 = fmaxf(m1, fmaxf(s[ni][2], s[ni][3]));
        }
        m0 = fmaxf(m0, __shfl_xor_sync(0xffffffffu, m0, 1));
        m0 = fmaxf(m0, __shfl_xor_sync(0xffffffffu, m0, 2));
        m1 = fmaxf(m1, __shfl_xor_sync(0xffffffffu, m1, 1));
        m1 = fmaxf(m1, __shfl_xor_sync(0xffffffffu, m1, 2));
        float s0 = 0.f, s1 = 0.f;
#pragma unroll
        for (int ni = 0; ni < 8; ni++) {
            s[ni][0] = __expf(s[ni][0] - m0); s0 += s[ni][0];
            s[ni][1] = __expf(s[ni][1] - m0); s0 += s[ni][1];
            s[ni][2] = __expf(s[ni][2] - m1); s1 += s[ni][2];
            s[ni][3] = __expf(s[ni][3] - m1); s1 += s[ni][3];
        }
        s0 += __shfl_xor_sync(0xffffffffu, s0, 1);
        s0 += __shfl_xor_sync(0xffffffffu, s0, 2);
        s1 += __shfl_xor_sync(0xffffffffu, s1, 1);
        s1 += __shfl_xor_sync(0xffffffffu, s1, 2);
        float inv0 = 1.f / s0, inv1 = 1.f / s1;
        unsigned pv[4][4];
#pragma unroll
        for (int js = 0; js < 4; js++) {
            pv[js][0] = h2u(__floats2half2_rn(s[2*js][0]   * inv0, s[2*js][1]   * inv0));
            pv[js][1] = h2u(__floats2half2_rn(s[2*js][2]   * inv1, s[2*js][3]   * inv1));
            pv[js][2] = h2u(__floats2half2_rn(s[2*js+1][0] * inv0, s[2*js+1][1] * inv0));
            pv[js][3] = h2u(__floats2half2_rn(s[2*js+1][2] * inv1, s[2*js+1][3] * inv1));
        }
        // P @ V
        float o[4][4];
#pragma unroll
        for (int nd = 0; nd < 4; nd++)
#pragma unroll
            for (int e = 0; e < 4; e++) o[nd][e] = 0.f;
        const __half* Vb = Vt + h * 2304 + g * 72 + 2 * tg;
#pragma unroll
        for (int nd = 0; nd < 4; nd++)
#pragma unroll
            for (int js = 0; js < 4; js++)
                mma16(o[nd], pv[js], ldu(Vb + nd * 576 + 16 * js),
                                     ldu(Vb + nd * 576 + 16 * js + 8));
        // store fp16 to g_attnh [win][n][192]
        __half* ob = g_attnh + ((size_t)win * 64) * Cd + h * HDd;
#pragma unroll
        for (int nd = 0; nd < 4; nd++) {
            int d0 = 8 * nd + 2 * tg;
            *(__half2*)(ob + (size_t)i0 * Cd + d0) =
                __floats2half2_rn(o[nd][0], o[nd][1]);
            *(__half2*)(ob + (size_t)(i0 + 8) * Cd + d0) =
                __floats2half2_rn(o[nd][2], o[nd][3]);
        }
    }
}

// ======================= K3: proj GEMM + scatter (fp16 out) =======================
__global__ void __launch_bounds__(256, 2) k_proj(const float* __restrict__ pb)
{
    extern __shared__ float sm[];
    __half* smh = (__half*)sm;
    __shared__ int ppix[128];
    int tid = threadIdx.x;
    int colbase = blockIdx.x * 96;
    size_t mbase = (size_t)blockIdx.y * 128;
    if (tid < 128) {
        int win = blockIdx.y * 2 + (tid >> 6);
        int n = tid & 63;
        int b = win >> 10, wh = (win >> 5) & 31, ww = win & 31;
        int h = (wh * 8 + (n >> 3) + 4) & 255;
        int w = (ww * 8 + (n & 7) + 4) & 255;
        ppix[tid] = (b << 16) | (h << 8) | w;
    }
    const int r0 = tid >> 3, c4 = 4 * (tid & 7);
    const __half* aP[4]; const __half* bP[3];
#pragma unroll
    for (int i = 0; i < 4; i++) aP[i] = g_attnh + (mbase + r0 + 32 * i) * 192 + c4;
#pragma unroll
    for (int i = 0; i < 3; i++) bP[i] = w_ph + (size_t)(colbase + r0 + 32 * i) * 192 + c4;
    float acc[2][6][4];
#pragma unroll
    for (int a = 0; a < 2; a++)
#pragma unroll
        for (int b2 = 0; b2 < 6; b2++)
#pragma unroll
            for (int cc = 0; cc < 4; cc++) acc[a][b2][cc] = 0.f;
    gemm_core_h2<128, 96, 6>(aP, bP, smh, acc, tid);
    float* St = sm;
    frag_store<128, 104>(St, acc, tid);
    __syncthreads();
#pragma unroll 1
    for (int p = tid; p < 128 * 24; p += 256) {
        int m = p / 24, j4 = 4 * (p - (p / 24) * 24);
        int col = colbase + j4;
        __half hv[4];
#pragma unroll
        for (int e = 0; e < 4; e++)
            hv[e] = __float2half_rn(St[m * 104 + j4 + e] + pb[col + e]);
        *reinterpret_cast<uint2*>(g_projh + (size_t)ppix[m] * Cd + col) =
            *reinterpret_cast<uint2*>(hv);
    }
}

// ======================= K4: merge GEMM + LN + shortcut =======================
__global__ void __launch_bounds__(256, 2) k_merge(
    const float* __restrict__ g1, const float* __restrict__ b1)
{
    extern __shared__ float sm[];
    __half* smh = (__half*)sm;
    int tid = threadIdx.x;
    size_t mbase = (size_t)blockIdx.x * 64;
    const int r0 = tid >> 3, c4 = 4 * (tid & 7);
    const __half* aP[2]; const __half* bP[6];
#pragma unroll
    for (int i = 0; i < 2; i++) aP[i] = g_projh + (mbase + r0 + 32 * i) * 192 + c4;
#pragma unroll
    for (int i = 0; i < 6; i++) bP[i] = w_mh + (size_t)(r0 + 32 * i) * 192 + c4;
    float acc[2][6][4];
#pragma unroll
    for (int a = 0; a < 2; a++)
#pragma unroll
        for (int b2 = 0; b2 < 6; b2++)
#pragma unroll
            for (int cc = 0; cc < 4; cc++) acc[a][b2][cc] = 0.f;
    gemm_core_h2<64, 192, 6>(aP, bP, smh, acc, tid);
    float* St = sm;
    frag_store<64, 200>(St, acc, tid);
    __syncthreads();
    int wp = tid >> 5, l = tid & 31;
#pragma unroll 1
    for (int rr = 0; rr < 8; rr++) {
        int r = wp * 8 + rr;
        float vv[6]; float su = 0.f;
#pragma unroll
        for (int u = 0; u < 6; u++) { vv[u] = St[r * 200 + l + 32 * u]; su += vv[u]; }
        su = warp_sum(su);
        float mean = su * (1.f / 192.f);
        float sq = 0.f;
#pragma unroll
        for (int u = 0; u < 6; u++) { float d = vv[u] - mean; sq += d * d; }
        sq = warp_sum(sq);
        float rstd = rsqrtf(sq * (1.f / 192.f) + 1e-5f);
        size_t row = (mbase + r) * Cd;
#pragma unroll
        for (int u = 0; u < 6; u++) {
            int c = l + 32 * u;
            float y = (vv[u] - mean) * rstd * g1[c] + b1[c] + g_xt[row + c];
            g_x1[row + c]  = y;
            g_x1h[row + c] = __float2half_rn(y);
        }
    }
}

// ======================= K5a: fc1 + GELU (fp16 out) =======================
__global__ void __launch_bounds__(256, 2) k_fc1(const float* __restrict__ b1h)
{
    extern __shared__ float sm[];
    __half* smh = (__half*)sm;
    int tid = threadIdx.x;
    int colbase = blockIdx.x * 96;
    size_t mbase = (size_t)blockIdx.y * 128;
    const int r0 = tid >> 3, c4 = 4 * (tid & 7);
    const __half* aP[4]; const __half* bP[3];
#pragma unroll
    for (int i = 0; i < 4; i++) aP[i] = g_x1h + (mbase + r0 + 32 * i) * 192 + c4;
#pragma unroll
    for (int i = 0; i < 3; i++) bP[i] = w_f1h + (size_t)(colbase + r0 + 32 * i) * 192 + c4;
    float acc[2][6][4];
#pragma unroll
    for (int a = 0; a < 2; a++)
#pragma unroll
        for (int b2 = 0; b2 < 6; b2++)
#pragma unroll
            for (int cc = 0; cc < 4; cc++) acc[a][b2][cc] = 0.f;
    gemm_core_h2<128, 96, 6>(aP, bP, smh, acc, tid);
    float* St = sm;
    frag_store<128, 104>(St, acc, tid);
    __syncthreads();
#pragma unroll 1
    for (int p = tid; p < 128 * 24; p += 256) {
        int m = p / 24, j4 = 4 * (p - (p / 24) * 24);
        int col = colbase + j4;
        __half hv[4];
#pragma unroll
        for (int e = 0; e < 4; e++) {
            float val = St[m * 104 + j4 + e] + b1h[col + e];
            val = 0.5f * val * (1.f + erff(val * 0.70710678118654752f));
            hv[e] = __float2half_rn(val);
        }
        *reinterpret_cast<uint2*>(g_h1h + (mbase + m) * HIDd + col) =
            *reinterpret_cast<uint2*>(hv);
    }
}

// ======================= K5b: fc2 + LN + residual =======================
__global__ void __launch_bounds__(256, 2) k_fc2(
    const float* __restrict__ b2,
    const float* __restrict__ g2, const float* __restrict__ bb2,
    float* __restrict__ out)
{
    extern __shared__ float sm[];
    __half* smh = (__half*)sm;
    int tid = threadIdx.x;
    size_t mbase = (size_t)blockIdx.x * 64;
    const int r0 = tid >> 3, c4 = 4 * (tid & 7);
    const __half* aP[2]; const __half* bP[6];
#pragma unroll
    for (int i = 0; i < 2; i++) aP[i] = g_h1h + (mbase + r0 + 32 * i) * 768 + c4;
#pragma unroll
    for (int i = 0; i < 6; i++) bP[i] = w_f2h + (size_t)(r0 + 32 * i) * 768 + c4;
    float acc[2][6][4];
#pragma unroll
    for (int a = 0; a < 2; a++)
#pragma unroll
        for (int b2i = 0; b2i < 6; b2i++)
#pragma unroll
            for (int cc = 0; cc < 4; cc++) acc[a][b2i][cc] = 0.f;
    gemm_core_h2<64, 192, 24>(aP, bP, smh, acc, tid);
    float* St = sm;
    frag_store<64, 200>(St, acc, tid);
    __syncthreads();
    int wp = tid >> 5, l = tid & 31;
#pragma unroll 1
    for (int rr = 0; rr < 8; rr++) {
        int r = wp * 8 + rr;
        float vv[6]; float su = 0.f;
#pragma unroll
        for (int u = 0; u < 6; u++) {
            int c = l + 32 * u;
            vv[u] = St[r * 200 + c] + b2[c];
            su += vv[u];
        }
        su = warp_sum(su);
        float mean = su * (1.f / 192.f);
        float sq = 0.f;
#pragma unroll
        for (int u = 0; u < 6; u++) { float d = vv[u] - mean; sq += d * d; }
        sq = warp_sum(sq);
        float rstd = rsqrtf(sq * (1.f / 192.f) + 1e-5f);
        size_t row = (mbase + r) * Cd;
#pragma unroll
        for (int u = 0; u < 6; u++) {
            int c = l + 32 * u;
            out[row + c] = g_x1[row + c] + (vv[u] - mean) * rstd * g2[c] + bb2[c];
        }
    }
}

// ======================= host =======================
extern "C" void kernel_launch(void* const* d_in, const int* in_sizes, int n_in,
                              void* d_out, int out_size)
{
    const float* x    = (const float*)d_in[0];
    const float* feat = (const float*)d_in[1];
    const int*   ridx = (const int*)  d_in[3];
    const float* rtab = (const float*)d_in[4];
    const float* q_w  = (const float*)d_in[5];
    const float* q_b  = (const float*)d_in[6];
    const float* kv_w = (const float*)d_in[7];
    const float* kv_b = (const float*)d_in[8];
    const float* p_w  = (const float*)d_in[9];
    const float* p_b  = (const float*)d_in[10];
    const float* m_w  = (const float*)d_in[11];
    const float* n1g  = (const float*)d_in[12];
    const float* n1b  = (const float*)d_in[13];
    const float* n2g  = (const float*)d_in[14];
    const float* n2b  = (const float*)d_in[15];
    const float* f1w  = (const float*)d_in[16];
    const float* f1b  = (const float*)d_in[17];
    const float* f2w  = (const float*)d_in[18];
    const float* f2b  = (const float*)d_in[19];
    float* out = (float*)d_out;

    __half *dwq, *dwkv, *dwp, *dwm, *dwf1, *dwf2;
    cudaGetSymbolAddress((void**)&dwq,  w_qh);
    cudaGetSymbolAddress((void**)&dwkv, w_kvh);
    cudaGetSymbolAddress((void**)&dwp,  w_ph);
    cudaGetSymbolAddress((void**)&dwm,  w_mh);
    cudaGetSymbolAddress((void**)&dwf1, w_f1h);
    cudaGetSymbolAddress((void**)&dwf2, w_f2h);

    const int smBig  = 128 * 104 * (int)sizeof(float);   // 53248
    const int smWide = 64 * 200 * (int)sizeof(float);    // 51200
    const int smAttn = (15360 + 13824) * 2;              // 58368
    cudaFuncSetAttribute(k_qkv,   cudaFuncAttributeMaxDynamicSharedMemorySize, smWide);
    cudaFuncSetAttribute(k_proj,  cudaFuncAttributeMaxDynamicSharedMemorySize, smBig);
    cudaFuncSetAttribute(k_fc1,   cudaFuncAttributeMaxDynamicSharedMemorySize, smBig);
    cudaFuncSetAttribute(k_merge, cudaFuncAttributeMaxDynamicSharedMemorySize, smWide);
    cudaFuncSetAttribute(k_fc2,   cudaFuncAttributeMaxDynamicSharedMemorySize, smWide);
    cudaFuncSetAttribute(k_attn,  cudaFuncAttributeMaxDynamicSharedMemorySize, smAttn);

    k_f2h<<<144, 256>>>(q_w,  dwq,  36864);
    k_f2h<<<288, 256>>>(kv_w, dwkv, 73728);
    k_f2h<<<144, 256>>>(p_w,  dwp,  36864);
    k_f2h<<<144, 256>>>(m_w,  dwm,  36864);
    k_f2h<<<576, 256>>>(f1w,  dwf1, 147456);
    k_f2h<<<576, 256>>>(f2w,  dwf2, 147456);
    k_bias<<<96, 256>>>(ridx, rtab);
    k_transpose<<<dim3(6, 2048, 8), dim3(32, 8)>>>(x, feat);
    k_qkv  <<<dim3(3, 4096), 256, smWide>>>(q_b, kv_b);
    k_attn <<<NWINd, 256, smAttn>>>();
    k_proj <<<dim3(2, 2048), 256, smBig>>>(p_b);
    k_merge<<<4096, 256, smWide>>>(n1g, n1b);
    k_fc1  <<<dim3(8, 2048), 256, smBig>>>(f1b);
    k_fc2  <<<4096, 256, smWide>>>(f2b, n2g, n2b, out);
}

// round 5
// speedup vs baseline: 6.0199x; 1.0479x over previous
#include <cuda_runtime.h>
#include <cuda_fp16.h>
#include <math.h>
#include <stdint.h>

#define Hd    256
#define Wdim  256
#define HWd   65536
#define Cd    192
#define Bd    4
#define NHd   6
#define HDd   32
#define NWINd 4096
#define MTOKd 262144
#define HIDd  768
#define QSCALE 0.17677669529663687f

// -------- scratch --------
__device__ float  g_xt  [(size_t)MTOKd * Cd];           // fp32 pixel-order (shortcut)
__device__ __half g_xth [(size_t)MTOKd * Cd];           // fp16 WINDOW-order
__device__ __half g_fth [(size_t)MTOKd * Cd];           // fp16 WINDOW-order
__device__ __half g_qh  [(size_t)NWINd * NHd * 64 * HDd];
__device__ __half g_kh  [(size_t)NWINd * NHd * 64 * HDd];
__device__ __half g_vh  [(size_t)NWINd * NHd * HDd * 64];
__device__ __half g_biash[NHd * 64 * 64];
__device__ __half g_attnh[(size_t)NWINd * 64 * Cd];
__device__ __half g_projh[(size_t)MTOKd * Cd];          // pixel order
__device__ float  g_x1  [(size_t)MTOKd * Cd];
__device__ __half g_x1h [(size_t)MTOKd * Cd];
__device__ __half w_qh [36864];
__device__ __half w_kvh[73728];
__device__ __half w_ph [36864];
__device__ __half w_mh [36864];
__device__ __half w_f1h[147456];
__device__ __half w_f2h[147456];

__device__ __forceinline__ float warp_sum(float v) {
#pragma unroll
    for (int o = 16; o; o >>= 1) v += __shfl_xor_sync(0xffffffffu, v, o);
    return v;
}
__device__ __forceinline__ unsigned h2u(__half2 h) {
    return *reinterpret_cast<unsigned*>(&h);
}
__device__ __forceinline__ unsigned ldu(const __half* p) {
    return *reinterpret_cast<const unsigned*>(p);
}
__device__ __forceinline__ float gelu_f(float v) {
    return 0.5f * v * (1.f + erff(v * 0.70710678118654752f));
}
__device__ __forceinline__ void mma16(float* c, const unsigned* a, unsigned b0, unsigned b1) {
    asm volatile(
        "mma.sync.aligned.m16n8k16.row.col.f32.f16.f16.f32 "
        "{%0,%1,%2,%3}, {%4,%5,%6,%7}, {%8,%9}, {%0,%1,%2,%3};"
        : "+f"(c[0]), "+f"(c[1]), "+f"(c[2]), "+f"(c[3])
        : "r"(a[0]), "r"(a[1]), "r"(a[2]), "r"(a[3]), "r"(b0), "r"(b1));
}

// ======================= fp16 GEMM core (A,B fp16 in gmem) =======================
template<int BM, int BN, int NC>
__device__ __forceinline__ void gemm_core_h2(
    const __half* const* aP, const __half* const* bP,
    __half* smh, float (&acc)[2][6][4], int tid)
{
    constexpr int nA  = BM / 32;
    constexpr int nB  = BN / 32;
    constexpr int BUF = (BM + BN) * 40;
    const int lane = tid & 31, w = tid >> 5;
    const int g = lane >> 2, tg = lane & 3;
    const int wr = (BM == 128) ? (w & 3) * 32 : (w & 1) * 32;
    const int wc = (BM == 128) ? (w >> 2) * 48 : (w >> 1) * 48;
    const int stsO = (tid >> 3) * 40 + 4 * (tid & 7);

    uint2 ra[nA], rb[nB];
#pragma unroll
    for (int i = 0; i < nA; i++) ra[i] = *(const uint2*)(aP[i]);
#pragma unroll
    for (int i = 0; i < nB; i++) rb[i] = *(const uint2*)(bP[i]);
#pragma unroll
    for (int i = 0; i < nA; i++) *(uint2*)(smh + stsO + 1280 * i) = ra[i];
#pragma unroll
    for (int i = 0; i < nB; i++) *(uint2*)(smh + BM * 40 + stsO + 1280 * i) = rb[i];
    __syncthreads();

#pragma unroll 1
    for (int c = 0; c < NC; c++) {
        if (c + 1 < NC) {
#pragma unroll
            for (int i = 0; i < nA; i++) ra[i] = *(const uint2*)(aP[i] + (c + 1) * 32);
#pragma unroll
            for (int i = 0; i < nB; i++) rb[i] = *(const uint2*)(bP[i] + (c + 1) * 32);
        }
        const __half* A  = smh + (c & 1) * BUF;
        const __half* Bs = A + BM * 40;
#pragma unroll
        for (int kk = 0; kk < 32; kk += 16) {
            unsigned af[2][4], bf[6][2];
#pragma unroll
            for (int mi = 0; mi < 2; mi++) {
                const __half* Ar = A + (wr + 16 * mi + g) * 40 + kk + 2 * tg;
                af[mi][0] = ldu(Ar);       af[mi][1] = ldu(Ar + 320);
                af[mi][2] = ldu(Ar + 8);   af[mi][3] = ldu(Ar + 328);
            }
#pragma unroll
            for (int ni = 0; ni < 6; ni++) {
                const __half* Br = Bs + (wc + 8 * ni + g) * 40 + kk + 2 * tg;
                bf[ni][0] = ldu(Br);  bf[ni][1] = ldu(Br + 8);
            }
#pragma unroll
            for (int mi = 0; mi < 2; mi++)
#pragma unroll
                for (int ni = 0; ni < 6; ni++)
                    mma16(acc[mi][ni], af[mi], bf[ni][0], bf[ni][1]);
        }
        if (c + 1 < NC) {
            __half* dA = smh + ((c + 1) & 1) * BUF;
#pragma unroll
            for (int i = 0; i < nA; i++) *(uint2*)(dA + stsO + 1280 * i) = ra[i];
#pragma unroll
            for (int i = 0; i < nB; i++) *(uint2*)(dA + BM * 40 + stsO + 1280 * i) = rb[i];
        }
        __syncthreads();
    }
}

template<int BM, int PST>
__device__ __forceinline__ void frag_store(float* St, float (&acc)[2][6][4], int tid) {
    const int lane = tid & 31, w = tid >> 5;
    const int g = lane >> 2, tg = lane & 3;
    const int wr = (BM == 128) ? (w & 3) * 32 : (w & 1) * 32;
    const int wc = (BM == 128) ? (w >> 2) * 48 : (w >> 1) * 48;
#pragma unroll
    for (int mi = 0; mi < 2; mi++)
#pragma unroll
        for (int ni = 0; ni < 6; ni++) {
            int row = wr + 16 * mi + g;
            int col = wc + 8 * ni + 2 * tg;
            St[row * PST + col]           = acc[mi][ni][0];
            St[row * PST + col + 1]       = acc[mi][ni][1];
            St[(row + 8) * PST + col]     = acc[mi][ni][2];
            St[(row + 8) * PST + col + 1] = acc[mi][ni][3];
        }
}

// ======================= prep kernels =======================
__global__ void k_f2h(const float* __restrict__ src, __half* __restrict__ dst, int n) {
    int i = blockIdx.x * 256 + threadIdx.x;
    if (i < n) dst[i] = __float2half_rn(src[i]);
}
__global__ void k_bias(const int* __restrict__ relidx, const float* __restrict__ table) {
    int idx = blockIdx.x * 256 + threadIdx.x;
    if (idx < NHd * 4096) {
        int h = idx >> 12, r = idx & 4095;
        g_biash[idx] = __float2half_rn(table[relidx[r] * NHd + h]);
    }
}

// ======================= K0: transpose; fp16 copies in WINDOW order =======================
__global__ void k_transpose(const float* __restrict__ x, const float* __restrict__ feat) {
    __shared__ float t[32][33];
    int z = blockIdx.z;
    int b = z & 3, which = z >> 2;
    int c0 = blockIdx.x << 5;
    int p0 = blockIdx.y << 5;
    const float* src = (which ? feat : x) + (size_t)b * Cd * HWd;
    int tx = threadIdx.x, ty = threadIdx.y;
#pragma unroll
    for (int i = ty; i < 32; i += 8)
        t[i][tx] = src[(size_t)(c0 + i) * HWd + p0 + tx];
    __syncthreads();
    int h  = p0 >> 8;
    int h2 = (h - 4) & 255;
    int whp = ((h2 >> 3) << 5);
    int nh8 = (h2 & 7) << 3;
    __half* dh = (which ? g_fth : g_xth) + (size_t)b * HWd * Cd;
    float*  df = g_xt + (size_t)b * HWd * Cd;
#pragma unroll
    for (int i = ty; i < 32; i += 8) {
        int wv = ((p0 & 255) + i);
        int w2 = (wv - 4) & 255;
        int tok = ((whp + (w2 >> 3)) << 6) + nh8 + (w2 & 7);
        float v = t[tx][i];
        dh[(size_t)tok * Cd + c0 + tx] = __float2half_rn(v);
        if (!which) df[(size_t)(p0 + i) * Cd + c0 + tx] = v;
    }
}

// ======================= K1: QKV GEMM (contiguous window-ordered A) =======================
__global__ void __launch_bounds__(256, 2) k_qkv(
    const float* __restrict__ q_b, const float* __restrict__ kv_b)
{
    extern __shared__ float sm[];
    __half* smh = (__half*)sm;
    int tid = threadIdx.x;
    int which = blockIdx.x;
    int win = blockIdx.y;
    const __half* src = (which == 0) ? g_xth : g_fth;
    const __half* W   = (which == 0) ? w_qh : (which == 1 ? w_kvh : (w_kvh + 192 * 192));
    const int r0 = tid >> 3, c4 = 4 * (tid & 7);
    const __half* aP[2]; const __half* bP[6];
#pragma unroll
    for (int i = 0; i < 2; i++) aP[i] = src + ((size_t)win * 64 + r0 + 32 * i) * 192 + c4;
#pragma unroll
    for (int i = 0; i < 6; i++) bP[i] = W + (size_t)(r0 + 32 * i) * 192 + c4;

    float acc[2][6][4];
#pragma unroll
    for (int a = 0; a < 2; a++)
#pragma unroll
        for (int b2 = 0; b2 < 6; b2++)
#pragma unroll
            for (int cc = 0; cc < 4; cc++) acc[a][b2][cc] = 0.f;
    gemm_core_h2<64, 192, 6>(aP, bP, smh, acc, tid);

    float* St = sm;
    frag_store<64, 200>(St, acc, tid);
    __syncthreads();

    if (which < 2) {
        __half* dst = (which == 0) ? g_qh : g_kh;
        const float* bias = (which == 0) ? q_b : kv_b;
#pragma unroll 1
        for (int p = tid; p < 64 * 48; p += 256) {
            int m = p / 48, j4 = 4 * (p - (p / 48) * 48);
            __half hv[4];
#pragma unroll
            for (int e = 0; e < 4; e++) {
                float val = St[m * 200 + j4 + e] + bias[j4 + e];
                if (which == 0) val *= QSCALE;
                hv[e] = __float2half_rn(val);
            }
            size_t didx = (((size_t)win * NHd + (j4 >> 5)) * 64 + m) * HDd + (j4 & 31);
            *reinterpret_cast<uint2*>(dst + didx) = *reinterpret_cast<uint2*>(hv);
        }
    } else {
#pragma unroll 1
        for (int p = tid; p < 1536; p += 256) {
            int h = p >> 8, d = (p >> 3) & 31, ng = p & 7;
            int j = h * 32 + d;
            float bv = kv_b[192 + j];
            __half hv[8];
#pragma unroll
            for (int r = 0; r < 8; r++)
                hv[r] = __float2half_rn(St[(ng * 8 + r) * 200 + j] + bv);
            size_t didx = (((size_t)win * NHd + h) * HDd + d) * 64 + ng * 8;
            *reinterpret_cast<uint4*>(g_vh + didx) = *reinterpret_cast<uint4*>(hv);
        }
    }
}

// ======================= K2: attention =======================
__global__ void __launch_bounds__(256, 2) k_attn()
{
    extern __shared__ float smf[];
    __half* Kh = (__half*)smf;
    __half* Vt = Kh + 15360;
    int win = blockIdx.x;
    int tid = threadIdx.x;
    int lane = tid & 31, w = tid >> 5;
    int g = lane >> 2, tg = lane & 3;
    int mi = w & 3, hp = w >> 2;

    size_t qkbase = (size_t)win * NHd * 64 * HDd;
    size_t vbase  = (size_t)win * NHd * HDd * 64;
#pragma unroll 1
    for (int p = tid; p < 1536; p += 256) {
        int h = p >> 8, rem = p & 255;
        int n = rem >> 2, u = rem & 3;
        uint4 v = *reinterpret_cast<const uint4*>(g_kh + qkbase + (h * 64 + n) * 32 + 8 * u);
        *reinterpret_cast<uint4*>(Kh + h * 2560 + n * 40 + 8 * u) = v;
    }
#pragma unroll 1
    for (int p = tid; p < 1536; p += 256) {
        int h = p >> 8, rem = p & 255;
        int d = rem >> 3, u = rem & 7;
        uint4 v = *reinterpret_cast<const uint4*>(g_vh + vbase + (h * 32 + d) * 64 + 8 * u);
        *reinterpret_cast<uint4*>(Vt + h * 2304 + d * 72 + 8 * u) = v;
    }
    __syncthreads();

    int i0 = 16 * mi + g;
    int w10 = win & 1023;
    bool eh = ((w10 >> 5) == 31), ew = ((w10 & 31) == 31);
    bool edge = eh || ew;
    int ri0 = 0, ri1 = 0, rj0a[8], rj1a[8];
    if (edge) {
        auto region = [&](int n) {
            int a = eh ? (((n >> 3) >= 4) ? 2 : 1) : 0;
            int b = ew ? (((n & 7)  >= 4) ? 2 : 1) : 0;
            return a * 3 + b;
        };
        ri0 = region(i0); ri1 = region(i0 + 8);
#pragma unroll
        for (int ni = 0; ni < 8; ni++) {
            int j0 = 8 * ni + 2 * tg;
            rj0a[ni] = region(j0);
            rj1a[ni] = region(j0 + 1);
        }
    }

#pragma unroll 1
    for (int t = 0; t < 3; t++) {
        int h = 2 * t + hp;
        const __half* Qg = g_qh + qkbase + (size_t)h * 2048 + i0 * 32 + 2 * tg;
        unsigned aq[2][4];
#pragma unroll
        for (int ks = 0; ks < 2; ks++) {
            aq[ks][0] = ldu(Qg + 16 * ks);
            aq[ks][1] = ldu(Qg + 16 * ks + 256);
            aq[ks][2] = ldu(Qg + 16 * ks + 8);
            aq[ks][3] = ldu(Qg + 16 * ks + 264);
        }
        float s[8][4];
#pragma unroll
        for (int ni = 0; ni < 8; ni++)
#pragma unroll
            for (int e = 0; e < 4; e++) s[ni][e] = 0.f;
        const __half* Kb = Kh + h * 2560 + g * 40 + 2 * tg;
#pragma unroll
        for (int ni = 0; ni < 8; ni++) {
            mma16(s[ni], aq[0], ldu(Kb + ni * 320),      ldu(Kb + ni * 320 + 8));
            mma16(s[ni], aq[1], ldu(Kb + ni * 320 + 16), ldu(Kb + ni * 320 + 24));
        }
        const __half* bb0 = g_biash + (h * 64 + i0) * 64;
#pragma unroll
        for (int ni = 0; ni < 8; ni++) {
            int j0 = 8 * ni + 2 * tg;
            float2 f0 = __half22float2(*(const __half2*)(bb0 + j0));
            float2 f1 = __half22float2(*(const __half2*)(bb0 + 512 + j0));
            s[ni][0] += f0.x; s[ni][1] += f0.y;
            s[ni][2] += f1.x; s[ni][3] += f1.y;
        }
        if (edge) {
#pragma unroll
            for (int ni = 0; ni < 8; ni++) {
                if (rj0a[ni] != ri0) s[ni][0] -= 100.f;
                if (rj1a[ni] != ri0) s[ni][1] -= 100.f;
                if (rj0a[ni] != ri1) s[ni][2] -= 100.f;
                if (rj1a[ni] != ri1) s[ni][3] -= 100.f;
            }
        }
        float m0 = -1e30f, m1 = -1e30f;
#pragma unroll
        for (int ni = 0; ni < 8; ni++) {
            m0 = fmaxf(m0, fmaxf(s[ni][0], s[ni][1]));
            m1 = fmaxf(m1, fmaxf(s[ni][2], s[ni][3]));
        }
        m0 = fmaxf(m0, __shfl_xor_sync(0xffffffffu, m0, 1));
        m0 = fmaxf(m0, __shfl_xor_sync(0xffffffffu, m0, 2));
        m1 = fmaxf(m1, __shfl_xor_sync(0xffffffffu, m1, 1));
        m1 = fmaxf(m1, __shfl_xor_sync(0xffffffffu, m1, 2));
        float s0 = 0.f, s1 = 0.f;
#pragma unroll
        for (int ni = 0; ni < 8; ni++) {
            s[ni][0] = __expf(s[ni][0] - m0); s0 += s[ni][0];
            s[ni][1] = __expf(s[ni][1] - m0); s0 += s[ni][1];
            s[ni][2] = __expf(s[ni][2] - m1); s1 += s[ni][2];
            s[ni][3] = __expf(s[ni][3] - m1); s1 += s[ni][3];
        }
        s0 += __shfl_xor_sync(0xffffffffu, s0, 1);
        s0 += __shfl_xor_sync(0xffffffffu, s0, 2);
        s1 += __shfl_xor_sync(0xffffffffu, s1, 1);
        s1 += __shfl_xor_sync(0xffffffffu, s1, 2);
        float inv0 = 1.f / s0, inv1 = 1.f / s1;
        unsigned pv[4][4];
#pragma unroll
        for (int js = 0; js < 4; js++) {
            pv[js][0] = h2u(__floats2half2_rn(s[2*js][0]   * inv0, s[2*js][1]   * inv0));
            pv[js][1] = h2u(__floats2half2_rn(s[2*js][2]   * inv1, s[2*js][3]   * inv1));
            pv[js][2] = h2u(__floats2half2_rn(s[2*js+1][0] * inv0, s[2*js+1][1] * inv0));
            pv[js][3] = h2u(__floats2half2_rn(s[2*js+1][2] * inv1, s[2*js+1][3] * inv1));
        }
        float o[4][4];
#pragma unroll
        for (int nd = 0; nd < 4; nd++)
#pragma unroll
            for (int e = 0; e < 4; e++) o[nd][e] = 0.f;
        const __half* Vb = Vt + h * 2304 + g * 72 + 2 * tg;
#pragma unroll
        for (int nd = 0; nd < 4; nd++)
#pragma unroll
            for (int js = 0; js < 4; js++)
                mma16(o[nd], pv[js], ldu(Vb + nd * 576 + 16 * js),
                                     ldu(Vb + nd * 576 + 16 * js + 8));
        __half* ob = g_attnh + ((size_t)win * 64) * Cd + h * HDd;
#pragma unroll
        for (int nd = 0; nd < 4; nd++) {
            int d0 = 8 * nd + 2 * tg;
            *(__half2*)(ob + (size_t)i0 * Cd + d0) =
                __floats2half2_rn(o[nd][0], o[nd][1]);
            *(__half2*)(ob + (size_t)(i0 + 8) * Cd + d0) =
                __floats2half2_rn(o[nd][2], o[nd][3]);
        }
    }
}

// ======================= K3: proj GEMM + scatter =======================
__global__ void __launch_bounds__(256, 2) k_proj(const float* __restrict__ pb)
{
    extern __shared__ float sm[];
    __half* smh = (__half*)sm;
    __shared__ int ppix[128];
    int tid = threadIdx.x;
    int colbase = blockIdx.x * 96;
    size_t mbase = (size_t)blockIdx.y * 128;
    if (tid < 128) {
        int win = blockIdx.y * 2 + (tid >> 6);
        int n = tid & 63;
        int b = win >> 10, wh = (win >> 5) & 31, ww = win & 31;
        int h = (wh * 8 + (n >> 3) + 4) & 255;
        int w = (ww * 8 + (n & 7) + 4) & 255;
        ppix[tid] = (b << 16) | (h << 8) | w;
    }
    const int r0 = tid >> 3, c4 = 4 * (tid & 7);
    const __half* aP[4]; const __half* bP[3];
#pragma unroll
    for (int i = 0; i < 4; i++) aP[i] = g_attnh + (mbase + r0 + 32 * i) * 192 + c4;
#pragma unroll
    for (int i = 0; i < 3; i++) bP[i] = w_ph + (size_t)(colbase + r0 + 32 * i) * 192 + c4;
    float acc[2][6][4];
#pragma unroll
    for (int a = 0; a < 2; a++)
#pragma unroll
        for (int b2 = 0; b2 < 6; b2++)
#pragma unroll
            for (int cc = 0; cc < 4; cc++) acc[a][b2][cc] = 0.f;
    gemm_core_h2<128, 96, 6>(aP, bP, smh, acc, tid);
    float* St = sm;
    frag_store<128, 104>(St, acc, tid);
    __syncthreads();
#pragma unroll 1
    for (int p = tid; p < 128 * 24; p += 256) {
        int m = p / 24, j4 = 4 * (p - (p / 24) * 24);
        int col = colbase + j4;
        __half hv[4];
#pragma unroll
        for (int e = 0; e < 4; e++)
            hv[e] = __float2half_rn(St[m * 104 + j4 + e] + pb[col + e]);
        *reinterpret_cast<uint2*>(g_projh + (size_t)ppix[m] * Cd + col) =
            *reinterpret_cast<uint2*>(hv);
    }
}

// ======================= K4: merge GEMM + LN + shortcut =======================
__global__ void __launch_bounds__(256, 2) k_merge(
    const float* __restrict__ g1, const float* __restrict__ b1)
{
    extern __shared__ float sm[];
    __half* smh = (__half*)sm;
    int tid = threadIdx.x;
    size_t mbase = (size_t)blockIdx.x * 64;
    const int r0 = tid >> 3, c4 = 4 * (tid & 7);
    const __half* aP[2]; const __half* bP[6];
#pragma unroll
    for (int i = 0; i < 2; i++) aP[i] = g_projh + (mbase + r0 + 32 * i) * 192 + c4;
#pragma unroll
    for (int i = 0; i < 6; i++) bP[i] = w_mh + (size_t)(r0 + 32 * i) * 192 + c4;
    float acc[2][6][4];
#pragma unroll
    for (int a = 0; a < 2; a++)
#pragma unroll
        for (int b2 = 0; b2 < 6; b2++)
#pragma unroll
            for (int cc = 0; cc < 4; cc++) acc[a][b2][cc] = 0.f;
    gemm_core_h2<64, 192, 6>(aP, bP, smh, acc, tid);
    float* St = sm;
    frag_store<64, 200>(St, acc, tid);
    __syncthreads();
    int wp = tid >> 5, l = tid & 31;
#pragma unroll 1
    for (int rr = 0; rr < 8; rr++) {
        int r = wp * 8 + rr;
        float vv[6]; float su = 0.f;
#pragma unroll
        for (int u = 0; u < 6; u++) { vv[u] = St[r * 200 + l + 32 * u]; su += vv[u]; }
        su = warp_sum(su);
        float mean = su * (1.f / 192.f);
        float sq = 0.f;
#pragma unroll
        for (int u = 0; u < 6; u++) { float d = vv[u] - mean; sq += d * d; }
        sq = warp_sum(sq);
        float rstd = rsqrtf(sq * (1.f / 192.f) + 1e-5f);
        size_t row = (mbase + r) * Cd;
#pragma unroll
        for (int u = 0; u < 6; u++) {
            int c = l + 32 * u;
            float y = (vv[u] - mean) * rstd * g1[c] + b1[c] + g_xt[row + c];
            g_x1[row + c]  = y;
            g_x1h[row + c] = __float2half_rn(y);
        }
    }
}

// ======================= K5: fused MLP (fc1 + GELU + fc2 + LN + residual) ==========
// BM=64. A (x1h 64x192) resident in smem; loop 8 chunks of 96 hidden cols:
//   S = A @ W1[chunk] (warp tile 32x24) -> GELU -> h1 chunk in smem ->
//   acc2 += h1 @ W2[chunk rows] (warp tile 32x48).
// smem halves: A 6*2560 | B1 2*3840 | H 3*2560 | B2 2*7680  = 46080 (92160 B)
__global__ void __launch_bounds__(256, 2) k_mlp(
    const float* __restrict__ b1h, const float* __restrict__ b2,
    const float* __restrict__ g2, const float* __restrict__ bb2,
    float* __restrict__ out)
{
    extern __shared__ float sm[];
    __half* smA  = (__half*)sm;
    __half* smB1 = smA + 15360;
    __half* smH  = smB1 + 7680;
    __half* smB2 = smH + 7680;
    int tid = threadIdx.x;
    size_t mbase = (size_t)blockIdx.x * 64;
    const int lane = tid & 31, w = tid >> 5;
    const int g = lane >> 2, tg = lane & 3;
    const int wr  = (w & 1) * 32;          // M split (both GEMMs)
    const int wc1 = (w >> 1) * 24;         // S-GEMM N split
    const int wc2 = (w >> 1) * 48;         // fc2 N split
    const int r0 = tid >> 3, c4 = 4 * (tid & 7);
    const int stsO = r0 * 40 + c4;

    // load full A (64x192) into 6 k-chunks
    const __half* aSrc = g_x1h + mbase * 192;
#pragma unroll
    for (int c = 0; c < 6; c++)
#pragma unroll
        for (int i = 0; i < 2; i++) {
            uint2 v = *(const uint2*)(aSrc + (size_t)(r0 + 32 * i) * 192 + c * 32 + c4);
            *(uint2*)(smA + c * 2560 + stsO + 1280 * i) = v;
        }

    float acc2[2][6][4];
#pragma unroll
    for (int a = 0; a < 2; a++)
#pragma unroll
        for (int b_ = 0; b_ < 6; b_++)
#pragma unroll
            for (int cc = 0; cc < 4; cc++) acc2[a][b_][cc] = 0.f;

#pragma unroll 1
    for (int oc = 0; oc < 8; oc++) {
        // ---------- S = A @ W1[oc] ----------
        const __half* W1 = w_f1h + (size_t)(oc * 96) * 192;
        uint2 rb1[3];
#pragma unroll
        for (int i = 0; i < 3; i++)
            rb1[i] = *(const uint2*)(W1 + (size_t)(r0 + 32 * i) * 192 + c4);
#pragma unroll
        for (int i = 0; i < 3; i++)
            *(uint2*)(smB1 + stsO + 1280 * i) = rb1[i];
        __syncthreads();   // covers A (oc==0) and B1 chunk 0

        float acc1[2][3][4];
#pragma unroll
        for (int a = 0; a < 2; a++)
#pragma unroll
            for (int b_ = 0; b_ < 3; b_++)
#pragma unroll
                for (int cc = 0; cc < 4; cc++) acc1[a][b_][cc] = 0.f;

#pragma unroll 1
        for (int kc = 0; kc < 6; kc++) {
            if (kc + 1 < 6)
#pragma unroll
                for (int i = 0; i < 3; i++)
                    rb1[i] = *(const uint2*)(W1 + (size_t)(r0 + 32 * i) * 192 + (kc + 1) * 32 + c4);
            const __half* Ab = smA + kc * 2560;
            const __half* Bb = smB1 + (kc & 1) * 3840;
#pragma unroll
            for (int kk = 0; kk < 32; kk += 16) {
                unsigned af[2][4], bf[3][2];
#pragma unroll
                for (int mi = 0; mi < 2; mi++) {
                    const __half* Ar = Ab + (wr + 16 * mi + g) * 40 + kk + 2 * tg;
                    af[mi][0] = ldu(Ar);       af[mi][1] = ldu(Ar + 320);
                    af[mi][2] = ldu(Ar + 8);   af[mi][3] = ldu(Ar + 328);
                }
#pragma unroll
                for (int ni = 0; ni < 3; ni++) {
                    const __half* Br = Bb + (wc1 + 8 * ni + g) * 40 + kk + 2 * tg;
                    bf[ni][0] = ldu(Br);  bf[ni][1] = ldu(Br + 8);
                }
#pragma unroll
                for (int mi = 0; mi < 2; mi++)
#pragma unroll
                    for (int ni = 0; ni < 3; ni++)
                        mma16(acc1[mi][ni], af[mi], bf[ni][0], bf[ni][1]);
            }
            if (kc + 1 < 6)
#pragma unroll
                for (int i = 0; i < 3; i++)
                    *(uint2*)(smB1 + ((kc + 1) & 1) * 3840 + stsO + 1280 * i) = rb1[i];
            __syncthreads();
        }

        // ---------- GELU -> smH (A-layout, 3 k-chunks of 32) ----------
#pragma unroll
        for (int mi = 0; mi < 2; mi++)
#pragma unroll
            for (int ni = 0; ni < 3; ni++) {
                int row = wr + 16 * mi + g;
                int col = wc1 + 8 * ni + 2 * tg;
                float2 bv = *(const float2*)(b1h + oc * 96 + col);
                __half* hp0 = smH + (col >> 5) * 2560 + row * 40 + (col & 31);
                *(__half2*)hp0 = __floats2half2_rn(
                    gelu_f(acc1[mi][ni][0] + bv.x), gelu_f(acc1[mi][ni][1] + bv.y));
                *(__half2*)(hp0 + 320) = __floats2half2_rn(
                    gelu_f(acc1[mi][ni][2] + bv.x), gelu_f(acc1[mi][ni][3] + bv.y));
            }

        // ---------- stage B2 chunk 0 + sync (covers smH too) ----------
        const __half* W2 = w_f2h;
        uint2 rb2[6];
#pragma unroll
        for (int i = 0; i < 6; i++)
            rb2[i] = *(const uint2*)(W2 + (size_t)(r0 + 32 * i) * 768 + oc * 96 + c4);
#pragma unroll
        for (int i = 0; i < 6; i++)
            *(uint2*)(smB2 + stsO + 1280 * i) = rb2[i];
        __syncthreads();

        // ---------- acc2 += h1 @ W2 ----------
#pragma unroll 1
        for (int kc = 0; kc < 3; kc++) {
            if (kc + 1 < 3)
#pragma unroll
                for (int i = 0; i < 6; i++)
                    rb2[i] = *(const uint2*)(W2 + (size_t)(r0 + 32 * i) * 768 + oc * 96 + (kc + 1) * 32 + c4);
            const __half* Ab = smH + kc * 2560;
            const __half* Bb = smB2 + (kc & 1) * 7680;
#pragma unroll
            for (int kk = 0; kk < 32; kk += 16) {
                unsigned af[2][4], bf[6][2];
#pragma unroll
                for (int mi = 0; mi < 2; mi++) {
                    const __half* Ar = Ab + (wr + 16 * mi + g) * 40 + kk + 2 * tg;
                    af[mi][0] = ldu(Ar);       af[mi][1] = ldu(Ar + 320);
                    af[mi][2] = ldu(Ar + 8);   af[mi][3] = ldu(Ar + 328);
                }
#pragma unroll
                for (int ni = 0; ni < 6; ni++) {
                    const __half* Br = Bb + (wc2 + 8 * ni + g) * 40 + kk + 2 * tg;
                    bf[ni][0] = ldu(Br);  bf[ni][1] = ldu(Br + 8);
                }
#pragma unroll
                for (int mi = 0; mi < 2; mi++)
#pragma unroll
                    for (int ni = 0; ni < 6; ni++)
                        mma16(acc2[mi][ni], af[mi], bf[ni][0], bf[ni][1]);
            }
            if (kc + 1 < 3)
#pragma unroll
                for (int i = 0; i < 6; i++)
                    *(uint2*)(smB2 + ((kc + 1) & 1) * 7680 + stsO + 1280 * i) = rb2[i];
            __syncthreads();
        }
    }

    // ---------- epilogue: bias + LN + residual ----------
    float* St = sm;   // overlaps dead smA/smB1 (51200 B < 92160 B)
    frag_store<64, 200>(St, acc2, tid);
    __syncthreads();
    int wp = tid >> 5, l = tid & 31;
#pragma unroll 1
    for (int rr = 0; rr < 8; rr++) {
        int r = wp * 8 + rr;
        float vv[6]; float su = 0.f;
#pragma unroll
        for (int u = 0; u < 6; u++) {
            int c = l + 32 * u;
            vv[u] = St[r * 200 + c] + b2[c];
            su += vv[u];
        }
        su = warp_sum(su);
        float mean = su * (1.f / 192.f);
        float sq = 0.f;
#pragma unroll
        for (int u = 0; u < 6; u++) { float d = vv[u] - mean; sq += d * d; }
        sq = warp_sum(sq);
        float rstd = rsqrtf(sq * (1.f / 192.f) + 1e-5f);
        size_t row = (mbase + r) * Cd;
#pragma unroll
        for (int u = 0; u < 6; u++) {
            int c = l + 32 * u;
            out[row + c] = g_x1[row + c] + (vv[u] - mean) * rstd * g2[c] + bb2[c];
        }
    }
}

// ======================= host =======================
extern "C" void kernel_launch(void* const* d_in, const int* in_sizes, int n_in,
                              void* d_out, int out_size)
{
    const float* x    = (const float*)d_in[0];
    const float* feat = (const float*)d_in[1];
    const int*   ridx = (const int*)  d_in[3];
    const float* rtab = (const float*)d_in[4];
    const float* q_w  = (const float*)d_in[5];
    const float* q_b  = (const float*)d_in[6];
    const float* kv_w = (const float*)d_in[7];
    const float* kv_b = (const float*)d_in[8];
    const float* p_w  = (const float*)d_in[9];
    const float* p_b  = (const float*)d_in[10];
    const float* m_w  = (const float*)d_in[11];
    const float* n1g  = (const float*)d_in[12];
    const float* n1b  = (const float*)d_in[13];
    const float* n2g  = (const float*)d_in[14];
    const float* n2b  = (const float*)d_in[15];
    const float* f1w  = (const float*)d_in[16];
    const float* f1b  = (const float*)d_in[17];
    const float* f2w  = (const float*)d_in[18];
    const float* f2b  = (const float*)d_in[19];
    float* out = (float*)d_out;

    __half *dwq, *dwkv, *dwp, *dwm, *dwf1, *dwf2;
    cudaGetSymbolAddress((void**)&dwq,  w_qh);
    cudaGetSymbolAddress((void**)&dwkv, w_kvh);
    cudaGetSymbolAddress((void**)&dwp,  w_ph);
    cudaGetSymbolAddress((void**)&dwm,  w_mh);
    cudaGetSymbolAddress((void**)&dwf1, w_f1h);
    cudaGetSymbolAddress((void**)&dwf2, w_f2h);

    const int smBig  = 128 * 104 * (int)sizeof(float);   // 53248
    const int smWide = 64 * 200 * (int)sizeof(float);    // 51200
    const int smAttn = (15360 + 13824) * 2;              // 58368
    const int smMlp  = 46080 * 2;                        // 92160
    cudaFuncSetAttribute(k_qkv,   cudaFuncAttributeMaxDynamicSharedMemorySize, smWide);
    cudaFuncSetAttribute(k_proj,  cudaFuncAttributeMaxDynamicSharedMemorySize, smBig);
    cudaFuncSetAttribute(k_merge, cudaFuncAttributeMaxDynamicSharedMemorySize, smWide);
    cudaFuncSetAttribute(k_attn,  cudaFuncAttributeMaxDynamicSharedMemorySize, smAttn);
    cudaFuncSetAttribute(k_mlp,   cudaFuncAttributeMaxDynamicSharedMemorySize, smMlp);

    k_f2h<<<144, 256>>>(q_w,  dwq,  36864);
    k_f2h<<<288, 256>>>(kv_w, dwkv, 73728);
    k_f2h<<<144, 256>>>(p_w,  dwp,  36864);
    k_f2h<<<144, 256>>>(m_w,  dwm,  36864);
    k_f2h<<<576, 256>>>(f1w,  dwf1, 147456);
    k_f2h<<<576, 256>>>(f2w,  dwf2, 147456);
    k_bias<<<96, 256>>>(ridx, rtab);
    k_transpose<<<dim3(6, 2048, 8), dim3(32, 8)>>>(x, feat);
    k_qkv  <<<dim3(3, 4096), 256, smWide>>>(q_b, kv_b);
    k_attn <<<NWINd, 256, smAttn>>>();
    k_proj <<<dim3(2, 2048), 256, smBig>>>(p_b);
    k_merge<<<4096, 256, smWide>>>(n1g, n1b);
    k_mlp  <<<4096, 256, smMlp>>>(f1b, f2b, n2g, n2b, out);
}

// round 6
// speedup vs baseline: 6.3071x; 1.0477x over previous
#include <cuda_runtime.h>
#include <cuda_fp16.h>
#include <math.h>
#include <stdint.h>

#define Hd    256
#define Wdim  256
#define HWd   65536
#define Cd    192
#define Bd    4
#define NHd   6
#define HDd   32
#define NWINd 4096
#define MTOKd 262144
#define HIDd  768
#define QSCALE 0.17677669529663687f

// -------- scratch --------
__device__ float  g_xt  [(size_t)MTOKd * Cd];           // fp32 pixel-order (shortcut)
__device__ __half g_xth [(size_t)MTOKd * Cd];           // fp16 WINDOW-order
__device__ __half g_fth [(size_t)MTOKd * Cd];           // fp16 WINDOW-order
__device__ __half g_qh  [(size_t)NWINd * NHd * 64 * HDd];
__device__ __half g_kh  [(size_t)NWINd * NHd * 64 * HDd];
__device__ __half g_vh  [(size_t)NWINd * NHd * HDd * 64];
__device__ __half g_biash[NHd * 64 * 64];
__device__ float  g_x1  [(size_t)MTOKd * Cd];
__device__ __half g_x1h [(size_t)MTOKd * Cd];
__device__ __half w_qh [36864];
__device__ __half w_kvh[73728];
__device__ __half w_ch [36864];     // combined merge@proj weight
__device__ float  g_bc [192];       // combined bias m_w @ p_b
__device__ __half w_f1h[147456];
__device__ __half w_f2h[147456];

__device__ __forceinline__ float warp_sum(float v) {
#pragma unroll
    for (int o = 16; o; o >>= 1) v += __shfl_xor_sync(0xffffffffu, v, o);
    return v;
}
__device__ __forceinline__ unsigned h2u(__half2 h) {
    return *reinterpret_cast<unsigned*>(&h);
}
__device__ __forceinline__ unsigned ldu(const __half* p) {
    return *reinterpret_cast<const unsigned*>(p);
}
__device__ __forceinline__ float gelu_f(float v) {
    return 0.5f * v * (1.f + erff(v * 0.70710678118654752f));
}
__device__ __forceinline__ void mma16(float* c, const unsigned* a, unsigned b0, unsigned b1) {
    asm volatile(
        "mma.sync.aligned.m16n8k16.row.col.f32.f16.f16.f32 "
        "{%0,%1,%2,%3}, {%4,%5,%6,%7}, {%8,%9}, {%0,%1,%2,%3};"
        : "+f"(c[0]), "+f"(c[1]), "+f"(c[2]), "+f"(c[3])
        : "r"(a[0]), "r"(a[1]), "r"(a[2]), "r"(a[3]), "r"(b0), "r"(b1));
}

// ======================= fp16 GEMM core (A,B fp16 in gmem) =======================
template<int BM, int BN, int NC>
__device__ __forceinline__ void gemm_core_h2(
    const __half* const* aP, const __half* const* bP,
    __half* smh, float (&acc)[2][6][4], int tid)
{
    constexpr int nA  = BM / 32;
    constexpr int nB  = BN / 32;
    constexpr int BUF = (BM + BN) * 40;
    const int lane = tid & 31, w = tid >> 5;
    const int g = lane >> 2, tg = lane & 3;
    const int wr = (BM == 128) ? (w & 3) * 32 : (w & 1) * 32;
    const int wc = (BM == 128) ? (w >> 2) * 48 : (w >> 1) * 48;
    const int stsO = (tid >> 3) * 40 + 4 * (tid & 7);

    uint2 ra[nA], rb[nB];
#pragma unroll
    for (int i = 0; i < nA; i++) ra[i] = *(const uint2*)(aP[i]);
#pragma unroll
    for (int i = 0; i < nB; i++) rb[i] = *(const uint2*)(bP[i]);
#pragma unroll
    for (int i = 0; i < nA; i++) *(uint2*)(smh + stsO + 1280 * i) = ra[i];
#pragma unroll
    for (int i = 0; i < nB; i++) *(uint2*)(smh + BM * 40 + stsO + 1280 * i) = rb[i];
    __syncthreads();

#pragma unroll 1
    for (int c = 0; c < NC; c++) {
        if (c + 1 < NC) {
#pragma unroll
            for (int i = 0; i < nA; i++) ra[i] = *(const uint2*)(aP[i] + (c + 1) * 32);
#pragma unroll
            for (int i = 0; i < nB; i++) rb[i] = *(const uint2*)(bP[i] + (c + 1) * 32);
        }
        const __half* A  = smh + (c & 1) * BUF;
        const __half* Bs = A + BM * 40;
#pragma unroll
        for (int kk = 0; kk < 32; kk += 16) {
            unsigned af[2][4], bf[6][2];
#pragma unroll
            for (int mi = 0; mi < 2; mi++) {
                const __half* Ar = A + (wr + 16 * mi + g) * 40 + kk + 2 * tg;
                af[mi][0] = ldu(Ar);       af[mi][1] = ldu(Ar + 320);
                af[mi][2] = ldu(Ar + 8);   af[mi][3] = ldu(Ar + 328);
            }
#pragma unroll
            for (int ni = 0; ni < 6; ni++) {
                const __half* Br = Bs + (wc + 8 * ni + g) * 40 + kk + 2 * tg;
                bf[ni][0] = ldu(Br);  bf[ni][1] = ldu(Br + 8);
            }
#pragma unroll
            for (int mi = 0; mi < 2; mi++)
#pragma unroll
                for (int ni = 0; ni < 6; ni++)
                    mma16(acc[mi][ni], af[mi], bf[ni][0], bf[ni][1]);
        }
        if (c + 1 < NC) {
            __half* dA = smh + ((c + 1) & 1) * BUF;
#pragma unroll
            for (int i = 0; i < nA; i++) *(uint2*)(dA + stsO + 1280 * i) = ra[i];
#pragma unroll
            for (int i = 0; i < nB; i++) *(uint2*)(dA + BM * 40 + stsO + 1280 * i) = rb[i];
        }
        __syncthreads();
    }
}

template<int BM, int PST>
__device__ __forceinline__ void frag_store(float* St, float (&acc)[2][6][4], int tid) {
    const int lane = tid & 31, w = tid >> 5;
    const int g = lane >> 2, tg = lane & 3;
    const int wr = (BM == 128) ? (w & 3) * 32 : (w & 1) * 32;
    const int wc = (BM == 128) ? (w >> 2) * 48 : (w >> 1) * 48;
#pragma unroll
    for (int mi = 0; mi < 2; mi++)
#pragma unroll
        for (int ni = 0; ni < 6; ni++) {
            int row = wr + 16 * mi + g;
            int col = wc + 8 * ni + 2 * tg;
            St[row * PST + col]           = acc[mi][ni][0];
            St[row * PST + col + 1]       = acc[mi][ni][1];
            St[(row + 8) * PST + col]     = acc[mi][ni][2];
            St[(row + 8) * PST + col + 1] = acc[mi][ni][3];
        }
}

// ======================= prep kernels =======================
__global__ void k_f2h(const float* __restrict__ src, __half* __restrict__ dst, int n) {
    int i = blockIdx.x * 256 + threadIdx.x;
    if (i < n) dst[i] = __float2half_rn(src[i]);
}
__global__ void k_f2h_s(const float* __restrict__ src, __half* __restrict__ dst,
                        int n, float s) {
    int i = blockIdx.x * 256 + threadIdx.x;
    if (i < n) dst[i] = __float2half_rn(src[i] * s);
}
__global__ void k_bias(const int* __restrict__ relidx, const float* __restrict__ table) {
    int idx = blockIdx.x * 256 + threadIdx.x;
    if (idx < NHd * 4096) {
        int h = idx >> 12, r = idx & 4095;
        g_biash[idx] = __float2half_rn(table[relidx[r] * NHd + h]);
    }
}
// combined weight Wc = m_w @ p_w (fp32 accumulate), bc = m_w @ p_b
__global__ void k_wcomb(const float* __restrict__ mw, const float* __restrict__ pw,
                        const float* __restrict__ pb) {
    int e = blockIdx.x * 256 + threadIdx.x;
    if (e < 36864) {
        int i = e / 192, j = e - (e / 192) * 192;
        float acc = 0.f;
        for (int k = 0; k < 192; k++) acc += mw[i * 192 + k] * pw[k * 192 + j];
        w_ch[e] = __float2half_rn(acc);
    }
    if (e < 192) {
        float acc = 0.f;
        for (int k = 0; k < 192; k++) acc += mw[e * 192 + k] * pb[k];
        g_bc[e] = acc;
    }
}

// ======================= K0: transpose; fp16 copies in WINDOW order =======================
__global__ void k_transpose(const float* __restrict__ x, const float* __restrict__ feat) {
    __shared__ float t[32][33];
    int z = blockIdx.z;
    int b = z & 3, which = z >> 2;
    int c0 = blockIdx.x << 5;
    int p0 = blockIdx.y << 5;
    const float* src = (which ? feat : x) + (size_t)b * Cd * HWd;
    int tx = threadIdx.x, ty = threadIdx.y;
#pragma unroll
    for (int i = ty; i < 32; i += 8)
        t[i][tx] = src[(size_t)(c0 + i) * HWd + p0 + tx];
    __syncthreads();
    int h  = p0 >> 8;
    int h2 = (h - 4) & 255;
    int whp = ((h2 >> 3) << 5);
    int nh8 = (h2 & 7) << 3;
    __half* dh = (which ? g_fth : g_xth) + (size_t)b * HWd * Cd;
    float*  df = g_xt + (size_t)b * HWd * Cd;
#pragma unroll
    for (int i = ty; i < 32; i += 8) {
        int wv = ((p0 & 255) + i);
        int w2 = (wv - 4) & 255;
        int tok = ((whp + (w2 >> 3)) << 6) + nh8 + (w2 & 7);
        float v = t[tx][i];
        dh[(size_t)tok * Cd + c0 + tx] = __float2half_rn(v);
        if (!which) df[(size_t)(p0 + i) * Cd + c0 + tx] = v;
    }
}

// ======================= K1: QKV GEMM =======================
__global__ void __launch_bounds__(256, 2) k_qkv(
    const float* __restrict__ q_b, const float* __restrict__ kv_b)
{
    extern __shared__ float sm[];
    __half* smh = (__half*)sm;
    int tid = threadIdx.x;
    int which = blockIdx.x;
    int win = blockIdx.y;
    const __half* src = (which == 0) ? g_xth : g_fth;
    const __half* W   = (which == 0) ? w_qh : (which == 1 ? w_kvh : (w_kvh + 192 * 192));
    const int r0 = tid >> 3, c4 = 4 * (tid & 7);
    const __half* aP[2]; const __half* bP[6];
#pragma unroll
    for (int i = 0; i < 2; i++) aP[i] = src + ((size_t)win * 64 + r0 + 32 * i) * 192 + c4;
#pragma unroll
    for (int i = 0; i < 6; i++) bP[i] = W + (size_t)(r0 + 32 * i) * 192 + c4;

    float acc[2][6][4];
#pragma unroll
    for (int a = 0; a < 2; a++)
#pragma unroll
        for (int b2 = 0; b2 < 6; b2++)
#pragma unroll
            for (int cc = 0; cc < 4; cc++) acc[a][b2][cc] = 0.f;
    gemm_core_h2<64, 192, 6>(aP, bP, smh, acc, tid);

    float* St = sm;
    frag_store<64, 200>(St, acc, tid);
    __syncthreads();

    if (which < 2) {
        __half* dst = (which == 0) ? g_qh : g_kh;
        const float* bias = (which == 0) ? q_b : kv_b;
        float bs = (which == 0) ? QSCALE : 1.f;   // Q weights pre-scaled; scale bias here
#pragma unroll 1
        for (int p = tid; p < 64 * 48; p += 256) {
            int m = p / 48, j4 = 4 * (p - (p / 48) * 48);
            __half hv[4];
#pragma unroll
            for (int e = 0; e < 4; e++)
                hv[e] = __float2half_rn(St[m * 200 + j4 + e] + bias[j4 + e] * bs);
            size_t didx = (((size_t)win * NHd + (j4 >> 5)) * 64 + m) * HDd + (j4 & 31);
            *reinterpret_cast<uint2*>(dst + didx) = *reinterpret_cast<uint2*>(hv);
        }
    } else {
#pragma unroll 1
        for (int p = tid; p < 1536; p += 256) {
            int h = p >> 8, d = (p >> 3) & 31, ng = p & 7;
            int j = h * 32 + d;
            float bv = kv_b[192 + j];
            __half hv[8];
#pragma unroll
            for (int r = 0; r < 8; r++)
                hv[r] = __float2half_rn(St[(ng * 8 + r) * 200 + j] + bv);
            size_t didx = (((size_t)win * NHd + h) * HDd + d) * 64 + ng * 8;
            *reinterpret_cast<uint4*>(g_vh + didx) = *reinterpret_cast<uint4*>(hv);
        }
    }
}

// ======================= K2: attention + proj·merge GEMM + LN + shortcut ========
// smem (halves): Kh [0,15360) | Vt [15360,29184) | smA [29184,44544)
//   after attention: smB (2x7680) overlays Kh; St (25600 h as float) overlays Kh+Vt.
__global__ void __launch_bounds__(256, 2) k_attn(
    const float* __restrict__ n1g, const float* __restrict__ n1b)
{
    extern __shared__ float smf[];
    __half* Kh  = (__half*)smf;
    __half* Vt  = Kh + 15360;
    __half* smA = Kh + 29184;
    __half* smB = Kh;
    float*  St  = smf;
    int win = blockIdx.x;
    int tid = threadIdx.x;
    int lane = tid & 31, w = tid >> 5;
    int g = lane >> 2, tg = lane & 3;
    int mi = w & 3, hp = w >> 2;

    size_t qkbase = (size_t)win * NHd * 64 * HDd;
    size_t vbase  = (size_t)win * NHd * HDd * 64;
#pragma unroll 1
    for (int p = tid; p < 1536; p += 256) {
        int h = p >> 8, rem = p & 255;
        int n = rem >> 2, u = rem & 3;
        uint4 v = *reinterpret_cast<const uint4*>(g_kh + qkbase + (h * 64 + n) * 32 + 8 * u);
        *reinterpret_cast<uint4*>(Kh + h * 2560 + n * 40 + 8 * u) = v;
    }
#pragma unroll 1
    for (int p = tid; p < 1536; p += 256) {
        int h = p >> 8, rem = p & 255;
        int d = rem >> 3, u = rem & 7;
        uint4 v = *reinterpret_cast<const uint4*>(g_vh + vbase + (h * 32 + d) * 64 + 8 * u);
        *reinterpret_cast<uint4*>(Vt + h * 2304 + d * 72 + 8 * u) = v;
    }
    __syncthreads();

    int i0 = 16 * mi + g;
    int w10 = win & 1023;
    bool eh = ((w10 >> 5) == 31), ew = ((w10 & 31) == 31);
    bool edge = eh || ew;
    int ri0 = 0, ri1 = 0, rj0a[8], rj1a[8];
    if (edge) {
        auto region = [&](int n) {
            int a = eh ? (((n >> 3) >= 4) ? 2 : 1) : 0;
            int b = ew ? (((n & 7)  >= 4) ? 2 : 1) : 0;
            return a * 3 + b;
        };
        ri0 = region(i0); ri1 = region(i0 + 8);
#pragma unroll
        for (int ni = 0; ni < 8; ni++) {
            int j0 = 8 * ni + 2 * tg;
            rj0a[ni] = region(j0);
            rj1a[ni] = region(j0 + 1);
        }
    }

#pragma unroll 1
    for (int t = 0; t < 3; t++) {
        int h = 2 * t + hp;
        const __half* Qg = g_qh + qkbase + (size_t)h * 2048 + i0 * 32 + 2 * tg;
        unsigned aq[2][4];
#pragma unroll
        for (int ks = 0; ks < 2; ks++) {
            aq[ks][0] = ldu(Qg + 16 * ks);
            aq[ks][1] = ldu(Qg + 16 * ks + 256);
            aq[ks][2] = ldu(Qg + 16 * ks + 8);
            aq[ks][3] = ldu(Qg + 16 * ks + 264);
        }
        float s[8][4];
#pragma unroll
        for (int ni = 0; ni < 8; ni++)
#pragma unroll
            for (int e = 0; e < 4; e++) s[ni][e] = 0.f;
        const __half* Kb = Kh + h * 2560 + g * 40 + 2 * tg;
#pragma unroll
        for (int ni = 0; ni < 8; ni++) {
            mma16(s[ni], aq[0], ldu(Kb + ni * 320),      ldu(Kb + ni * 320 + 8));
            mma16(s[ni], aq[1], ldu(Kb + ni * 320 + 16), ldu(Kb + ni * 320 + 24));
        }
        const __half* bb0 = g_biash + (h * 64 + i0) * 64;
#pragma unroll
        for (int ni = 0; ni < 8; ni++) {
            int j0 = 8 * ni + 2 * tg;
            float2 f0 = __half22float2(*(const __half2*)(bb0 + j0));
            float2 f1 = __half22float2(*(const __half2*)(bb0 + 512 + j0));
            s[ni][0] += f0.x; s[ni][1] += f0.y;
            s[ni][2] += f1.x; s[ni][3] += f1.y;
        }
        if (edge) {
#pragma unroll
            for (int ni = 0; ni < 8; ni++) {
                if (rj0a[ni] != ri0) s[ni][0] -= 100.f;
                if (rj1a[ni] != ri0) s[ni][1] -= 100.f;
                if (rj0a[ni] != ri1) s[ni][2] -= 100.f;
                if (rj1a[ni] != ri1) s[ni][3] -= 100.f;
            }
        }
        float m0 = -1e30f, m1 = -1e30f;
#pragma unroll
        for (int ni = 0; ni < 8; ni++) {
            m0 = fmaxf(m0, fmaxf(s[ni][0], s[ni][1]));
            m1 = fmaxf(m1, fmaxf(s[ni][2], s[ni][3]));
        }
        m0 = fmaxf(m0, __shfl_xor_sync(0xffffffffu, m0, 1));
        m0 = fmaxf(m0, __shfl_xor_sync(0xffffffffu, m0, 2));
        m1 = fmaxf(m1, __shfl_xor_sync(0xffffffffu, m1, 1));
        m1 = fmaxf(m1, __shfl_xor_sync(0xffffffffu, m1, 2));
        float s0 = 0.f, s1 = 0.f;
#pragma unroll
        for (int ni = 0; ni < 8; ni++) {
            s[ni][0] = __expf(s[ni][0] - m0); s0 += s[ni][0];
            s[ni][1] = __expf(s[ni][1] - m0); s0 += s[ni][1];
            s[ni][2] = __expf(s[ni][2] - m1); s1 += s[ni][2];
            s[ni][3] = __expf(s[ni][3] - m1); s1 += s[ni][3];
        }
        s0 += __shfl_xor_sync(0xffffffffu, s0, 1);
        s0 += __shfl_xor_sync(0xffffffffu, s0, 2);
        s1 += __shfl_xor_sync(0xffffffffu, s1, 1);
        s1 += __shfl_xor_sync(0xffffffffu, s1, 2);
        float inv0 = 1.f / s0, inv1 = 1.f / s1;
        unsigned pv[4][4];
#pragma unroll
        for (int js = 0; js < 4; js++) {
            pv[js][0] = h2u(__floats2half2_rn(s[2*js][0]   * inv0, s[2*js][1]   * inv0));
            pv[js][1] = h2u(__floats2half2_rn(s[2*js][2]   * inv1, s[2*js][3]   * inv1));
            pv[js][2] = h2u(__floats2half2_rn(s[2*js+1][0] * inv0, s[2*js+1][1] * inv0));
            pv[js][3] = h2u(__floats2half2_rn(s[2*js+1][2] * inv1, s[2*js+1][3] * inv1));
        }
        float o[4][4];
#pragma unroll
        for (int nd = 0; nd < 4; nd++)
#pragma unroll
            for (int e = 0; e < 4; e++) o[nd][e] = 0.f;
        const __half* Vb = Vt + h * 2304 + g * 72 + 2 * tg;
#pragma unroll
        for (int nd = 0; nd < 4; nd++)
#pragma unroll
            for (int js = 0; js < 4; js++)
                mma16(o[nd], pv[js], ldu(Vb + nd * 576 + 16 * js),
                                     ldu(Vb + nd * 576 + 16 * js + 8));
        // store to smA in GEMM A-layout: chunk = head, rows i0/i0+8, k = d
#pragma unroll
        for (int nd = 0; nd < 4; nd++) {
            int d0 = 8 * nd + 2 * tg;
            *(__half2*)(smA + h * 2560 + i0 * 40 + d0) =
                __floats2half2_rn(o[nd][0], o[nd][1]);
            *(__half2*)(smA + h * 2560 + (i0 + 8) * 40 + d0) =
                __floats2half2_rn(o[nd][2], o[nd][3]);
        }
    }

    // ---------- fused proj+merge GEMM: out64x192 = smA @ Wc^T ----------
    const int r0 = tid >> 3, c4 = 4 * (tid & 7);
    const int stsO = r0 * 40 + c4;
    const int wr = (w & 1) * 32, wc = (w >> 1) * 48;
    uint2 rb[6];
#pragma unroll
    for (int i = 0; i < 6; i++)
        rb[i] = *(const uint2*)(w_ch + (size_t)(r0 + 32 * i) * 192 + c4);
    __syncthreads();    // all attention reads of Kh/Vt done; smA complete
#pragma unroll
    for (int i = 0; i < 6; i++)
        *(uint2*)(smB + stsO + 1280 * i) = rb[i];
    __syncthreads();

    float acc[2][6][4];
#pragma unroll
    for (int a = 0; a < 2; a++)
#pragma unroll
        for (int b_ = 0; b_ < 6; b_++)
#pragma unroll
            for (int cc = 0; cc < 4; cc++) acc[a][b_][cc] = 0.f;

#pragma unroll 1
    for (int kc = 0; kc < 6; kc++) {
        if (kc + 1 < 6)
#pragma unroll
            for (int i = 0; i < 6; i++)
                rb[i] = *(const uint2*)(w_ch + (size_t)(r0 + 32 * i) * 192 + (kc + 1) * 32 + c4);
        const __half* Ab = smA + kc * 2560;
        const __half* Bb = smB + (kc & 1) * 7680;
#pragma unroll
        for (int kk = 0; kk < 32; kk += 16) {
            unsigned af[2][4], bf[6][2];
#pragma unroll
            for (int mi2 = 0; mi2 < 2; mi2++) {
                const __half* Ar = Ab + (wr + 16 * mi2 + g) * 40 + kk + 2 * tg;
                af[mi2][0] = ldu(Ar);       af[mi2][1] = ldu(Ar + 320);
                af[mi2][2] = ldu(Ar + 8);   af[mi2][3] = ldu(Ar + 328);
            }
#pragma unroll
            for (int ni = 0; ni < 6; ni++) {
                const __half* Br = Bb + (wc + 8 * ni + g) * 40 + kk + 2 * tg;
                bf[ni][0] = ldu(Br);  bf[ni][1] = ldu(Br + 8);
            }
#pragma unroll
            for (int mi2 = 0; mi2 < 2; mi2++)
#pragma unroll
                for (int ni = 0; ni < 6; ni++)
                    mma16(acc[mi2][ni], af[mi2], bf[ni][0], bf[ni][1]);
        }
        if (kc + 1 < 6)
#pragma unroll
            for (int i = 0; i < 6; i++)
                *(uint2*)(smB + ((kc + 1) & 1) * 7680 + stsO + 1280 * i) = rb[i];
        __syncthreads();
    }

    // ---------- epilogue: combined bias + LN(norm1) + shortcut + scatter ----------
    frag_store<64, 200>(St, acc, tid);
    __syncthreads();
    int wp = tid >> 5, l = tid & 31;
    int b = win >> 10, wh = (win >> 5) & 31, ww = win & 31;
#pragma unroll 1
    for (int rr = 0; rr < 8; rr++) {
        int n = wp * 8 + rr;
        int hpx = (wh * 8 + (n >> 3) + 4) & 255;
        int wpx = (ww * 8 + (n & 7) + 4) & 255;
        size_t row = ((size_t)b * HWd + hpx * Wdim + wpx) * Cd;
        float vv[6]; float su = 0.f;
#pragma unroll
        for (int u = 0; u < 6; u++) {
            int c = l + 32 * u;
            vv[u] = St[n * 200 + c] + g_bc[c];
            su += vv[u];
        }
        su = warp_sum(su);
        float mean = su * (1.f / 192.f);
        float sq = 0.f;
#pragma unroll
        for (int u = 0; u < 6; u++) { float d = vv[u] - mean; sq += d * d; }
        sq = warp_sum(sq);
        float rstd = rsqrtf(sq * (1.f / 192.f) + 1e-5f);
#pragma unroll
        for (int u = 0; u < 6; u++) {
            int c = l + 32 * u;
            float y = (vv[u] - mean) * rstd * n1g[c] + n1b[c] + g_xt[row + c];
            g_x1[row + c]  = y;
            g_x1h[row + c] = __float2half_rn(y);
        }
    }
}

// ======================= K5: fused MLP =======================
__global__ void __launch_bounds__(256, 2) k_mlp(
    const float* __restrict__ b1h, const float* __restrict__ b2,
    const float* __restrict__ g2, const float* __restrict__ bb2,
    float* __restrict__ out)
{
    extern __shared__ float sm[];
    __half* smA  = (__half*)sm;
    __half* smB1 = smA + 15360;
    __half* smH  = smB1 + 7680;
    __half* smB2 = smH + 7680;
    int tid = threadIdx.x;
    size_t mbase = (size_t)blockIdx.x * 64;
    const int lane = tid & 31, w = tid >> 5;
    const int g = lane >> 2, tg = lane & 3;
    const int wr  = (w & 1) * 32;
    const int wc1 = (w >> 1) * 24;
    const int wc2 = (w >> 1) * 48;
    const int r0 = tid >> 3, c4 = 4 * (tid & 7);
    const int stsO = r0 * 40 + c4;

    const __half* aSrc = g_x1h + mbase * 192;
#pragma unroll
    for (int c = 0; c < 6; c++)
#pragma unroll
        for (int i = 0; i < 2; i++) {
            uint2 v = *(const uint2*)(aSrc + (size_t)(r0 + 32 * i) * 192 + c * 32 + c4);
            *(uint2*)(smA + c * 2560 + stsO + 1280 * i) = v;
        }

    float acc2[2][6][4];
#pragma unroll
    for (int a = 0; a < 2; a++)
#pragma unroll
        for (int b_ = 0; b_ < 6; b_++)
#pragma unroll
            for (int cc = 0; cc < 4; cc++) acc2[a][b_][cc] = 0.f;

#pragma unroll 1
    for (int oc = 0; oc < 8; oc++) {
        const __half* W1 = w_f1h + (size_t)(oc * 96) * 192;
        uint2 rb1[3];
#pragma unroll
        for (int i = 0; i < 3; i++)
            rb1[i] = *(const uint2*)(W1 + (size_t)(r0 + 32 * i) * 192 + c4);
#pragma unroll
        for (int i = 0; i < 3; i++)
            *(uint2*)(smB1 + stsO + 1280 * i) = rb1[i];
        __syncthreads();

        float acc1[2][3][4];
#pragma unroll
        for (int a = 0; a < 2; a++)
#pragma unroll
            for (int b_ = 0; b_ < 3; b_++)
#pragma unroll
                for (int cc = 0; cc < 4; cc++) acc1[a][b_][cc] = 0.f;

#pragma unroll 1
        for (int kc = 0; kc < 6; kc++) {
            if (kc + 1 < 6)
#pragma unroll
                for (int i = 0; i < 3; i++)
                    rb1[i] = *(const uint2*)(W1 + (size_t)(r0 + 32 * i) * 192 + (kc + 1) * 32 + c4);
            const __half* Ab = smA + kc * 2560;
            const __half* Bb = smB1 + (kc & 1) * 3840;
#pragma unroll
            for (int kk = 0; kk < 32; kk += 16) {
                unsigned af[2][4], bf[3][2];
#pragma unroll
                for (int mi = 0; mi < 2; mi++) {
                    const __half* Ar = Ab + (wr + 16 * mi + g) * 40 + kk + 2 * tg;
                    af[mi][0] = ldu(Ar);       af[mi][1] = ldu(Ar + 320);
                    af[mi][2] = ldu(Ar + 8);   af[mi][3] = ldu(Ar + 328);
                }
#pragma unroll
                for (int ni = 0; ni < 3; ni++) {
                    const __half* Br = Bb + (wc1 + 8 * ni + g) * 40 + kk + 2 * tg;
                    bf[ni][0] = ldu(Br);  bf[ni][1] = ldu(Br + 8);
                }
#pragma unroll
                for (int mi = 0; mi < 2; mi++)
#pragma unroll
                    for (int ni = 0; ni < 3; ni++)
                        mma16(acc1[mi][ni], af[mi], bf[ni][0], bf[ni][1]);
            }
            if (kc + 1 < 6)
#pragma unroll
                for (int i = 0; i < 3; i++)
                    *(uint2*)(smB1 + ((kc + 1) & 1) * 3840 + stsO + 1280 * i) = rb1[i];
            __syncthreads();
        }

#pragma unroll
        for (int mi = 0; mi < 2; mi++)
#pragma unroll
            for (int ni = 0; ni < 3; ni++) {
                int row = wr + 16 * mi + g;
                int col = wc1 + 8 * ni + 2 * tg;
                float2 bv = *(const float2*)(b1h + oc * 96 + col);
                __half* hp0 = smH + (col >> 5) * 2560 + row * 40 + (col & 31);
                *(__half2*)hp0 = __floats2half2_rn(
                    gelu_f(acc1[mi][ni][0] + bv.x), gelu_f(acc1[mi][ni][1] + bv.y));
                *(__half2*)(hp0 + 320) = __floats2half2_rn(
                    gelu_f(acc1[mi][ni][2] + bv.x), gelu_f(acc1[mi][ni][3] + bv.y));
            }

        const __half* W2 = w_f2h;
        uint2 rb2[6];
#pragma unroll
        for (int i = 0; i < 6; i++)
            rb2[i] = *(const uint2*)(W2 + (size_t)(r0 + 32 * i) * 768 + oc * 96 + c4);
#pragma unroll
        for (int i = 0; i < 6; i++)
            *(uint2*)(smB2 + stsO + 1280 * i) = rb2[i];
        __syncthreads();

#pragma unroll 1
        for (int kc = 0; kc < 3; kc++) {
            if (kc + 1 < 3)
#pragma unroll
                for (int i = 0; i < 6; i++)
                    rb2[i] = *(const uint2*)(W2 + (size_t)(r0 + 32 * i) * 768 + oc * 96 + (kc + 1) * 32 + c4);
            const __half* Ab = smH + kc * 2560;
            const __half* Bb = smB2 + (kc & 1) * 7680;
#pragma unroll
            for (int kk = 0; kk < 32; kk += 16) {
                unsigned af[2][4], bf[6][2];
#pragma unroll
                for (int mi = 0; mi < 2; mi++) {
                    const __half* Ar = Ab + (wr + 16 * mi + g) * 40 + kk + 2 * tg;
                    af[mi][0] = ldu(Ar);       af[mi][1] = ldu(Ar + 320);
                    af[mi][2] = ldu(Ar + 8);   af[mi][3] = ldu(Ar + 328);
                }
#pragma unroll
                for (int ni = 0; ni < 6; ni++) {
                    const __half* Br = Bb + (wc2 + 8 * ni + g) * 40 + kk + 2 * tg;
                    bf[ni][0] = ldu(Br);  bf[ni][1] = ldu(Br + 8);
                }
#pragma unroll
                for (int mi = 0; mi < 2; mi++)
#pragma unroll
                    for (int ni = 0; ni < 6; ni++)
                        mma16(acc2[mi][ni], af[mi], bf[ni][0], bf[ni][1]);
            }
            if (kc + 1 < 3)
#pragma unroll
                for (int i = 0; i < 6; i++)
                    *(uint2*)(smB2 + ((kc + 1) & 1) * 7680 + stsO + 1280 * i) = rb2[i];
            __syncthreads();
        }
    }

    float* St = sm;
    frag_store<64, 200>(St, acc2, tid);
    __syncthreads();
    int wp = tid >> 5, l = tid & 31;
#pragma unroll 1
    for (int rr = 0; rr < 8; rr++) {
        int r = wp * 8 + rr;
        float vv[6]; float su = 0.f;
#pragma unroll
        for (int u = 0; u < 6; u++) {
            int c = l + 32 * u;
            vv[u] = St[r * 200 + c] + b2[c];
            su += vv[u];
        }
        su = warp_sum(su);
        float mean = su * (1.f / 192.f);
        float sq = 0.f;
#pragma unroll
        for (int u = 0; u < 6; u++) { float d = vv[u] - mean; sq += d * d; }
        sq = warp_sum(sq);
        float rstd = rsqrtf(sq * (1.f / 192.f) + 1e-5f);
        size_t row = (mbase + r) * Cd;
#pragma unroll
        for (int u = 0; u < 6; u++) {
            int c = l + 32 * u;
            out[row + c] = g_x1[row + c] + (vv[u] - mean) * rstd * g2[c] + bb2[c];
        }
    }
}

// ======================= host =======================
extern "C" void kernel_launch(void* const* d_in, const int* in_sizes, int n_in,
                              void* d_out, int out_size)
{
    const float* x    = (const float*)d_in[0];
    const float* feat = (const float*)d_in[1];
    const int*   ridx = (const int*)  d_in[3];
    const float* rtab = (const float*)d_in[4];
    const float* q_w  = (const float*)d_in[5];
    const float* q_b  = (const float*)d_in[6];
    const float* kv_w = (const float*)d_in[7];
    const float* kv_b = (const float*)d_in[8];
    const float* p_w  = (const float*)d_in[9];
    const float* p_b  = (const float*)d_in[10];
    const float* m_w  = (const float*)d_in[11];
    const float* n1g  = (const float*)d_in[12];
    const float* n1b  = (const float*)d_in[13];
    const float* n2g  = (const float*)d_in[14];
    const float* n2b  = (const float*)d_in[15];
    const float* f1w  = (const float*)d_in[16];
    const float* f1b  = (const float*)d_in[17];
    const float* f2w  = (const float*)d_in[18];
    const float* f2b  = (const float*)d_in[19];
    float* out = (float*)d_out;

    __half *dwq, *dwkv, *dwf1, *dwf2;
    cudaGetSymbolAddress((void**)&dwq,  w_qh);
    cudaGetSymbolAddress((void**)&dwkv, w_kvh);
    cudaGetSymbolAddress((void**)&dwf1, w_f1h);
    cudaGetSymbolAddress((void**)&dwf2, w_f2h);

    const int smWide = 64 * 200 * (int)sizeof(float);    // 51200
    const int smAttn = 44544 * 2;                        // 89088
    const int smMlp  = 46080 * 2;                        // 92160
    cudaFuncSetAttribute(k_qkv,  cudaFuncAttributeMaxDynamicSharedMemorySize, smWide);
    cudaFuncSetAttribute(k_attn, cudaFuncAttributeMaxDynamicSharedMemorySize, smAttn);
    cudaFuncSetAttribute(k_mlp,  cudaFuncAttributeMaxDynamicSharedMemorySize, smMlp);

    k_f2h_s<<<144, 256>>>(q_w,  dwq,  36864, QSCALE);
    k_f2h  <<<288, 256>>>(kv_w, dwkv, 73728);
    k_wcomb<<<144, 256>>>(m_w, p_w, p_b);
    k_f2h  <<<576, 256>>>(f1w,  dwf1, 147456);
    k_f2h  <<<576, 256>>>(f2w,  dwf2, 147456);
    k_bias <<<96, 256>>>(ridx, rtab);
    k_transpose<<<dim3(6, 2048, 8), dim3(32, 8)>>>(x, feat);
    k_qkv  <<<dim3(3, 4096), 256, smWide>>>(q_b, kv_b);
    k_attn <<<NWINd, 256, smAttn>>>(n1g, n1b);
    k_mlp  <<<4096, 256, smMlp>>>(f1b, f2b, n2g, n2b, out);
}

// round 7
// speedup vs baseline: 7.1750x; 1.1376x over previous
#include <cuda_runtime.h>
#include <cuda_fp16.h>
#include <math.h>
#include <stdint.h>

#define Hd    256
#define Wdim  256
#define HWd   65536
#define Cd    192
#define Bd    4
#define NHd   6
#define HDd   32
#define NWINd 4096
#define MTOKd 262144
#define HIDd  768
#define QSCALE 0.17677669529663687f

// -------- scratch --------
__device__ float  g_xt  [(size_t)MTOKd * Cd];           // fp32 pixel-order (shortcut)
__device__ __half g_xth [(size_t)MTOKd * Cd];           // fp16 WINDOW-order
__device__ __half g_fth [(size_t)MTOKd * Cd];           // fp16 WINDOW-order
__device__ __half g_biash[NHd * 64 * 64];
__device__ float  g_x1  [(size_t)MTOKd * Cd];
__device__ __half g_x1h [(size_t)MTOKd * Cd];
__device__ __half w_qh [36864];
__device__ __half w_kvh[73728];
__device__ __half w_ch [36864];     // combined merge@proj weight
__device__ float  g_bc [192];       // combined bias m_w @ p_b
__device__ __half w_f1h[147456];
__device__ __half w_f2h[147456];

__device__ __forceinline__ float warp_sum(float v) {
#pragma unroll
    for (int o = 16; o; o >>= 1) v += __shfl_xor_sync(0xffffffffu, v, o);
    return v;
}
__device__ __forceinline__ unsigned h2u(__half2 h) {
    return *reinterpret_cast<unsigned*>(&h);
}
__device__ __forceinline__ unsigned ldu(const __half* p) {
    return *reinterpret_cast<const unsigned*>(p);
}
__device__ __forceinline__ float gelu_f(float v) {
    return 0.5f * v * (1.f + erff(v * 0.70710678118654752f));
}
__device__ __forceinline__ void mma16(float* c, const unsigned* a, unsigned b0, unsigned b1) {
    asm volatile(
        "mma.sync.aligned.m16n8k16.row.col.f32.f16.f16.f32 "
        "{%0,%1,%2,%3}, {%4,%5,%6,%7}, {%8,%9}, {%0,%1,%2,%3};"
        : "+f"(c[0]), "+f"(c[1]), "+f"(c[2]), "+f"(c[3])
        : "r"(a[0]), "r"(a[1]), "r"(a[2]), "r"(a[3]), "r"(b0), "r"(b1));
}

// ======================= prep kernels =======================
__global__ void k_f2h(const float* __restrict__ src, __half* __restrict__ dst, int n) {
    int i = blockIdx.x * 256 + threadIdx.x;
    if (i < n) dst[i] = __float2half_rn(src[i]);
}
__global__ void k_f2h_s(const float* __restrict__ src, __half* __restrict__ dst,
                        int n, float s) {
    int i = blockIdx.x * 256 + threadIdx.x;
    if (i < n) dst[i] = __float2half_rn(src[i] * s);
}
__global__ void k_bias(const int* __restrict__ relidx, const float* __restrict__ table) {
    int idx = blockIdx.x * 256 + threadIdx.x;
    if (idx < NHd * 4096) {
        int h = idx >> 12, r = idx & 4095;
        g_biash[idx] = __float2half_rn(table[relidx[r] * NHd + h]);
    }
}
__global__ void k_wcomb(const float* __restrict__ mw, const float* __restrict__ pw,
                        const float* __restrict__ pb) {
    int e = blockIdx.x * 256 + threadIdx.x;
    if (e < 36864) {
        int i = e / 192, j = e - (e / 192) * 192;
        float acc = 0.f;
        for (int k = 0; k < 192; k++) acc += mw[i * 192 + k] * pw[k * 192 + j];
        w_ch[e] = __float2half_rn(acc);
    }
    if (e < 192) {
        float acc = 0.f;
        for (int k = 0; k < 192; k++) acc += mw[e * 192 + k] * pb[k];
        g_bc[e] = acc;
    }
}

// ======================= K0: transpose; fp16 copies in WINDOW order =======================
__global__ void k_transpose(const float* __restrict__ x, const float* __restrict__ feat) {
    __shared__ float t[32][33];
    int z = blockIdx.z;
    int b = z & 3, which = z >> 2;
    int c0 = blockIdx.x << 5;
    int p0 = blockIdx.y << 5;
    const float* src = (which ? feat : x) + (size_t)b * Cd * HWd;
    int tx = threadIdx.x, ty = threadIdx.y;
#pragma unroll
    for (int i = ty; i < 32; i += 8)
        t[i][tx] = src[(size_t)(c0 + i) * HWd + p0 + tx];
    __syncthreads();
    int h  = p0 >> 8;
    int h2 = (h - 4) & 255;
    int whp = ((h2 >> 3) << 5);
    int nh8 = (h2 & 7) << 3;
    __half* dh = (which ? g_fth : g_xth) + (size_t)b * HWd * Cd;
    float*  df = g_xt + (size_t)b * HWd * Cd;
#pragma unroll
    for (int i = ty; i < 32; i += 8) {
        int wv = ((p0 & 255) + i);
        int w2 = (wv - 4) & 255;
        int tok = ((whp + (w2 >> 3)) << 6) + nh8 + (w2 & 7);
        float v = t[tx][i];
        dh[(size_t)tok * Cd + c0 + tx] = __float2half_rn(v);
        if (!which) df[(size_t)(p0 + i) * Cd + c0 + tx] = v;
    }
}

// ======================= K2: QKV + attention + proj·merge + LN (mega kernel) ========
// smem halves: smA [0,15360) | Kh [15360,30720) | Vt [30720,44544) | smB [44544,52224)
// post-attn: attn-out overlays smA; Wc B-dbuf overlays Kh; St fp32 overlays [15360,40960).
__global__ void __launch_bounds__(256, 2) k_attn(
    const float* __restrict__ q_b, const float* __restrict__ kv_b,
    const float* __restrict__ n1g, const float* __restrict__ n1b)
{
    extern __shared__ float smf[];
    __half* smA = (__half*)smf;
    __half* Kh  = smA + 15360;
    __half* Vt  = smA + 30720;
    __half* smB = smA + 44544;
    __half* smB2 = Kh;                 // Wc GEMM double buffer (2x7680)
    float*  St  = smf + 7680;          // fp32 stage [halves 15360,40960)
    int win = blockIdx.x;
    int tid = threadIdx.x;
    int lane = tid & 31, w = tid >> 5;
    int g = lane >> 2, tg = lane & 3;
    int mi = w & 3, hp = w >> 2;
    const int r0 = tid >> 3, c4 = 4 * (tid & 7);
    const int stsO = r0 * 40 + c4;
    const int wr = (w & 1) * 32, wc = (w >> 1) * 48;

    // ---------- load xw; stage Wq chunk 0 ----------
    const __half* xsrc = g_xth + (size_t)win * 64 * 192;
#pragma unroll
    for (int c = 0; c < 6; c++)
#pragma unroll
        for (int i = 0; i < 2; i++) {
            uint2 v = *(const uint2*)(xsrc + (size_t)(r0 + 32 * i) * 192 + c * 32 + c4);
            *(uint2*)(smA + c * 2560 + stsO + 1280 * i) = v;
        }
    uint2 rb[6];
#pragma unroll
    for (int i = 0; i < 6; i++)
        rb[i] = *(const uint2*)(w_qh + (size_t)(r0 + 32 * i) * 192 + c4);
#pragma unroll
    for (int i = 0; i < 6; i++) *(uint2*)(smB + stsO + 1280 * i) = rb[i];
    __syncthreads();

    // ---------- Q GEMM: rows 16mi..+16, heads {hp,2+hp,4+hp} ----------
    float qacc[3][4][4];
#pragma unroll
    for (int t = 0; t < 3; t++)
#pragma unroll
        for (int nq = 0; nq < 4; nq++)
#pragma unroll
            for (int e = 0; e < 4; e++) qacc[t][nq][e] = 0.f;
#pragma unroll 1
    for (int kc = 0; kc < 6; kc++) {
        if (kc + 1 < 6)
#pragma unroll
            for (int i = 0; i < 6; i++)
                rb[i] = *(const uint2*)(w_qh + (size_t)(r0 + 32 * i) * 192 + (kc + 1) * 32 + c4);
#pragma unroll
        for (int kk = 0; kk < 32; kk += 16) {
            unsigned af[4];
            const __half* Ar = smA + kc * 2560 + (16 * mi + g) * 40 + kk + 2 * tg;
            af[0] = ldu(Ar);      af[1] = ldu(Ar + 320);
            af[2] = ldu(Ar + 8);  af[3] = ldu(Ar + 328);
#pragma unroll
            for (int t = 0; t < 3; t++)
#pragma unroll
                for (int nq = 0; nq < 4; nq++) {
                    const __half* Br = smB + (32 * (2 * t + hp) + 8 * nq + g) * 40 + kk + 2 * tg;
                    mma16(qacc[t][nq], af, ldu(Br), ldu(Br + 8));
                }
        }
        __syncthreads();
        if (kc + 1 < 6) {
#pragma unroll
            for (int i = 0; i < 6; i++)
                *(uint2*)(smB + stsO + 1280 * i) = rb[i];
            __syncthreads();
        }
    }

    // ---------- repack Q: C-frag -> A-frag, + scaled bias ----------
    unsigned aq[3][2][4];
#pragma unroll
    for (int t = 0; t < 3; t++) {
        int h = 2 * t + hp;
#pragma unroll
        for (int ks = 0; ks < 2; ks++) {
            float2 b0 = *(const float2*)(q_b + 32 * h + 16 * ks + 2 * tg);
            float2 b1 = *(const float2*)(q_b + 32 * h + 16 * ks + 8 + 2 * tg);
            b0.x *= QSCALE; b0.y *= QSCALE; b1.x *= QSCALE; b1.y *= QSCALE;
            aq[t][ks][0] = h2u(__floats2half2_rn(qacc[t][2*ks][0] + b0.x, qacc[t][2*ks][1] + b0.y));
            aq[t][ks][1] = h2u(__floats2half2_rn(qacc[t][2*ks][2] + b0.x, qacc[t][2*ks][3] + b0.y));
            aq[t][ks][2] = h2u(__floats2half2_rn(qacc[t][2*ks+1][0] + b1.x, qacc[t][2*ks+1][1] + b1.y));
            aq[t][ks][3] = h2u(__floats2half2_rn(qacc[t][2*ks+1][2] + b1.x, qacc[t][2*ks+1][3] + b1.y));
        }
    }

    // ---------- load fw (overwrite smA); stage Wk chunk 0 ----------
    const __half* fsrc = g_fth + (size_t)win * 64 * 192;
#pragma unroll
    for (int c = 0; c < 6; c++)
#pragma unroll
        for (int i = 0; i < 2; i++) {
            uint2 v = *(const uint2*)(fsrc + (size_t)(r0 + 32 * i) * 192 + c * 32 + c4);
            *(uint2*)(smA + c * 2560 + stsO + 1280 * i) = v;
        }
#pragma unroll
    for (int i = 0; i < 6; i++)
        rb[i] = *(const uint2*)(w_kvh + (size_t)(r0 + 32 * i) * 192 + c4);
#pragma unroll
    for (int i = 0; i < 6; i++) *(uint2*)(smB + stsO + 1280 * i) = rb[i];
    __syncthreads();

    // ---------- K GEMM (64x192) -> Kh, then V GEMM -> Vt ----------
#pragma unroll 1
    for (int kv = 0; kv < 2; kv++) {
        const __half* W = w_kvh + (size_t)kv * 36864;
        float acc[2][6][4];
#pragma unroll
        for (int a = 0; a < 2; a++)
#pragma unroll
            for (int b_ = 0; b_ < 6; b_++)
#pragma unroll
                for (int e = 0; e < 4; e++) acc[a][b_][e] = 0.f;
#pragma unroll 1
        for (int kc = 0; kc < 6; kc++) {
            // prefetch next chunk (next kc, or chunk 0 of V weights)
            if (kc + 1 < 6) {
#pragma unroll
                for (int i = 0; i < 6; i++)
                    rb[i] = *(const uint2*)(W + (size_t)(r0 + 32 * i) * 192 + (kc + 1) * 32 + c4);
            } else if (kv == 0) {
#pragma unroll
                for (int i = 0; i < 6; i++)
                    rb[i] = *(const uint2*)(w_kvh + 36864 + (size_t)(r0 + 32 * i) * 192 + c4);
            }
#pragma unroll
            for (int kk = 0; kk < 32; kk += 16) {
                unsigned af[2][4], bf[6][2];
#pragma unroll
                for (int m2 = 0; m2 < 2; m2++) {
                    const __half* Ar = smA + kc * 2560 + (wr + 16 * m2 + g) * 40 + kk + 2 * tg;
                    af[m2][0] = ldu(Ar);      af[m2][1] = ldu(Ar + 320);
                    af[m2][2] = ldu(Ar + 8);  af[m2][3] = ldu(Ar + 328);
                }
#pragma unroll
                for (int ni = 0; ni < 6; ni++) {
                    const __half* Br = smB + (wc + 8 * ni + g) * 40 + kk + 2 * tg;
                    bf[ni][0] = ldu(Br);  bf[ni][1] = ldu(Br + 8);
                }
#pragma unroll
                for (int m2 = 0; m2 < 2; m2++)
#pragma unroll
                    for (int ni = 0; ni < 6; ni++)
                        mma16(acc[m2][ni], af[m2], bf[ni][0], bf[ni][1]);
            }
            __syncthreads();
            if (kc + 1 < 6 || kv == 0) {
#pragma unroll
                for (int i = 0; i < 6; i++)
                    *(uint2*)(smB + stsO + 1280 * i) = rb[i];
                __syncthreads();
            }
        }
        // store to Kh / Vt with bias
#pragma unroll
        for (int m2 = 0; m2 < 2; m2++)
#pragma unroll
            for (int ni = 0; ni < 6; ni++) {
                int c = wc + 8 * ni + 2 * tg;
                int h = c >> 5, d = c & 31;
                float2 bv = *(const float2*)(kv_b + kv * 192 + c);
                int row = wr + 16 * m2 + g;
                if (kv == 0) {
                    *(__half2*)(Kh + h * 2560 + row * 40 + d) =
                        __floats2half2_rn(acc[m2][ni][0] + bv.x, acc[m2][ni][1] + bv.y);
                    *(__half2*)(Kh + h * 2560 + (row + 8) * 40 + d) =
                        __floats2half2_rn(acc[m2][ni][2] + bv.x, acc[m2][ni][3] + bv.y);
                } else {
                    __half* vb = Vt + h * 2304 + d * 72;
                    vb[row]          = __float2half_rn(acc[m2][ni][0] + bv.x);
                    vb[72 + row]     = __float2half_rn(acc[m2][ni][1] + bv.y);
                    vb[row + 8]      = __float2half_rn(acc[m2][ni][2] + bv.x);
                    vb[72 + row + 8] = __float2half_rn(acc[m2][ni][3] + bv.y);
                }
            }
    }
    __syncthreads();

    // ---------- attention ----------
    int i0 = 16 * mi + g;
    int w10 = win & 1023;
    bool eh = ((w10 >> 5) == 31), ew = ((w10 & 31) == 31);
    bool edge = eh || ew;
    int ri0 = 0, ri1 = 0, rj0a[8], rj1a[8];
    if (edge) {
        auto region = [&](int n) {
            int a = eh ? (((n >> 3) >= 4) ? 2 : 1) : 0;
            int b = ew ? (((n & 7)  >= 4) ? 2 : 1) : 0;
            return a * 3 + b;
        };
        ri0 = region(i0); ri1 = region(i0 + 8);
#pragma unroll
        for (int ni = 0; ni < 8; ni++) {
            int j0 = 8 * ni + 2 * tg;
            rj0a[ni] = region(j0);
            rj1a[ni] = region(j0 + 1);
        }
    }

#pragma unroll 1
    for (int t = 0; t < 3; t++) {
        int h = 2 * t + hp;
        float s[8][4];
#pragma unroll
        for (int ni = 0; ni < 8; ni++)
#pragma unroll
            for (int e = 0; e < 4; e++) s[ni][e] = 0.f;
        const __half* Kb = Kh + h * 2560 + g * 40 + 2 * tg;
#pragma unroll
        for (int ni = 0; ni < 8; ni++) {
            mma16(s[ni], aq[t][0], ldu(Kb + ni * 320),      ldu(Kb + ni * 320 + 8));
            mma16(s[ni], aq[t][1], ldu(Kb + ni * 320 + 16), ldu(Kb + ni * 320 + 24));
        }
        const __half* bb0 = g_biash + (h * 64 + i0) * 64;
#pragma unroll
        for (int ni = 0; ni < 8; ni++) {
            int j0 = 8 * ni + 2 * tg;
            float2 f0 = __half22float2(*(const __half2*)(bb0 + j0));
            float2 f1 = __half22float2(*(const __half2*)(bb0 + 512 + j0));
            s[ni][0] += f0.x; s[ni][1] += f0.y;
            s[ni][2] += f1.x; s[ni][3] += f1.y;
        }
        if (edge) {
#pragma unroll
            for (int ni = 0; ni < 8; ni++) {
                if (rj0a[ni] != ri0) s[ni][0] -= 100.f;
                if (rj1a[ni] != ri0) s[ni][1] -= 100.f;
                if (rj0a[ni] != ri1) s[ni][2] -= 100.f;
                if (rj1a[ni] != ri1) s[ni][3] -= 100.f;
            }
        }
        float m0 = -1e30f, m1 = -1e30f;
#pragma unroll
        for (int ni = 0; ni < 8; ni++) {
            m0 = fmaxf(m0, fmaxf(s[ni][0], s[ni][1]));
            m1 = fmaxf(m1, fmaxf(s[ni][2], s[ni][3]));
        }
        m0 = fmaxf(m0, __shfl_xor_sync(0xffffffffu, m0, 1));
        m0 = fmaxf(m0, __shfl_xor_sync(0xffffffffu, m0, 2));
        m1 = fmaxf(m1, __shfl_xor_sync(0xffffffffu, m1, 1));
        m1 = fmaxf(m1, __shfl_xor_sync(0xffffffffu, m1, 2));
        float s0 = 0.f, s1 = 0.f;
#pragma unroll
        for (int ni = 0; ni < 8; ni++) {
            s[ni][0] = __expf(s[ni][0] - m0); s0 += s[ni][0];
            s[ni][1] = __expf(s[ni][1] - m0); s0 += s[ni][1];
            s[ni][2] = __expf(s[ni][2] - m1); s1 += s[ni][2];
            s[ni][3] = __expf(s[ni][3] - m1); s1 += s[ni][3];
        }
        s0 += __shfl_xor_sync(0xffffffffu, s0, 1);
        s0 += __shfl_xor_sync(0xffffffffu, s0, 2);
        s1 += __shfl_xor_sync(0xffffffffu, s1, 1);
        s1 += __shfl_xor_sync(0xffffffffu, s1, 2);
        float inv0 = 1.f / s0, inv1 = 1.f / s1;
        unsigned pv[4][4];
#pragma unroll
        for (int js = 0; js < 4; js++) {
            pv[js][0] = h2u(__floats2half2_rn(s[2*js][0]   * inv0, s[2*js][1]   * inv0));
            pv[js][1] = h2u(__floats2half2_rn(s[2*js][2]   * inv1, s[2*js][3]   * inv1));
            pv[js][2] = h2u(__floats2half2_rn(s[2*js+1][0] * inv0, s[2*js+1][1] * inv0));
            pv[js][3] = h2u(__floats2half2_rn(s[2*js+1][2] * inv1, s[2*js+1][3] * inv1));
        }
        float o[4][4];
#pragma unroll
        for (int nd = 0; nd < 4; nd++)
#pragma unroll
            for (int e = 0; e < 4; e++) o[nd][e] = 0.f;
        const __half* Vb = Vt + h * 2304 + g * 72 + 2 * tg;
#pragma unroll
        for (int nd = 0; nd < 4; nd++)
#pragma unroll
            for (int js = 0; js < 4; js++)
                mma16(o[nd], pv[js], ldu(Vb + nd * 576 + 16 * js),
                                     ldu(Vb + nd * 576 + 16 * js + 8));
        // store attn-out to smA in GEMM A-layout (chunk=head)
#pragma unroll
        for (int nd = 0; nd < 4; nd++) {
            int d0 = 8 * nd + 2 * tg;
            *(__half2*)(smA + h * 2560 + i0 * 40 + d0) =
                __floats2half2_rn(o[nd][0], o[nd][1]);
            *(__half2*)(smA + h * 2560 + (i0 + 8) * 40 + d0) =
                __floats2half2_rn(o[nd][2], o[nd][3]);
        }
    }

    // ---------- fused proj+merge GEMM: 64x192 = smA @ Wc^T ----------
#pragma unroll
    for (int i = 0; i < 6; i++)
        rb[i] = *(const uint2*)(w_ch + (size_t)(r0 + 32 * i) * 192 + c4);
    __syncthreads();    // attention reads of Kh/Vt done; smA complete
#pragma unroll
    for (int i = 0; i < 6; i++)
        *(uint2*)(smB2 + stsO + 1280 * i) = rb[i];
    __syncthreads();

    float acc[2][6][4];
#pragma unroll
    for (int a = 0; a < 2; a++)
#pragma unroll
        for (int b_ = 0; b_ < 6; b_++)
#pragma unroll
            for (int e = 0; e < 4; e++) acc[a][b_][e] = 0.f;

#pragma unroll 1
    for (int kc = 0; kc < 6; kc++) {
        if (kc + 1 < 6)
#pragma unroll
            for (int i = 0; i < 6; i++)
                rb[i] = *(const uint2*)(w_ch + (size_t)(r0 + 32 * i) * 192 + (kc + 1) * 32 + c4);
        const __half* Ab = smA + kc * 2560;
        const __half* Bb = smB2 + (kc & 1) * 7680;
#pragma unroll
        for (int kk = 0; kk < 32; kk += 16) {
            unsigned af[2][4], bf[6][2];
#pragma unroll
            for (int m2 = 0; m2 < 2; m2++) {
                const __half* Ar = Ab + (wr + 16 * m2 + g) * 40 + kk + 2 * tg;
                af[m2][0] = ldu(Ar);      af[m2][1] = ldu(Ar + 320);
                af[m2][2] = ldu(Ar + 8);  af[m2][3] = ldu(Ar + 328);
            }
#pragma unroll
            for (int ni = 0; ni < 6; ni++) {
                const __half* Br = Bb + (wc + 8 * ni + g) * 40 + kk + 2 * tg;
                bf[ni][0] = ldu(Br);  bf[ni][1] = ldu(Br + 8);
            }
#pragma unroll
            for (int m2 = 0; m2 < 2; m2++)
#pragma unroll
                for (int ni = 0; ni < 6; ni++)
                    mma16(acc[m2][ni], af[m2], bf[ni][0], bf[ni][1]);
        }
        if (kc + 1 < 6)
#pragma unroll
            for (int i = 0; i < 6; i++)
                *(uint2*)(smB2 + ((kc + 1) & 1) * 7680 + stsO + 1280 * i) = rb[i];
        __syncthreads();
    }

    // ---------- epilogue: combined bias + LN(norm1) + shortcut + scatter ----------
    {
        const int lane2 = tid & 31, w2 = tid >> 5;
        const int g2 = lane2 >> 2, tg2 = lane2 & 3;
#pragma unroll
        for (int m2 = 0; m2 < 2; m2++)
#pragma unroll
            for (int ni = 0; ni < 6; ni++) {
                int row = wr + 16 * m2 + g2;
                int col = wc + 8 * ni + 2 * tg2;
                St[row * 200 + col]           = acc[m2][ni][0];
                St[row * 200 + col + 1]       = acc[m2][ni][1];
                St[(row + 8) * 200 + col]     = acc[m2][ni][2];
                St[(row + 8) * 200 + col + 1] = acc[m2][ni][3];
            }
    }
    __syncthreads();
    int wp = tid >> 5, l = tid & 31;
    int b = win >> 10, wh = (win >> 5) & 31, ww = win & 31;
#pragma unroll 1
    for (int rr = 0; rr < 8; rr++) {
        int n = wp * 8 + rr;
        int hpx = (wh * 8 + (n >> 3) + 4) & 255;
        int wpx = (ww * 8 + (n & 7) + 4) & 255;
        size_t row = ((size_t)b * HWd + hpx * Wdim + wpx) * Cd;
        float vv[6]; float su = 0.f;
#pragma unroll
        for (int u = 0; u < 6; u++) {
            int c = l + 32 * u;
            vv[u] = St[n * 200 + c] + g_bc[c];
            su += vv[u];
        }
        su = warp_sum(su);
        float mean = su * (1.f / 192.f);
        float sq = 0.f;
#pragma unroll
        for (int u = 0; u < 6; u++) { float d = vv[u] - mean; sq += d * d; }
        sq = warp_sum(sq);
        float rstd = rsqrtf(sq * (1.f / 192.f) + 1e-5f);
#pragma unroll
        for (int u = 0; u < 6; u++) {
            int c = l + 32 * u;
            float y = (vv[u] - mean) * rstd * n1g[c] + n1b[c] + g_xt[row + c];
            g_x1[row + c]  = y;
            g_x1h[row + c] = __float2half_rn(y);
        }
    }
}

// ======================= K5: fused MLP =======================
__global__ void __launch_bounds__(256, 2) k_mlp(
    const float* __restrict__ b1h, const float* __restrict__ b2,
    const float* __restrict__ g2, const float* __restrict__ bb2,
    float* __restrict__ out)
{
    extern __shared__ float sm[];
    __half* smA  = (__half*)sm;
    __half* smB1 = smA + 15360;
    __half* smH  = smB1 + 7680;
    __half* smB2 = smH + 7680;
    int tid = threadIdx.x;
    size_t mbase = (size_t)blockIdx.x * 64;
    const int lane = tid & 31, w = tid >> 5;
    const int g = lane >> 2, tg = lane & 3;
    const int wr  = (w & 1) * 32;
    const int wc1 = (w >> 1) * 24;
    const int wc2 = (w >> 1) * 48;
    const int r0 = tid >> 3, c4 = 4 * (tid & 7);
    const int stsO = r0 * 40 + c4;

    const __half* aSrc = g_x1h + mbase * 192;
#pragma unroll
    for (int c = 0; c < 6; c++)
#pragma unroll
        for (int i = 0; i < 2; i++) {
            uint2 v = *(const uint2*)(aSrc + (size_t)(r0 + 32 * i) * 192 + c * 32 + c4);
            *(uint2*)(smA + c * 2560 + stsO + 1280 * i) = v;
        }

    float acc2[2][6][4];
#pragma unroll
    for (int a = 0; a < 2; a++)
#pragma unroll
        for (int b_ = 0; b_ < 6; b_++)
#pragma unroll
            for (int cc = 0; cc < 4; cc++) acc2[a][b_][cc] = 0.f;

#pragma unroll 1
    for (int oc = 0; oc < 8; oc++) {
        const __half* W1 = w_f1h + (size_t)(oc * 96) * 192;
        uint2 rb1[3];
#pragma unroll
        for (int i = 0; i < 3; i++)
            rb1[i] = *(const uint2*)(W1 + (size_t)(r0 + 32 * i) * 192 + c4);
#pragma unroll
        for (int i = 0; i < 3; i++)
            *(uint2*)(smB1 + stsO + 1280 * i) = rb1[i];
        __syncthreads();

        float acc1[2][3][4];
#pragma unroll
        for (int a = 0; a < 2; a++)
#pragma unroll
            for (int b_ = 0; b_ < 3; b_++)
#pragma unroll
                for (int cc = 0; cc < 4; cc++) acc1[a][b_][cc] = 0.f;

#pragma unroll 1
        for (int kc = 0; kc < 6; kc++) {
            if (kc + 1 < 6)
#pragma unroll
                for (int i = 0; i < 3; i++)
                    rb1[i] = *(const uint2*)(W1 + (size_t)(r0 + 32 * i) * 192 + (kc + 1) * 32 + c4);
            const __half* Ab = smA + kc * 2560;
            const __half* Bb = smB1 + (kc & 1) * 3840;
#pragma unroll
            for (int kk = 0; kk < 32; kk += 16) {
                unsigned af[2][4], bf[3][2];
#pragma unroll
                for (int mi = 0; mi < 2; mi++) {
                    const __half* Ar = Ab + (wr + 16 * mi + g) * 40 + kk + 2 * tg;
                    af[mi][0] = ldu(Ar);       af[mi][1] = ldu(Ar + 320);
                    af[mi][2] = ldu(Ar + 8);   af[mi][3] = ldu(Ar + 328);
                }
#pragma unroll
                for (int ni = 0; ni < 3; ni++) {
                    const __half* Br = Bb + (wc1 + 8 * ni + g) * 40 + kk + 2 * tg;
                    bf[ni][0] = ldu(Br);  bf[ni][1] = ldu(Br + 8);
                }
#pragma unroll
                for (int mi = 0; mi < 2; mi++)
#pragma unroll
                    for (int ni = 0; ni < 3; ni++)
                        mma16(acc1[mi][ni], af[mi], bf[ni][0], bf[ni][1]);
            }
            if (kc + 1 < 6)
#pragma unroll
                for (int i = 0; i < 3; i++)
                    *(uint2*)(smB1 + ((kc + 1) & 1) * 3840 + stsO + 1280 * i) = rb1[i];
            __syncthreads();
        }

#pragma unroll
        for (int mi = 0; mi < 2; mi++)
#pragma unroll
            for (int ni = 0; ni < 3; ni++) {
                int row = wr + 16 * mi + g;
                int col = wc1 + 8 * ni + 2 * tg;
                float2 bv = *(const float2*)(b1h + oc * 96 + col);
                __half* hp0 = smH + (col >> 5) * 2560 + row * 40 + (col & 31);
                *(__half2*)hp0 = __floats2half2_rn(
                    gelu_f(acc1[mi][ni][0] + bv.x), gelu_f(acc1[mi][ni][1] + bv.y));
                *(__half2*)(hp0 + 320) = __floats2half2_rn(
                    gelu_f(acc1[mi][ni][2] + bv.x), gelu_f(acc1[mi][ni][3] + bv.y));
            }

        const __half* W2 = w_f2h;
        uint2 rb2[6];
#pragma unroll
        for (int i = 0; i < 6; i++)
            rb2[i] = *(const uint2*)(W2 + (size_t)(r0 + 32 * i) * 768 + oc * 96 + c4);
#pragma unroll
        for (int i = 0; i < 6; i++)
            *(uint2*)(smB2 + stsO + 1280 * i) = rb2[i];
        __syncthreads();

#pragma unroll 1
        for (int kc = 0; kc < 3; kc++) {
            if (kc + 1 < 3)
#pragma unroll
                for (int i = 0; i < 6; i++)
                    rb2[i] = *(const uint2*)(W2 + (size_t)(r0 + 32 * i) * 768 + oc * 96 + (kc + 1) * 32 + c4);
            const __half* Ab = smH + kc * 2560;
            const __half* Bb = smB2 + (kc & 1) * 7680;
#pragma unroll
            for (int kk = 0; kk < 32; kk += 16) {
                unsigned af[2][4], bf[6][2];
#pragma unroll
                for (int mi = 0; mi < 2; mi++) {
                    const __half* Ar = Ab + (wr + 16 * mi + g) * 40 + kk + 2 * tg;
                    af[mi][0] = ldu(Ar);       af[mi][1] = ldu(Ar + 320);
                    af[mi][2] = ldu(Ar + 8);   af[mi][3] = ldu(Ar + 328);
                }
#pragma unroll
                for (int ni = 0; ni < 6; ni++) {
                    const __half* Br = Bb + (wc2 + 8 * ni + g) * 40 + kk + 2 * tg;
                    bf[ni][0] = ldu(Br);  bf[ni][1] = ldu(Br + 8);
                }
#pragma unroll
                for (int mi = 0; mi < 2; mi++)
#pragma unroll
                    for (int ni = 0; ni < 6; ni++)
                        mma16(acc2[mi][ni], af[mi], bf[ni][0], bf[ni][1]);
            }
            if (kc + 1 < 3)
#pragma unroll
                for (int i = 0; i < 6; i++)
                    *(uint2*)(smB2 + ((kc + 1) & 1) * 7680 + stsO + 1280 * i) = rb2[i];
            __syncthreads();
        }
    }

    float* St = sm;
    {
#pragma unroll
        for (int mi = 0; mi < 2; mi++)
#pragma unroll
            for (int ni = 0; ni < 6; ni++) {
                int row = wr + 16 * mi + g;
                int col = wc2 + 8 * ni + 2 * tg;
                St[row * 200 + col]           = acc2[mi][ni][0];
                St[row * 200 + col + 1]       = acc2[mi][ni][1];
                St[(row + 8) * 200 + col]     = acc2[mi][ni][2];
                St[(row + 8) * 200 + col + 1] = acc2[mi][ni][3];
            }
    }
    __syncthreads();
    int wp = tid >> 5, l = tid & 31;
#pragma unroll 1
    for (int rr = 0; rr < 8; rr++) {
        int r = wp * 8 + rr;
        float vv[6]; float su = 0.f;
#pragma unroll
        for (int u = 0; u < 6; u++) {
            int c = l + 32 * u;
            vv[u] = St[r * 200 + c] + b2[c];
            su += vv[u];
        }
        su = warp_sum(su);
        float mean = su * (1.f / 192.f);
        float sq = 0.f;
#pragma unroll
        for (int u = 0; u < 6; u++) { float d = vv[u] - mean; sq += d * d; }
        sq = warp_sum(sq);
        float rstd = rsqrtf(sq * (1.f / 192.f) + 1e-5f);
        size_t row = (mbase + r) * Cd;
#pragma unroll
        for (int u = 0; u < 6; u++) {
            int c = l + 32 * u;
            out[row + c] = g_x1[row + c] + (vv[u] - mean) * rstd * g2[c] + bb2[c];
        }
    }
}

// ======================= host =======================
extern "C" void kernel_launch(void* const* d_in, const int* in_sizes, int n_in,
                              void* d_out, int out_size)
{
    const float* x    = (const float*)d_in[0];
    const float* feat = (const float*)d_in[1];
    const int*   ridx = (const int*)  d_in[3];
    const float* rtab = (const float*)d_in[4];
    const float* q_w  = (const float*)d_in[5];
    const float* q_b  = (const float*)d_in[6];
    const float* kv_w = (const float*)d_in[7];
    const float* kv_b = (const float*)d_in[8];
    const float* p_w  = (const float*)d_in[9];
    const float* p_b  = (const float*)d_in[10];
    const float* m_w  = (const float*)d_in[11];
    const float* n1g  = (const float*)d_in[12];
    const float* n1b  = (const float*)d_in[13];
    const float* n2g  = (const float*)d_in[14];
    const float* n2b  = (const float*)d_in[15];
    const float* f1w  = (const float*)d_in[16];
    const float* f1b  = (const float*)d_in[17];
    const float* f2w  = (const float*)d_in[18];
    const float* f2b  = (const float*)d_in[19];
    float* out = (float*)d_out;

    __half *dwq, *dwkv, *dwf1, *dwf2;
    cudaGetSymbolAddress((void**)&dwq,  w_qh);
    cudaGetSymbolAddress((void**)&dwkv, w_kvh);
    cudaGetSymbolAddress((void**)&dwf1, w_f1h);
    cudaGetSymbolAddress((void**)&dwf2, w_f2h);

    const int smAttn = 52224 * 2;                        // 104448
    const int smMlp  = 46080 * 2;                        // 92160
    cudaFuncSetAttribute(k_attn, cudaFuncAttributeMaxDynamicSharedMemorySize, smAttn);
    cudaFuncSetAttribute(k_mlp,  cudaFuncAttributeMaxDynamicSharedMemorySize, smMlp);

    k_f2h_s<<<144, 256>>>(q_w,  dwq,  36864, QSCALE);
    k_f2h  <<<288, 256>>>(kv_w, dwkv, 73728);
    k_wcomb<<<144, 256>>>(m_w, p_w, p_b);
    k_f2h  <<<576, 256>>>(f1w,  dwf1, 147456);
    k_f2h  <<<576, 256>>>(f2w,  dwf2, 147456);
    k_bias <<<96, 256>>>(ridx, rtab);
    k_transpose<<<dim3(6, 2048, 8), dim3(32, 8)>>>(x, feat);
    k_attn <<<NWINd, 256, smAttn>>>(q_b, kv_b, n1g, n1b);
    k_mlp  <<<4096, 256, smMlp>>>(f1b, f2b, n2g, n2b, out);
}

// round 8
// speedup vs baseline: 8.7164x; 1.2148x over previous
#include <cuda_runtime.h>
#include <cuda_fp16.h>
#include <math.h>
#include <stdint.h>

#define Hd    256
#define Wdim  256
#define HWd   65536
#define Cd    192
#define Bd    4
#define NHd   6
#define HDd   32
#define NWINd 4096
#define MTOKd 262144
#define HIDd  768
#define QSCALE 0.17677669529663687f

// -------- scratch --------
__device__ float  g_xt  [(size_t)MTOKd * Cd];           // fp32 pixel-order (shortcut)
__device__ __half g_xth [(size_t)MTOKd * Cd];           // fp16 WINDOW-order
__device__ __half g_fth [(size_t)MTOKd * Cd];           // fp16 WINDOW-order
__device__ __half g_biash[NHd * 64 * 64];
__device__ __half w_qh [36864];
__device__ __half w_kvh[73728];
__device__ __half w_ch [36864];     // combined merge@proj weight
__device__ float  g_bc [192];       // combined bias m_w @ p_b
__device__ __half w_f1h[147456];
__device__ __half w_f2h[147456];

__device__ __forceinline__ float warp_sum(float v) {
#pragma unroll
    for (int o = 16; o; o >>= 1) v += __shfl_xor_sync(0xffffffffu, v, o);
    return v;
}
__device__ __forceinline__ unsigned h2u(__half2 h) {
    return *reinterpret_cast<unsigned*>(&h);
}
__device__ __forceinline__ unsigned ldu(const __half* p) {
    return *reinterpret_cast<const unsigned*>(p);
}
__device__ __forceinline__ float gelu_f(float v) {
    return 0.5f * v * (1.f + erff(v * 0.70710678118654752f));
}
__device__ __forceinline__ void mma16(float* c, const unsigned* a, unsigned b0, unsigned b1) {
    asm volatile(
        "mma.sync.aligned.m16n8k16.row.col.f32.f16.f16.f32 "
        "{%0,%1,%2,%3}, {%4,%5,%6,%7}, {%8,%9}, {%0,%1,%2,%3};"
        : "+f"(c[0]), "+f"(c[1]), "+f"(c[2]), "+f"(c[3])
        : "r"(a[0]), "r"(a[1]), "r"(a[2]), "r"(a[3]), "r"(b0), "r"(b1));
}

// ======================= prep kernels =======================
__global__ void k_f2h(const float* __restrict__ src, __half* __restrict__ dst, int n) {
    int i = blockIdx.x * 256 + threadIdx.x;
    if (i < n) dst[i] = __float2half_rn(src[i]);
}
__global__ void k_f2h_s(const float* __restrict__ src, __half* __restrict__ dst,
                        int n, float s) {
    int i = blockIdx.x * 256 + threadIdx.x;
    if (i < n) dst[i] = __float2half_rn(src[i] * s);
}
__global__ void k_bias(const int* __restrict__ relidx, const float* __restrict__ table) {
    int idx = blockIdx.x * 256 + threadIdx.x;
    if (idx < NHd * 4096) {
        int h = idx >> 12, r = idx & 4095;
        g_biash[idx] = __float2half_rn(table[relidx[r] * NHd + h]);
    }
}
__global__ void k_wcomb(const float* __restrict__ mw, const float* __restrict__ pw,
                        const float* __restrict__ pb) {
    int e = blockIdx.x * 256 + threadIdx.x;
    if (e < 36864) {
        int i = e / 192, j = e - (e / 192) * 192;
        float acc = 0.f;
        for (int k = 0; k < 192; k++) acc += mw[i * 192 + k] * pw[k * 192 + j];
        w_ch[e] = __float2half_rn(acc);
    }
    if (e < 192) {
        float acc = 0.f;
        for (int k = 0; k < 192; k++) acc += mw[e * 192 + k] * pb[k];
        g_bc[e] = acc;
    }
}

// ======================= K0: transpose; fp16 copies in WINDOW order =======================
__global__ void k_transpose(const float* __restrict__ x, const float* __restrict__ feat) {
    __shared__ float t[32][33];
    int z = blockIdx.z;
    int b = z & 3, which = z >> 2;
    int c0 = blockIdx.x << 5;
    int p0 = blockIdx.y << 5;
    const float* src = (which ? feat : x) + (size_t)b * Cd * HWd;
    int tx = threadIdx.x, ty = threadIdx.y;
#pragma unroll
    for (int i = ty; i < 32; i += 8)
        t[i][tx] = src[(size_t)(c0 + i) * HWd + p0 + tx];
    __syncthreads();
    int h  = p0 >> 8;
    int h2 = (h - 4) & 255;
    int whp = ((h2 >> 3) << 5);
    int nh8 = (h2 & 7) << 3;
    __half* dh = (which ? g_fth : g_xth) + (size_t)b * HWd * Cd;
    float*  df = g_xt + (size_t)b * HWd * Cd;
#pragma unroll
    for (int i = ty; i < 32; i += 8) {
        int wv = ((p0 & 255) + i);
        int w2 = (wv - 4) & 255;
        int tok = ((whp + (w2 >> 3)) << 6) + nh8 + (w2 & 7);
        float v = t[tx][i];
        dh[(size_t)tok * Cd + c0 + tx] = __float2half_rn(v);
        if (!which) df[(size_t)(p0 + i) * Cd + c0 + tx] = v;
    }
}

// ======================= MEGA kernel: QKV + attn + proj·merge + LN1 + MLP + LN2 ====
// smem halves (52224 total = 104448 B):
//   phase A: smA [0,15360) | Kh [15360,30720) | Vt [30720,44544) | smB [44544,52224)
//   phase B (proj GEMM): Wc dbuf overlays Kh; St fp32 overlays halves [15360,40960)
//   phase C (MLP): smA = x1h | B1 dbuf [15360,23040) | H [23040,30720) | B2 dbuf [30720,46080)
//   final: St fp32 overlays [15360,40960)
__global__ void __launch_bounds__(256, 2) k_mega(
    const float* __restrict__ q_b, const float* __restrict__ kv_b,
    const float* __restrict__ n1g, const float* __restrict__ n1b,
    const float* __restrict__ b1h, const float* __restrict__ b2,
    const float* __restrict__ g2, const float* __restrict__ bb2,
    float* __restrict__ out)
{
    extern __shared__ float smf[];
    __half* smA = (__half*)smf;
    __half* Kh  = smA + 15360;
    __half* Vt  = smA + 30720;
    __half* smB = smA + 44544;
    __half* smB2 = Kh;                 // Wc GEMM double buffer (2x7680)
    float*  St  = smf + 7680;          // fp32 stage, halves [15360,40960)
    __half* smB1m = smA + 15360;       // MLP fc1 W dbuf (2x3840)
    __half* smHm  = smA + 23040;       // MLP h1 (3x2560)
    __half* smB2m = smA + 30720;       // MLP fc2 W dbuf (2x7680)
    int win = blockIdx.x;
    int tid = threadIdx.x;
    int lane = tid & 31, w = tid >> 5;
    int g = lane >> 2, tg = lane & 3;
    int mi = w & 3, hp = w >> 2;
    const int r0 = tid >> 3, c4 = 4 * (tid & 7);
    const int stsO = r0 * 40 + c4;
    const int wr = (w & 1) * 32, wc = (w >> 1) * 48;
    const int wc1 = (w >> 1) * 24;

    // pixel scatter coords for this window
    int bI = win >> 10, wh = (win >> 5) & 31, ww = win & 31;

    // ---------- load xw; stage Wq chunk 0 ----------
    const __half* xsrc = g_xth + (size_t)win * 64 * 192;
#pragma unroll
    for (int c = 0; c < 6; c++)
#pragma unroll
        for (int i = 0; i < 2; i++) {
            uint2 v = *(const uint2*)(xsrc + (size_t)(r0 + 32 * i) * 192 + c * 32 + c4);
            *(uint2*)(smA + c * 2560 + stsO + 1280 * i) = v;
        }
    uint2 rb[6];
#pragma unroll
    for (int i = 0; i < 6; i++)
        rb[i] = *(const uint2*)(w_qh + (size_t)(r0 + 32 * i) * 192 + c4);
#pragma unroll
    for (int i = 0; i < 6; i++) *(uint2*)(smB + stsO + 1280 * i) = rb[i];
    __syncthreads();

    // ---------- Q GEMM: rows 16mi..+16, heads {hp,2+hp,4+hp} ----------
    float qacc[3][4][4];
#pragma unroll
    for (int t = 0; t < 3; t++)
#pragma unroll
        for (int nq = 0; nq < 4; nq++)
#pragma unroll
            for (int e = 0; e < 4; e++) qacc[t][nq][e] = 0.f;
#pragma unroll 1
    for (int kc = 0; kc < 6; kc++) {
        if (kc + 1 < 6)
#pragma unroll
            for (int i = 0; i < 6; i++)
                rb[i] = *(const uint2*)(w_qh + (size_t)(r0 + 32 * i) * 192 + (kc + 1) * 32 + c4);
#pragma unroll
        for (int kk = 0; kk < 32; kk += 16) {
            unsigned af[4];
            const __half* Ar = smA + kc * 2560 + (16 * mi + g) * 40 + kk + 2 * tg;
            af[0] = ldu(Ar);      af[1] = ldu(Ar + 320);
            af[2] = ldu(Ar + 8);  af[3] = ldu(Ar + 328);
#pragma unroll
            for (int t = 0; t < 3; t++)
#pragma unroll
                for (int nq = 0; nq < 4; nq++) {
                    const __half* Br = smB + (32 * (2 * t + hp) + 8 * nq + g) * 40 + kk + 2 * tg;
                    mma16(qacc[t][nq], af, ldu(Br), ldu(Br + 8));
                }
        }
        __syncthreads();
        if (kc + 1 < 6) {
#pragma unroll
            for (int i = 0; i < 6; i++)
                *(uint2*)(smB + stsO + 1280 * i) = rb[i];
            __syncthreads();
        }
    }

    // ---------- repack Q: C-frag -> A-frag, + scaled bias ----------
    unsigned aq[3][2][4];
#pragma unroll
    for (int t = 0; t < 3; t++) {
        int h = 2 * t + hp;
#pragma unroll
        for (int ks = 0; ks < 2; ks++) {
            float2 b0 = *(const float2*)(q_b + 32 * h + 16 * ks + 2 * tg);
            float2 b1 = *(const float2*)(q_b + 32 * h + 16 * ks + 8 + 2 * tg);
            b0.x *= QSCALE; b0.y *= QSCALE; b1.x *= QSCALE; b1.y *= QSCALE;
            aq[t][ks][0] = h2u(__floats2half2_rn(qacc[t][2*ks][0] + b0.x, qacc[t][2*ks][1] + b0.y));
            aq[t][ks][1] = h2u(__floats2half2_rn(qacc[t][2*ks][2] + b0.x, qacc[t][2*ks][3] + b0.y));
            aq[t][ks][2] = h2u(__floats2half2_rn(qacc[t][2*ks+1][0] + b1.x, qacc[t][2*ks+1][1] + b1.y));
            aq[t][ks][3] = h2u(__floats2half2_rn(qacc[t][2*ks+1][2] + b1.x, qacc[t][2*ks+1][3] + b1.y));
        }
    }

    // ---------- load fw (overwrite smA); stage Wk chunk 0 ----------
    const __half* fsrc = g_fth + (size_t)win * 64 * 192;
#pragma unroll
    for (int c = 0; c < 6; c++)
#pragma unroll
        for (int i = 0; i < 2; i++) {
            uint2 v = *(const uint2*)(fsrc + (size_t)(r0 + 32 * i) * 192 + c * 32 + c4);
            *(uint2*)(smA + c * 2560 + stsO + 1280 * i) = v;
        }
#pragma unroll
    for (int i = 0; i < 6; i++)
        rb[i] = *(const uint2*)(w_kvh + (size_t)(r0 + 32 * i) * 192 + c4);
#pragma unroll
    for (int i = 0; i < 6; i++) *(uint2*)(smB + stsO + 1280 * i) = rb[i];
    __syncthreads();

    // ---------- K GEMM -> Kh, then V GEMM -> Vt ----------
#pragma unroll 1
    for (int kv = 0; kv < 2; kv++) {
        const __half* W = w_kvh + (size_t)kv * 36864;
        float acc[2][6][4];
#pragma unroll
        for (int a = 0; a < 2; a++)
#pragma unroll
            for (int b_ = 0; b_ < 6; b_++)
#pragma unroll
                for (int e = 0; e < 4; e++) acc[a][b_][e] = 0.f;
#pragma unroll 1
        for (int kc = 0; kc < 6; kc++) {
            if (kc + 1 < 6) {
#pragma unroll
                for (int i = 0; i < 6; i++)
                    rb[i] = *(const uint2*)(W + (size_t)(r0 + 32 * i) * 192 + (kc + 1) * 32 + c4);
            } else if (kv == 0) {
#pragma unroll
                for (int i = 0; i < 6; i++)
                    rb[i] = *(const uint2*)(w_kvh + 36864 + (size_t)(r0 + 32 * i) * 192 + c4);
            }
#pragma unroll
            for (int kk = 0; kk < 32; kk += 16) {
                unsigned af[2][4], bf[6][2];
#pragma unroll
                for (int m2 = 0; m2 < 2; m2++) {
                    const __half* Ar = smA + kc * 2560 + (wr + 16 * m2 + g) * 40 + kk + 2 * tg;
                    af[m2][0] = ldu(Ar);      af[m2][1] = ldu(Ar + 320);
                    af[m2][2] = ldu(Ar + 8);  af[m2][3] = ldu(Ar + 328);
                }
#pragma unroll
                for (int ni = 0; ni < 6; ni++) {
                    const __half* Br = smB + (wc + 8 * ni + g) * 40 + kk + 2 * tg;
                    bf[ni][0] = ldu(Br);  bf[ni][1] = ldu(Br + 8);
                }
#pragma unroll
                for (int m2 = 0; m2 < 2; m2++)
#pragma unroll
                    for (int ni = 0; ni < 6; ni++)
                        mma16(acc[m2][ni], af[m2], bf[ni][0], bf[ni][1]);
            }
            __syncthreads();
            if (kc + 1 < 6 || kv == 0) {
#pragma unroll
                for (int i = 0; i < 6; i++)
                    *(uint2*)(smB + stsO + 1280 * i) = rb[i];
                __syncthreads();
            }
        }
#pragma unroll
        for (int m2 = 0; m2 < 2; m2++)
#pragma unroll
            for (int ni = 0; ni < 6; ni++) {
                int c = wc + 8 * ni + 2 * tg;
                int h = c >> 5, d = c & 31;
                float2 bv = *(const float2*)(kv_b + kv * 192 + c);
                int row = wr + 16 * m2 + g;
                if (kv == 0) {
                    *(__half2*)(Kh + h * 2560 + row * 40 + d) =
                        __floats2half2_rn(acc[m2][ni][0] + bv.x, acc[m2][ni][1] + bv.y);
                    *(__half2*)(Kh + h * 2560 + (row + 8) * 40 + d) =
                        __floats2half2_rn(acc[m2][ni][2] + bv.x, acc[m2][ni][3] + bv.y);
                } else {
                    __half* vb = Vt + h * 2304 + d * 72;
                    vb[row]          = __float2half_rn(acc[m2][ni][0] + bv.x);
                    vb[72 + row]     = __float2half_rn(acc[m2][ni][1] + bv.y);
                    vb[row + 8]      = __float2half_rn(acc[m2][ni][2] + bv.x);
                    vb[72 + row + 8] = __float2half_rn(acc[m2][ni][3] + bv.y);
                }
            }
    }
    __syncthreads();

    // ---------- attention ----------
    int i0 = 16 * mi + g;
    int w10 = win & 1023;
    bool eh = ((w10 >> 5) == 31), ew = ((w10 & 31) == 31);
    bool edge = eh || ew;
    int ri0 = 0, ri1 = 0, rj0a[8], rj1a[8];
    if (edge) {
        auto region = [&](int n) {
            int a = eh ? (((n >> 3) >= 4) ? 2 : 1) : 0;
            int b = ew ? (((n & 7)  >= 4) ? 2 : 1) : 0;
            return a * 3 + b;
        };
        ri0 = region(i0); ri1 = region(i0 + 8);
#pragma unroll
        for (int ni = 0; ni < 8; ni++) {
            int j0 = 8 * ni + 2 * tg;
            rj0a[ni] = region(j0);
            rj1a[ni] = region(j0 + 1);
        }
    }

#pragma unroll 1
    for (int t = 0; t < 3; t++) {
        int h = 2 * t + hp;
        float s[8][4];
#pragma unroll
        for (int ni = 0; ni < 8; ni++)
#pragma unroll
            for (int e = 0; e < 4; e++) s[ni][e] = 0.f;
        const __half* Kb = Kh + h * 2560 + g * 40 + 2 * tg;
#pragma unroll
        for (int ni = 0; ni < 8; ni++) {
            mma16(s[ni], aq[t][0], ldu(Kb + ni * 320),      ldu(Kb + ni * 320 + 8));
            mma16(s[ni], aq[t][1], ldu(Kb + ni * 320 + 16), ldu(Kb + ni * 320 + 24));
        }
        const __half* bb0 = g_biash + (h * 64 + i0) * 64;
#pragma unroll
        for (int ni = 0; ni < 8; ni++) {
            int j0 = 8 * ni + 2 * tg;
            float2 f0 = __half22float2(*(const __half2*)(bb0 + j0));
            float2 f1 = __half22float2(*(const __half2*)(bb0 + 512 + j0));
            s[ni][0] += f0.x; s[ni][1] += f0.y;
            s[ni][2] += f1.x; s[ni][3] += f1.y;
        }
        if (edge) {
#pragma unroll
            for (int ni = 0; ni < 8; ni++) {
                if (rj0a[ni] != ri0) s[ni][0] -= 100.f;
                if (rj1a[ni] != ri0) s[ni][1] -= 100.f;
                if (rj0a[ni] != ri1) s[ni][2] -= 100.f;
                if (rj1a[ni] != ri1) s[ni][3] -= 100.f;
            }
        }
        float m0 = -1e30f, m1 = -1e30f;
#pragma unroll
        for (int ni = 0; ni < 8; ni++) {
            m0 = fmaxf(m0, fmaxf(s[ni][0], s[ni][1]));
            m1 = fmaxf(m1, fmaxf(s[ni][2], s[ni][3]));
        }
        m0 = fmaxf(m0, __shfl_xor_sync(0xffffffffu, m0, 1));
        m0 = fmaxf(m0, __shfl_xor_sync(0xffffffffu, m0, 2));
        m1 = fmaxf(m1, __shfl_xor_sync(0xffffffffu, m1, 1));
        m1 = fmaxf(m1, __shfl_xor_sync(0xffffffffu, m1, 2));
        float s0 = 0.f, s1 = 0.f;
#pragma unroll
        for (int ni = 0; ni < 8; ni++) {
            s[ni][0] = __expf(s[ni][0] - m0); s0 += s[ni][0];
            s[ni][1] = __expf(s[ni][1] - m0); s0 += s[ni][1];
            s[ni][2] = __expf(s[ni][2] - m1); s1 += s[ni][2];
            s[ni][3] = __expf(s[ni][3] - m1); s1 += s[ni][3];
        }
        s0 += __shfl_xor_sync(0xffffffffu, s0, 1);
        s0 += __shfl_xor_sync(0xffffffffu, s0, 2);
        s1 += __shfl_xor_sync(0xffffffffu, s1, 1);
        s1 += __shfl_xor_sync(0xffffffffu, s1, 2);
        float inv0 = 1.f / s0, inv1 = 1.f / s1;
        unsigned pv[4][4];
#pragma unroll
        for (int js = 0; js < 4; js++) {
            pv[js][0] = h2u(__floats2half2_rn(s[2*js][0]   * inv0, s[2*js][1]   * inv0));
            pv[js][1] = h2u(__floats2half2_rn(s[2*js][2]   * inv1, s[2*js][3]   * inv1));
            pv[js][2] = h2u(__floats2half2_rn(s[2*js+1][0] * inv0, s[2*js+1][1] * inv0));
            pv[js][3] = h2u(__floats2half2_rn(s[2*js+1][2] * inv1, s[2*js+1][3] * inv1));
        }
        float o[4][4];
#pragma unroll
        for (int nd = 0; nd < 4; nd++)
#pragma unroll
            for (int e = 0; e < 4; e++) o[nd][e] = 0.f;
        const __half* Vb = Vt + h * 2304 + g * 72 + 2 * tg;
#pragma unroll
        for (int nd = 0; nd < 4; nd++)
#pragma unroll
            for (int js = 0; js < 4; js++)
                mma16(o[nd], pv[js], ldu(Vb + nd * 576 + 16 * js),
                                     ldu(Vb + nd * 576 + 16 * js + 8));
#pragma unroll
        for (int nd = 0; nd < 4; nd++) {
            int d0 = 8 * nd + 2 * tg;
            *(__half2*)(smA + h * 2560 + i0 * 40 + d0) =
                __floats2half2_rn(o[nd][0], o[nd][1]);
            *(__half2*)(smA + h * 2560 + (i0 + 8) * 40 + d0) =
                __floats2half2_rn(o[nd][2], o[nd][3]);
        }
    }

    // ---------- fused proj+merge GEMM: 64x192 = smA @ Wc^T ----------
#pragma unroll
    for (int i = 0; i < 6; i++)
        rb[i] = *(const uint2*)(w_ch + (size_t)(r0 + 32 * i) * 192 + c4);
    __syncthreads();
#pragma unroll
    for (int i = 0; i < 6; i++)
        *(uint2*)(smB2 + stsO + 1280 * i) = rb[i];
    __syncthreads();

    {
        float acc[2][6][4];
#pragma unroll
        for (int a = 0; a < 2; a++)
#pragma unroll
            for (int b_ = 0; b_ < 6; b_++)
#pragma unroll
                for (int e = 0; e < 4; e++) acc[a][b_][e] = 0.f;

#pragma unroll 1
        for (int kc = 0; kc < 6; kc++) {
            if (kc + 1 < 6)
#pragma unroll
                for (int i = 0; i < 6; i++)
                    rb[i] = *(const uint2*)(w_ch + (size_t)(r0 + 32 * i) * 192 + (kc + 1) * 32 + c4);
            const __half* Ab = smA + kc * 2560;
            const __half* Bb = smB2 + (kc & 1) * 7680;
#pragma unroll
            for (int kk = 0; kk < 32; kk += 16) {
                unsigned af[2][4], bf[6][2];
#pragma unroll
                for (int m2 = 0; m2 < 2; m2++) {
                    const __half* Ar = Ab + (wr + 16 * m2 + g) * 40 + kk + 2 * tg;
                    af[m2][0] = ldu(Ar);      af[m2][1] = ldu(Ar + 320);
                    af[m2][2] = ldu(Ar + 8);  af[m2][3] = ldu(Ar + 328);
                }
#pragma unroll
                for (int ni = 0; ni < 6; ni++) {
                    const __half* Br = Bb + (wc + 8 * ni + g) * 40 + kk + 2 * tg;
                    bf[ni][0] = ldu(Br);  bf[ni][1] = ldu(Br + 8);
                }
#pragma unroll
                for (int m2 = 0; m2 < 2; m2++)
#pragma unroll
                    for (int ni = 0; ni < 6; ni++)
                        mma16(acc[m2][ni], af[m2], bf[ni][0], bf[ni][1]);
            }
            if (kc + 1 < 6)
#pragma unroll
                for (int i = 0; i < 6; i++)
                    *(uint2*)(smB2 + ((kc + 1) & 1) * 7680 + stsO + 1280 * i) = rb[i];
            __syncthreads();
        }

        // stage to St fp32
#pragma unroll
        for (int m2 = 0; m2 < 2; m2++)
#pragma unroll
            for (int ni = 0; ni < 6; ni++) {
                int row = wr + 16 * m2 + g;
                int col = wc + 8 * ni + 2 * tg;
                St[row * 200 + col]           = acc[m2][ni][0];
                St[row * 200 + col + 1]       = acc[m2][ni][1];
                St[(row + 8) * 200 + col]     = acc[m2][ni][2];
                St[(row + 8) * 200 + col + 1] = acc[m2][ni][3];
            }
    }
    __syncthreads();

    // ---------- LN1 + shortcut -> x1h into smA (fc1 A-layout) ----------
    int wp = tid >> 5, l = tid & 31;
#pragma unroll 1
    for (int rr = 0; rr < 8; rr++) {
        int n = wp * 8 + rr;
        int hpx = (wh * 8 + (n >> 3) + 4) & 255;
        int wpx = (ww * 8 + (n & 7) + 4) & 255;
        size_t row = ((size_t)bI * HWd + hpx * Wdim + wpx) * Cd;
        float vv[6]; float su = 0.f;
#pragma unroll
        for (int u = 0; u < 6; u++) {
            int c = l + 32 * u;
            vv[u] = St[n * 200 + c] + g_bc[c];
            su += vv[u];
        }
        su = warp_sum(su);
        float mean = su * (1.f / 192.f);
        float sq = 0.f;
#pragma unroll
        for (int u = 0; u < 6; u++) { float d = vv[u] - mean; sq += d * d; }
        sq = warp_sum(sq);
        float rstd = rsqrtf(sq * (1.f / 192.f) + 1e-5f);
#pragma unroll
        for (int u = 0; u < 6; u++) {
            int c = l + 32 * u;
            float y = (vv[u] - mean) * rstd * n1g[c] + n1b[c] + g_xt[row + c];
            smA[u * 2560 + n * 40 + l] = __float2half_rn(y);
        }
    }
    __syncthreads();

    // ---------- MLP: fc1 + GELU + fc2 (A = x1h in smA) ----------
    float acc2[2][6][4];
#pragma unroll
    for (int a = 0; a < 2; a++)
#pragma unroll
        for (int b_ = 0; b_ < 6; b_++)
#pragma unroll
            for (int cc = 0; cc < 4; cc++) acc2[a][b_][cc] = 0.f;

#pragma unroll 1
    for (int oc = 0; oc < 8; oc++) {
        const __half* W1 = w_f1h + (size_t)(oc * 96) * 192;
        uint2 rb1[3];
#pragma unroll
        for (int i = 0; i < 3; i++)
            rb1[i] = *(const uint2*)(W1 + (size_t)(r0 + 32 * i) * 192 + c4);
#pragma unroll
        for (int i = 0; i < 3; i++)
            *(uint2*)(smB1m + stsO + 1280 * i) = rb1[i];
        __syncthreads();

        float acc1[2][3][4];
#pragma unroll
        for (int a = 0; a < 2; a++)
#pragma unroll
            for (int b_ = 0; b_ < 3; b_++)
#pragma unroll
                for (int cc = 0; cc < 4; cc++) acc1[a][b_][cc] = 0.f;

#pragma unroll 1
        for (int kc = 0; kc < 6; kc++) {
            if (kc + 1 < 6)
#pragma unroll
                for (int i = 0; i < 3; i++)
                    rb1[i] = *(const uint2*)(W1 + (size_t)(r0 + 32 * i) * 192 + (kc + 1) * 32 + c4);
            const __half* Ab = smA + kc * 2560;
            const __half* Bb = smB1m + (kc & 1) * 3840;
#pragma unroll
            for (int kk = 0; kk < 32; kk += 16) {
                unsigned af[2][4], bf[3][2];
#pragma unroll
                for (int m2 = 0; m2 < 2; m2++) {
                    const __half* Ar = Ab + (wr + 16 * m2 + g) * 40 + kk + 2 * tg;
                    af[m2][0] = ldu(Ar);       af[m2][1] = ldu(Ar + 320);
                    af[m2][2] = ldu(Ar + 8);   af[m2][3] = ldu(Ar + 328);
                }
#pragma unroll
                for (int ni = 0; ni < 3; ni++) {
                    const __half* Br = Bb + (wc1 + 8 * ni + g) * 40 + kk + 2 * tg;
                    bf[ni][0] = ldu(Br);  bf[ni][1] = ldu(Br + 8);
                }
#pragma unroll
                for (int m2 = 0; m2 < 2; m2++)
#pragma unroll
                    for (int ni = 0; ni < 3; ni++)
                        mma16(acc1[m2][ni], af[m2], bf[ni][0], bf[ni][1]);
            }
            if (kc + 1 < 6)
#pragma unroll
                for (int i = 0; i < 3; i++)
                    *(uint2*)(smB1m + ((kc + 1) & 1) * 3840 + stsO + 1280 * i) = rb1[i];
            __syncthreads();
        }

#pragma unroll
        for (int m2 = 0; m2 < 2; m2++)
#pragma unroll
            for (int ni = 0; ni < 3; ni++) {
                int row = wr + 16 * m2 + g;
                int col = wc1 + 8 * ni + 2 * tg;
                float2 bv = *(const float2*)(b1h + oc * 96 + col);
                __half* hp0 = smHm + (col >> 5) * 2560 + row * 40 + (col & 31);
                *(__half2*)hp0 = __floats2half2_rn(
                    gelu_f(acc1[m2][ni][0] + bv.x), gelu_f(acc1[m2][ni][1] + bv.y));
                *(__half2*)(hp0 + 320) = __floats2half2_rn(
                    gelu_f(acc1[m2][ni][2] + bv.x), gelu_f(acc1[m2][ni][3] + bv.y));
            }

        const __half* W2 = w_f2h;
        uint2 rb2[6];
#pragma unroll
        for (int i = 0; i < 6; i++)
            rb2[i] = *(const uint2*)(W2 + (size_t)(r0 + 32 * i) * 768 + oc * 96 + c4);
#pragma unroll
        for (int i = 0; i < 6; i++)
            *(uint2*)(smB2m + stsO + 1280 * i) = rb2[i];
        __syncthreads();

#pragma unroll 1
        for (int kc = 0; kc < 3; kc++) {
            if (kc + 1 < 3)
#pragma unroll
                for (int i = 0; i < 6; i++)
                    rb2[i] = *(const uint2*)(W2 + (size_t)(r0 + 32 * i) * 768 + oc * 96 + (kc + 1) * 32 + c4);
            const __half* Ab = smHm + kc * 2560;
            const __half* Bb = smB2m + (kc & 1) * 7680;
#pragma unroll
            for (int kk = 0; kk < 32; kk += 16) {
                unsigned af[2][4], bf[6][2];
#pragma unroll
                for (int m2 = 0; m2 < 2; m2++) {
                    const __half* Ar = Ab + (wr + 16 * m2 + g) * 40 + kk + 2 * tg;
                    af[m2][0] = ldu(Ar);       af[m2][1] = ldu(Ar + 320);
                    af[m2][2] = ldu(Ar + 8);   af[m2][3] = ldu(Ar + 328);
                }
#pragma unroll
                for (int ni = 0; ni < 6; ni++) {
                    const __half* Br = Bb + (wc + 8 * ni + g) * 40 + kk + 2 * tg;
                    bf[ni][0] = ldu(Br);  bf[ni][1] = ldu(Br + 8);
                }
#pragma unroll
                for (int m2 = 0; m2 < 2; m2++)
#pragma unroll
                    for (int ni = 0; ni < 6; ni++)
                        mma16(acc2[m2][ni], af[m2], bf[ni][0], bf[ni][1]);
            }
            if (kc + 1 < 3)
#pragma unroll
                for (int i = 0; i < 6; i++)
                    *(uint2*)(smB2m + ((kc + 1) & 1) * 7680 + stsO + 1280 * i) = rb2[i];
            __syncthreads();
        }
    }

    // ---------- final: bias + LN2 + residual(x1h) + pixel scatter ----------
#pragma unroll
    for (int m2 = 0; m2 < 2; m2++)
#pragma unroll
        for (int ni = 0; ni < 6; ni++) {
            int row = wr + 16 * m2 + g;
            int col = wc + 8 * ni + 2 * tg;
            St[row * 200 + col]           = acc2[m2][ni][0];
            St[row * 200 + col + 1]       = acc2[m2][ni][1];
            St[(row + 8) * 200 + col]     = acc2[m2][ni][2];
            St[(row + 8) * 200 + col + 1] = acc2[m2][ni][3];
        }
    __syncthreads();
#pragma unroll 1
    for (int rr = 0; rr < 8; rr++) {
        int n = wp * 8 + rr;
        int hpx = (wh * 8 + (n >> 3) + 4) & 255;
        int wpx = (ww * 8 + (n & 7) + 4) & 255;
        size_t row = ((size_t)bI * HWd + hpx * Wdim + wpx) * Cd;
        float vv[6]; float su = 0.f;
#pragma unroll
        for (int u = 0; u < 6; u++) {
            int c = l + 32 * u;
            vv[u] = St[n * 200 + c] + b2[c];
            su += vv[u];
        }
        su = warp_sum(su);
        float mean = su * (1.f / 192.f);
        float sq = 0.f;
#pragma unroll
        for (int u = 0; u < 6; u++) { float d = vv[u] - mean; sq += d * d; }
        sq = warp_sum(sq);
        float rstd = rsqrtf(sq * (1.f / 192.f) + 1e-5f);
#pragma unroll
        for (int u = 0; u < 6; u++) {
            int c = l + 32 * u;
            float x1v = __half2float(smA[u * 2560 + n * 40 + l]);
            out[row + c] = x1v + (vv[u] - mean) * rstd * g2[c] + bb2[c];
        }
    }
}

// ======================= host =======================
extern "C" void kernel_launch(void* const* d_in, const int* in_sizes, int n_in,
                              void* d_out, int out_size)
{
    const float* x    = (const float*)d_in[0];
    const float* feat = (const float*)d_in[1];
    const int*   ridx = (const int*)  d_in[3];
    const float* rtab = (const float*)d_in[4];
    const float* q_w  = (const float*)d_in[5];
    const float* q_b  = (const float*)d_in[6];
    const float* kv_w = (const float*)d_in[7];
    const float* kv_b = (const float*)d_in[8];
    const float* p_w  = (const float*)d_in[9];
    const float* p_b  = (const float*)d_in[10];
    const float* m_w  = (const float*)d_in[11];
    const float* n1g  = (const float*)d_in[12];
    const float* n1b  = (const float*)d_in[13];
    const float* n2g  = (const float*)d_in[14];
    const float* n2b  = (const float*)d_in[15];
    const float* f1w  = (const float*)d_in[16];
    const float* f1b  = (const float*)d_in[17];
    const float* f2w  = (const float*)d_in[18];
    const float* f2b  = (const float*)d_in[19];
    float* out = (float*)d_out;

    __half *dwq, *dwkv, *dwf1, *dwf2;
    cudaGetSymbolAddress((void**)&dwq,  w_qh);
    cudaGetSymbolAddress((void**)&dwkv, w_kvh);
    cudaGetSymbolAddress((void**)&dwf1, w_f1h);
    cudaGetSymbolAddress((void**)&dwf2, w_f2h);

    const int smMega = 52224 * 2;                        // 104448
    cudaFuncSetAttribute(k_mega, cudaFuncAttributeMaxDynamicSharedMemorySize, smMega);

    k_f2h_s<<<144, 256>>>(q_w,  dwq,  36864, QSCALE);
    k_f2h  <<<288, 256>>>(kv_w, dwkv, 73728);
    k_wcomb<<<144, 256>>>(m_w, p_w, p_b);
    k_f2h  <<<576, 256>>>(f1w,  dwf1, 147456);
    k_f2h  <<<576, 256>>>(f2w,  dwf2, 147456);
    k_bias <<<96, 256>>>(ridx, rtab);
    k_transpose<<<dim3(6, 2048, 8), dim3(32, 8)>>>(x, feat);
    k_mega <<<NWINd, 256, smMega>>>(q_b, kv_b, n1g, n1b, f1b, f2b, n2g, n2b, out);
}

// round 9
// speedup vs baseline: 8.9659x; 1.0286x over previous
#include <cuda_runtime.h>
#include <cuda_fp16.h>
#include <math.h>
#include <stdint.h>

#define Hd    256
#define Wdim  256
#define HWd   65536
#define Cd    192
#define Bd    4
#define NHd   6
#define HDd   32
#define NWINd 4096
#define MTOKd 262144
#define HIDd  768
#define QSCALE 0.17677669529663687f

// -------- scratch --------
__device__ __half g_xth [(size_t)MTOKd * Cd];           // fp16 WINDOW-order (also the shortcut)
__device__ __half g_fth [(size_t)MTOKd * Cd];           // fp16 WINDOW-order
__device__ __half g_biash[NHd * 64 * 64];
__device__ __half w_qh [36864];
__device__ __half w_kvh[73728];
__device__ __half w_ch [36864];     // combined merge@proj weight
__device__ float  g_bc [192];       // combined bias m_w @ p_b
__device__ __half w_f1h[147456];
__device__ __half w_f2h[147456];

__device__ __forceinline__ float warp_sum(float v) {
#pragma unroll
    for (int o = 16; o; o >>= 1) v += __shfl_xor_sync(0xffffffffu, v, o);
    return v;
}
__device__ __forceinline__ unsigned h2u(__half2 h) {
    return *reinterpret_cast<unsigned*>(&h);
}
__device__ __forceinline__ unsigned ldu(const __half* p) {
    return *reinterpret_cast<const unsigned*>(p);
}
__device__ __forceinline__ float gelu_f(float v) {
    return 0.5f * v * (1.f + erff(v * 0.70710678118654752f));
}
__device__ __forceinline__ void mma16(float* c, const unsigned* a, unsigned b0, unsigned b1) {
    asm volatile(
        "mma.sync.aligned.m16n8k16.row.col.f32.f16.f16.f32 "
        "{%0,%1,%2,%3}, {%4,%5,%6,%7}, {%8,%9}, {%0,%1,%2,%3};"
        : "+f"(c[0]), "+f"(c[1]), "+f"(c[2]), "+f"(c[3])
        : "r"(a[0]), "r"(a[1]), "r"(a[2]), "r"(a[3]), "r"(b0), "r"(b1));
}

// ======================= prep kernels =======================
// merged weight conversion: q (scaled) | kv | f1 | f2
__global__ void k_prepw(const float* __restrict__ qw, const float* __restrict__ kvw,
                        const float* __restrict__ f1w, const float* __restrict__ f2w) {
    int i = blockIdx.x * 256 + threadIdx.x;
    if (i < 36864)        w_qh [i]          = __float2half_rn(qw[i] * QSCALE);
    else if (i < 110592)  w_kvh[i - 36864]  = __float2half_rn(kvw[i - 36864]);
    else if (i < 258048)  w_f1h[i - 110592] = __float2half_rn(f1w[i - 110592]);
    else if (i < 405504)  w_f2h[i - 258048] = __float2half_rn(f2w[i - 258048]);
}
__global__ void k_bias(const int* __restrict__ relidx, const float* __restrict__ table) {
    int idx = blockIdx.x * 256 + threadIdx.x;
    if (idx < NHd * 4096) {
        int h = idx >> 12, r = idx & 4095;
        g_biash[idx] = __float2half_rn(table[relidx[r] * NHd + h]);
    }
}
__global__ void k_wcomb(const float* __restrict__ mw, const float* __restrict__ pw,
                        const float* __restrict__ pb) {
    int e = blockIdx.x * 256 + threadIdx.x;
    if (e < 36864) {
        int i = e / 192, j = e - (e / 192) * 192;
        float acc = 0.f;
        for (int k = 0; k < 192; k++) acc += mw[i * 192 + k] * pw[k * 192 + j];
        w_ch[e] = __float2half_rn(acc);
    }
    if (e < 192) {
        float acc = 0.f;
        for (int k = 0; k < 192; k++) acc += mw[e * 192 + k] * pb[k];
        g_bc[e] = acc;
    }
}

// ======================= K0: transpose one tensor -> fp16 WINDOW order =======================
__global__ void k_transpose(const float* __restrict__ src0, __half* __restrict__ dst0) {
    __shared__ float t[32][33];
    int b  = blockIdx.z;
    int c0 = blockIdx.x << 5;
    int p0 = blockIdx.y << 5;
    const float* src = src0 + (size_t)b * Cd * HWd;
    int tx = threadIdx.x, ty = threadIdx.y;
#pragma unroll
    for (int i = ty; i < 32; i += 8)
        t[i][tx] = src[(size_t)(c0 + i) * HWd + p0 + tx];
    __syncthreads();
    int h  = p0 >> 8;
    int h2 = (h - 4) & 255;
    int whp = ((h2 >> 3) << 5);
    int nh8 = (h2 & 7) << 3;
    __half* dh = dst0 + (size_t)b * HWd * Cd;
#pragma unroll
    for (int i = ty; i < 32; i += 8) {
        int wv = ((p0 & 255) + i);
        int w2 = (wv - 4) & 255;
        int tok = ((whp + (w2 >> 3)) << 6) + nh8 + (w2 & 7);
        dh[(size_t)tok * Cd + c0 + tx] = __float2half_rn(t[tx][i]);
    }
}

// ======================= MEGA kernel: QKV + attn + proj·merge + LN1 + MLP + LN2 ====
// smem halves (52224 total = 104448 B):
//   phase A: smA [0,15360) | Kh [15360,30720) | Vt [30720,44544) | smB [44544,52224)
//   phase B (proj GEMM): Wc dbuf overlays Kh; St fp32 overlays halves [15360,40960)
//   phase C (MLP): smA = x1h | B1 dbuf [15360,23040) | H [23040,30720) | B2 dbuf [30720,46080)
//   final: St fp32 overlays [15360,40960)
__global__ void __launch_bounds__(256, 2) k_mega(
    const float* __restrict__ q_b, const float* __restrict__ kv_b,
    const float* __restrict__ n1g, const float* __restrict__ n1b,
    const float* __restrict__ b1h, const float* __restrict__ b2,
    const float* __restrict__ g2, const float* __restrict__ bb2,
    float* __restrict__ out)
{
    extern __shared__ float smf[];
    __half* smA = (__half*)smf;
    __half* Kh  = smA + 15360;
    __half* Vt  = smA + 30720;
    __half* smB = smA + 44544;
    __half* smB2 = Kh;                 // Wc GEMM double buffer (2x7680)
    float*  St  = smf + 7680;          // fp32 stage, halves [15360,40960)
    __half* smB1m = smA + 15360;       // MLP fc1 W dbuf (2x3840)
    __half* smHm  = smA + 23040;       // MLP h1 (3x2560)
    __half* smB2m = smA + 30720;       // MLP fc2 W dbuf (2x7680)
    int win = blockIdx.x;
    int tid = threadIdx.x;
    int lane = tid & 31, w = tid >> 5;
    int g = lane >> 2, tg = lane & 3;
    int mi = w & 3, hp = w >> 2;
    const int r0 = tid >> 3, c4 = 4 * (tid & 7);
    const int stsO = r0 * 40 + c4;
    const int wr = (w & 1) * 32, wc = (w >> 1) * 48;
    const int wc1 = (w >> 1) * 24;

    int bI = win >> 10, wh = (win >> 5) & 31, ww = win & 31;

    // ---------- load xw; stage Wq chunk 0 ----------
    const __half* xsrc = g_xth + (size_t)win * 64 * 192;
#pragma unroll
    for (int c = 0; c < 6; c++)
#pragma unroll
        for (int i = 0; i < 2; i++) {
            uint2 v = *(const uint2*)(xsrc + (size_t)(r0 + 32 * i) * 192 + c * 32 + c4);
            *(uint2*)(smA + c * 2560 + stsO + 1280 * i) = v;
        }
    uint2 rb[6];
#pragma unroll
    for (int i = 0; i < 6; i++)
        rb[i] = *(const uint2*)(w_qh + (size_t)(r0 + 32 * i) * 192 + c4);
#pragma unroll
    for (int i = 0; i < 6; i++) *(uint2*)(smB + stsO + 1280 * i) = rb[i];
    __syncthreads();

    // ---------- Q GEMM: rows 16mi..+16, heads {hp,2+hp,4+hp} ----------
    float qacc[3][4][4];
#pragma unroll
    for (int t = 0; t < 3; t++)
#pragma unroll
        for (int nq = 0; nq < 4; nq++)
#pragma unroll
            for (int e = 0; e < 4; e++) qacc[t][nq][e] = 0.f;
#pragma unroll 1
    for (int kc = 0; kc < 6; kc++) {
        if (kc + 1 < 6)
#pragma unroll
            for (int i = 0; i < 6; i++)
                rb[i] = *(const uint2*)(w_qh + (size_t)(r0 + 32 * i) * 192 + (kc + 1) * 32 + c4);
#pragma unroll
        for (int kk = 0; kk < 32; kk += 16) {
            unsigned af[4];
            const __half* Ar = smA + kc * 2560 + (16 * mi + g) * 40 + kk + 2 * tg;
            af[0] = ldu(Ar);      af[1] = ldu(Ar + 320);
            af[2] = ldu(Ar + 8);  af[3] = ldu(Ar + 328);
#pragma unroll
            for (int t = 0; t < 3; t++)
#pragma unroll
                for (int nq = 0; nq < 4; nq++) {
                    const __half* Br = smB + (32 * (2 * t + hp) + 8 * nq + g) * 40 + kk + 2 * tg;
                    mma16(qacc[t][nq], af, ldu(Br), ldu(Br + 8));
                }
        }
        __syncthreads();
        if (kc + 1 < 6) {
#pragma unroll
            for (int i = 0; i < 6; i++)
                *(uint2*)(smB + stsO + 1280 * i) = rb[i];
            __syncthreads();
        }
    }

    // ---------- repack Q: C-frag -> A-frag, + scaled bias ----------
    unsigned aq[3][2][4];
#pragma unroll
    for (int t = 0; t < 3; t++) {
        int h = 2 * t + hp;
#pragma unroll
        for (int ks = 0; ks < 2; ks++) {
            float2 b0 = *(const float2*)(q_b + 32 * h + 16 * ks + 2 * tg);
            float2 b1 = *(const float2*)(q_b + 32 * h + 16 * ks + 8 + 2 * tg);
            b0.x *= QSCALE; b0.y *= QSCALE; b1.x *= QSCALE; b1.y *= QSCALE;
            aq[t][ks][0] = h2u(__floats2half2_rn(qacc[t][2*ks][0] + b0.x, qacc[t][2*ks][1] + b0.y));
            aq[t][ks][1] = h2u(__floats2half2_rn(qacc[t][2*ks][2] + b0.x, qacc[t][2*ks][3] + b0.y));
            aq[t][ks][2] = h2u(__floats2half2_rn(qacc[t][2*ks+1][0] + b1.x, qacc[t][2*ks+1][1] + b1.y));
            aq[t][ks][3] = h2u(__floats2half2_rn(qacc[t][2*ks+1][2] + b1.x, qacc[t][2*ks+1][3] + b1.y));
        }
    }

    // ---------- load fw (overwrite smA); stage Wk chunk 0 ----------
    const __half* fsrc = g_fth + (size_t)win * 64 * 192;
#pragma unroll
    for (int c = 0; c < 6; c++)
#pragma unroll
        for (int i = 0; i < 2; i++) {
            uint2 v = *(const uint2*)(fsrc + (size_t)(r0 + 32 * i) * 192 + c * 32 + c4);
            *(uint2*)(smA + c * 2560 + stsO + 1280 * i) = v;
        }
#pragma unroll
    for (int i = 0; i < 6; i++)
        rb[i] = *(const uint2*)(w_kvh + (size_t)(r0 + 32 * i) * 192 + c4);
#pragma unroll
    for (int i = 0; i < 6; i++) *(uint2*)(smB + stsO + 1280 * i) = rb[i];
    __syncthreads();

    // ---------- K GEMM -> Kh, then V GEMM -> Vt ----------
#pragma unroll 1
    for (int kv = 0; kv < 2; kv++) {
        const __half* W = w_kvh + (size_t)kv * 36864;
        float acc[2][6][4];
#pragma unroll
        for (int a = 0; a < 2; a++)
#pragma unroll
            for (int b_ = 0; b_ < 6; b_++)
#pragma unroll
                for (int e = 0; e < 4; e++) acc[a][b_][e] = 0.f;
#pragma unroll 1
        for (int kc = 0; kc < 6; kc++) {
            if (kc + 1 < 6) {
#pragma unroll
                for (int i = 0; i < 6; i++)
                    rb[i] = *(const uint2*)(W + (size_t)(r0 + 32 * i) * 192 + (kc + 1) * 32 + c4);
            } else if (kv == 0) {
#pragma unroll
                for (int i = 0; i < 6; i++)
                    rb[i] = *(const uint2*)(w_kvh + 36864 + (size_t)(r0 + 32 * i) * 192 + c4);
            }
#pragma unroll
            for (int kk = 0; kk < 32; kk += 16) {
                unsigned af[2][4], bf[6][2];
#pragma unroll
                for (int m2 = 0; m2 < 2; m2++) {
                    const __half* Ar = smA + kc * 2560 + (wr + 16 * m2 + g) * 40 + kk + 2 * tg;
                    af[m2][0] = ldu(Ar);      af[m2][1] = ldu(Ar + 320);
                    af[m2][2] = ldu(Ar + 8);  af[m2][3] = ldu(Ar + 328);
                }
#pragma unroll
                for (int ni = 0; ni < 6; ni++) {
                    const __half* Br = smB + (wc + 8 * ni + g) * 40 + kk + 2 * tg;
                    bf[ni][0] = ldu(Br);  bf[ni][1] = ldu(Br + 8);
                }
#pragma unroll
                for (int m2 = 0; m2 < 2; m2++)
#pragma unroll
                    for (int ni = 0; ni < 6; ni++)
                        mma16(acc[m2][ni], af[m2], bf[ni][0], bf[ni][1]);
            }
            __syncthreads();
            if (kc + 1 < 6 || kv == 0) {
#pragma unroll
                for (int i = 0; i < 6; i++)
                    *(uint2*)(smB + stsO + 1280 * i) = rb[i];
                __syncthreads();
            }
        }
#pragma unroll
        for (int m2 = 0; m2 < 2; m2++)
#pragma unroll
            for (int ni = 0; ni < 6; ni++) {
                int c = wc + 8 * ni + 2 * tg;
                int h = c >> 5, d = c & 31;
                float2 bv = *(const float2*)(kv_b + kv * 192 + c);
                int row = wr + 16 * m2 + g;
                if (kv == 0) {
                    *(__half2*)(Kh + h * 2560 + row * 40 + d) =
                        __floats2half2_rn(acc[m2][ni][0] + bv.x, acc[m2][ni][1] + bv.y);
                    *(__half2*)(Kh + h * 2560 + (row + 8) * 40 + d) =
                        __floats2half2_rn(acc[m2][ni][2] + bv.x, acc[m2][ni][3] + bv.y);
                } else {
                    __half* vb = Vt + h * 2304 + d * 72;
                    vb[row]          = __float2half_rn(acc[m2][ni][0] + bv.x);
                    vb[72 + row]     = __float2half_rn(acc[m2][ni][1] + bv.y);
                    vb[row + 8]      = __float2half_rn(acc[m2][ni][2] + bv.x);
                    vb[72 + row + 8] = __float2half_rn(acc[m2][ni][3] + bv.y);
                }
            }
    }
    __syncthreads();

    // ---------- attention ----------
    int i0 = 16 * mi + g;
    int w10 = win & 1023;
    bool eh = ((w10 >> 5) == 31), ew = ((w10 & 31) == 31);
    bool edge = eh || ew;
    int ri0 = 0, ri1 = 0, rj0a[8], rj1a[8];
    if (edge) {
        auto region = [&](int n) {
            int a = eh ? (((n >> 3) >= 4) ? 2 : 1) : 0;
            int b = ew ? (((n & 7)  >= 4) ? 2 : 1) : 0;
            return a * 3 + b;
        };
        ri0 = region(i0); ri1 = region(i0 + 8);
#pragma unroll
        for (int ni = 0; ni < 8; ni++) {
            int j0 = 8 * ni + 2 * tg;
            rj0a[ni] = region(j0);
            rj1a[ni] = region(j0 + 1);
        }
    }

#pragma unroll 1
    for (int t = 0; t < 3; t++) {
        int h = 2 * t + hp;
        float s[8][4];
#pragma unroll
        for (int ni = 0; ni < 8; ni++)
#pragma unroll
            for (int e = 0; e < 4; e++) s[ni][e] = 0.f;
        const __half* Kb = Kh + h * 2560 + g * 40 + 2 * tg;
#pragma unroll
        for (int ni = 0; ni < 8; ni++) {
            mma16(s[ni], aq[t][0], ldu(Kb + ni * 320),      ldu(Kb + ni * 320 + 8));
            mma16(s[ni], aq[t][1], ldu(Kb + ni * 320 + 16), ldu(Kb + ni * 320 + 24));
        }
        const __half* bb0 = g_biash + (h * 64 + i0) * 64;
#pragma unroll
        for (int ni = 0; ni < 8; ni++) {
            int j0 = 8 * ni + 2 * tg;
            float2 f0 = __half22float2(*(const __half2*)(bb0 + j0));
            float2 f1 = __half22float2(*(const __half2*)(bb0 + 512 + j0));
            s[ni][0] += f0.x; s[ni][1] += f0.y;
            s[ni][2] += f1.x; s[ni][3] += f1.y;
        }
        if (edge) {
#pragma unroll
            for (int ni = 0; ni < 8; ni++) {
                if (rj0a[ni] != ri0) s[ni][0] -= 100.f;
                if (rj1a[ni] != ri0) s[ni][1] -= 100.f;
                if (rj0a[ni] != ri1) s[ni][2] -= 100.f;
                if (rj1a[ni] != ri1) s[ni][3] -= 100.f;
            }
        }
        float m0 = -1e30f, m1 = -1e30f;
#pragma unroll
        for (int ni = 0; ni < 8; ni++) {
            m0 = fmaxf(m0, fmaxf(s[ni][0], s[ni][1]));
            m1 = fmaxf(m1, fmaxf(s[ni][2], s[ni][3]));
        }
        m0 = fmaxf(m0, __shfl_xor_sync(0xffffffffu, m0, 1));
        m0 = fmaxf(m0, __shfl_xor_sync(0xffffffffu, m0, 2));
        m1 = fmaxf(m1, __shfl_xor_sync(0xffffffffu, m1, 1));
        m1 = fmaxf(m1, __shfl_xor_sync(0xffffffffu, m1, 2));
        float s0 = 0.f, s1 = 0.f;
#pragma unroll
        for (int ni = 0; ni < 8; ni++) {
            s[ni][0] = __expf(s[ni][0] - m0); s0 += s[ni][0];
            s[ni][1] = __expf(s[ni][1] - m0); s0 += s[ni][1];
            s[ni][2] = __expf(s[ni][2] - m1); s1 += s[ni][2];
            s[ni][3] = __expf(s[ni][3] - m1); s1 += s[ni][3];
        }
        s0 += __shfl_xor_sync(0xffffffffu, s0, 1);
        s0 += __shfl_xor_sync(0xffffffffu, s0, 2);
        s1 += __shfl_xor_sync(0xffffffffu, s1, 1);
        s1 += __shfl_xor_sync(0xffffffffu, s1, 2);
        float inv0 = 1.f / s0, inv1 = 1.f / s1;
        unsigned pv[4][4];
#pragma unroll
        for (int js = 0; js < 4; js++) {
            pv[js][0] = h2u(__floats2half2_rn(s[2*js][0]   * inv0, s[2*js][1]   * inv0));
            pv[js][1] = h2u(__floats2half2_rn(s[2*js][2]   * inv1, s[2*js][3]   * inv1));
            pv[js][2] = h2u(__floats2half2_rn(s[2*js+1][0] * inv0, s[2*js+1][1] * inv0));
            pv[js][3] = h2u(__floats2half2_rn(s[2*js+1][2] * inv1, s[2*js+1][3] * inv1));
        }
        float o[4][4];
#pragma unroll
        for (int nd = 0; nd < 4; nd++)
#pragma unroll
            for (int e = 0; e < 4; e++) o[nd][e] = 0.f;
        const __half* Vb = Vt + h * 2304 + g * 72 + 2 * tg;
#pragma unroll
        for (int nd = 0; nd < 4; nd++)
#pragma unroll
            for (int js = 0; js < 4; js++)
                mma16(o[nd], pv[js], ldu(Vb + nd * 576 + 16 * js),
                                     ldu(Vb + nd * 576 + 16 * js + 8));
#pragma unroll
        for (int nd = 0; nd < 4; nd++) {
            int d0 = 8 * nd + 2 * tg;
            *(__half2*)(smA + h * 2560 + i0 * 40 + d0) =
                __floats2half2_rn(o[nd][0], o[nd][1]);
            *(__half2*)(smA + h * 2560 + (i0 + 8) * 40 + d0) =
                __floats2half2_rn(o[nd][2], o[nd][3]);
        }
    }

    // ---------- fused proj+merge GEMM: 64x192 = smA @ Wc^T ----------
#pragma unroll
    for (int i = 0; i < 6; i++)
        rb[i] = *(const uint2*)(w_ch + (size_t)(r0 + 32 * i) * 192 + c4);
    __syncthreads();
#pragma unroll
    for (int i = 0; i < 6; i++)
        *(uint2*)(smB2 + stsO + 1280 * i) = rb[i];
    __syncthreads();

    {
        float acc[2][6][4];
#pragma unroll
        for (int a = 0; a < 2; a++)
#pragma unroll
            for (int b_ = 0; b_ < 6; b_++)
#pragma unroll
                for (int e = 0; e < 4; e++) acc[a][b_][e] = 0.f;

#pragma unroll 1
        for (int kc = 0; kc < 6; kc++) {
            if (kc + 1 < 6)
#pragma unroll
                for (int i = 0; i < 6; i++)
                    rb[i] = *(const uint2*)(w_ch + (size_t)(r0 + 32 * i) * 192 + (kc + 1) * 32 + c4);
            const __half* Ab = smA + kc * 2560;
            const __half* Bb = smB2 + (kc & 1) * 7680;
#pragma unroll
            for (int kk = 0; kk < 32; kk += 16) {
                unsigned af[2][4], bf[6][2];
#pragma unroll
                for (int m2 = 0; m2 < 2; m2++) {
                    const __half* Ar = Ab + (wr + 16 * m2 + g) * 40 + kk + 2 * tg;
                    af[m2][0] = ldu(Ar);      af[m2][1] = ldu(Ar + 320);
                    af[m2][2] = ldu(Ar + 8);  af[m2][3] = ldu(Ar + 328);
                }
#pragma unroll
                for (int ni = 0; ni < 6; ni++) {
                    const __half* Br = Bb + (wc + 8 * ni + g) * 40 + kk + 2 * tg;
                    bf[ni][0] = ldu(Br);  bf[ni][1] = ldu(Br + 8);
                }
#pragma unroll
                for (int m2 = 0; m2 < 2; m2++)
#pragma unroll
                    for (int ni = 0; ni < 6; ni++)
                        mma16(acc[m2][ni], af[m2], bf[ni][0], bf[ni][1]);
            }
            if (kc + 1 < 6)
#pragma unroll
                for (int i = 0; i < 6; i++)
                    *(uint2*)(smB2 + ((kc + 1) & 1) * 7680 + stsO + 1280 * i) = rb[i];
            __syncthreads();
        }

#pragma unroll
        for (int m2 = 0; m2 < 2; m2++)
#pragma unroll
            for (int ni = 0; ni < 6; ni++) {
                int row = wr + 16 * m2 + g;
                int col = wc + 8 * ni + 2 * tg;
                St[row * 200 + col]           = acc[m2][ni][0];
                St[row * 200 + col + 1]       = acc[m2][ni][1];
                St[(row + 8) * 200 + col]     = acc[m2][ni][2];
                St[(row + 8) * 200 + col + 1] = acc[m2][ni][3];
            }
    }
    __syncthreads();

    // ---------- LN1 + shortcut(from g_xth) -> x1h into smA (fc1 A-layout) ----------
    int wp = tid >> 5, l = tid & 31;
#pragma unroll 1
    for (int rr = 0; rr < 8; rr++) {
        int n = wp * 8 + rr;
        float vv[6]; float su = 0.f;
#pragma unroll
        for (int u = 0; u < 6; u++) {
            int c = l + 32 * u;
            vv[u] = St[n * 200 + c] + g_bc[c];
            su += vv[u];
        }
        su = warp_sum(su);
        float mean = su * (1.f / 192.f);
        float sq = 0.f;
#pragma unroll
        for (int u = 0; u < 6; u++) { float d = vv[u] - mean; sq += d * d; }
        sq = warp_sum(sq);
        float rstd = rsqrtf(sq * (1.f / 192.f) + 1e-5f);
#pragma unroll
        for (int u = 0; u < 6; u++) {
            int c = l + 32 * u;
            float y = (vv[u] - mean) * rstd * n1g[c] + n1b[c]
                      + __half2float(xsrc[(size_t)n * 192 + c]);
            smA[u * 2560 + n * 40 + l] = __float2half_rn(y);
        }
    }
    __syncthreads();

    // ---------- MLP: fc1 + GELU + fc2 (A = x1h in smA) ----------
    float acc2[2][6][4];
#pragma unroll
    for (int a = 0; a < 2; a++)
#pragma unroll
        for (int b_ = 0; b_ < 6; b_++)
#pragma unroll
            for (int cc = 0; cc < 4; cc++) acc2[a][b_][cc] = 0.f;

#pragma unroll 1
    for (int oc = 0; oc < 8; oc++) {
        const __half* W1 = w_f1h + (size_t)(oc * 96) * 192;
        uint2 rb1[3];
#pragma unroll
        for (int i = 0; i < 3; i++)
            rb1[i] = *(const uint2*)(W1 + (size_t)(r0 + 32 * i) * 192 + c4);
#pragma unroll
        for (int i = 0; i < 3; i++)
            *(uint2*)(smB1m + stsO + 1280 * i) = rb1[i];
        __syncthreads();

        float acc1[2][3][4];
#pragma unroll
        for (int a = 0; a < 2; a++)
#pragma unroll
            for (int b_ = 0; b_ < 3; b_++)
#pragma unroll
                for (int cc = 0; cc < 4; cc++) acc1[a][b_][cc] = 0.f;

#pragma unroll 1
        for (int kc = 0; kc < 6; kc++) {
            if (kc + 1 < 6)
#pragma unroll
                for (int i = 0; i < 3; i++)
                    rb1[i] = *(const uint2*)(W1 + (size_t)(r0 + 32 * i) * 192 + (kc + 1) * 32 + c4);
            const __half* Ab = smA + kc * 2560;
            const __half* Bb = smB1m + (kc & 1) * 3840;
#pragma unroll
            for (int kk = 0; kk < 32; kk += 16) {
                unsigned af[2][4], bf[3][2];
#pragma unroll
                for (int m2 = 0; m2 < 2; m2++) {
                    const __half* Ar = Ab + (wr + 16 * m2 + g) * 40 + kk + 2 * tg;
                    af[m2][0] = ldu(Ar);       af[m2][1] = ldu(Ar + 320);
                    af[m2][2] = ldu(Ar + 8);   af[m2][3] = ldu(Ar + 328);
                }
#pragma unroll
                for (int ni = 0; ni < 3; ni++) {
                    const __half* Br = Bb + (wc1 + 8 * ni + g) * 40 + kk + 2 * tg;
                    bf[ni][0] = ldu(Br);  bf[ni][1] = ldu(Br + 8);
                }
#pragma unroll
                for (int m2 = 0; m2 < 2; m2++)
#pragma unroll
                    for (int ni = 0; ni < 3; ni++)
                        mma16(acc1[m2][ni], af[m2], bf[ni][0], bf[ni][1]);
            }
            if (kc + 1 < 6)
#pragma unroll
                for (int i = 0; i < 3; i++)
                    *(uint2*)(smB1m + ((kc + 1) & 1) * 3840 + stsO + 1280 * i) = rb1[i];
            __syncthreads();
        }

#pragma unroll
        for (int m2 = 0; m2 < 2; m2++)
#pragma unroll
            for (int ni = 0; ni < 3; ni++) {
                int row = wr + 16 * m2 + g;
                int col = wc1 + 8 * ni + 2 * tg;
                float2 bv = *(const float2*)(b1h + oc * 96 + col);
                __half* hp0 = smHm + (col >> 5) * 2560 + row * 40 + (col & 31);
                *(__half2*)hp0 = __floats2half2_rn(
                    gelu_f(acc1[m2][ni][0] + bv.x), gelu_f(acc1[m2][ni][1] + bv.y));
                *(__half2*)(hp0 + 320) = __floats2half2_rn(
                    gelu_f(acc1[m2][ni][2] + bv.x), gelu_f(acc1[m2][ni][3] + bv.y));
            }

        const __half* W2 = w_f2h;
        uint2 rb2[6];
#pragma unroll
        for (int i = 0; i < 6; i++)
            rb2[i] = *(const uint2*)(W2 + (size_t)(r0 + 32 * i) * 768 + oc * 96 + c4);
#pragma unroll
        for (int i = 0; i < 6; i++)
            *(uint2*)(smB2m + stsO + 1280 * i) = rb2[i];
        __syncthreads();

#pragma unroll 1
        for (int kc = 0; kc < 3; kc++) {
            if (kc + 1 < 3)
#pragma unroll
                for (int i = 0; i < 6; i++)
                    rb2[i] = *(const uint2*)(W2 + (size_t)(r0 + 32 * i) * 768 + oc * 96 + (kc + 1) * 32 + c4);
            const __half* Ab = smHm + kc * 2560;
            const __half* Bb = smB2m + (kc & 1) * 7680;
#pragma unroll
            for (int kk = 0; kk < 32; kk += 16) {
                unsigned af[2][4], bf[6][2];
#pragma unroll
                for (int m2 = 0; m2 < 2; m2++) {
                    const __half* Ar = Ab + (wr + 16 * m2 + g) * 40 + kk + 2 * tg;
                    af[m2][0] = ldu(Ar);       af[m2][1] = ldu(Ar + 320);
                    af[m2][2] = ldu(Ar + 8);   af[m2][3] = ldu(Ar + 328);
                }
#pragma unroll
                for (int ni = 0; ni < 6; ni++) {
                    const __half* Br = Bb + (wc + 8 * ni + g) * 40 + kk + 2 * tg;
                    bf[ni][0] = ldu(Br);  bf[ni][1] = ldu(Br + 8);
                }
#pragma unroll
                for (int m2 = 0; m2 < 2; m2++)
#pragma unroll
                    for (int ni = 0; ni < 6; ni++)
                        mma16(acc2[m2][ni], af[m2], bf[ni][0], bf[ni][1]);
            }
            if (kc + 1 < 3)
#pragma unroll
                for (int i = 0; i < 6; i++)
                    *(uint2*)(smB2m + ((kc + 1) & 1) * 7680 + stsO + 1280 * i) = rb2[i];
            __syncthreads();
        }
    }

    // ---------- final: bias + LN2 + residual(x1h) + pixel scatter ----------
#pragma unroll
    for (int m2 = 0; m2 < 2; m2++)
#pragma unroll
        for (int ni = 0; ni < 6; ni++) {
            int row = wr + 16 * m2 + g;
            int col = wc + 8 * ni + 2 * tg;
            St[row * 200 + col]           = acc2[m2][ni][0];
            St[row * 200 + col + 1]       = acc2[m2][ni][1];
            St[(row + 8) * 200 + col]     = acc2[m2][ni][2];
            St[(row + 8) * 200 + col + 1] = acc2[m2][ni][3];
        }
    __syncthreads();
#pragma unroll 1
    for (int rr = 0; rr < 8; rr++) {
        int n = wp * 8 + rr;
        int hpx = (wh * 8 + (n >> 3) + 4) & 255;
        int wpx = (ww * 8 + (n & 7) + 4) & 255;
        size_t row = ((size_t)bI * HWd + hpx * Wdim + wpx) * Cd;
        float vv[6]; float su = 0.f;
#pragma unroll
        for (int u = 0; u < 6; u++) {
            int c = l + 32 * u;
            vv[u] = St[n * 200 + c] + b2[c];
            su += vv[u];
        }
        su = warp_sum(su);
        float mean = su * (1.f / 192.f);
        float sq = 0.f;
#pragma unroll
        for (int u = 0; u < 6; u++) { float d = vv[u] - mean; sq += d * d; }
        sq = warp_sum(sq);
        float rstd = rsqrtf(sq * (1.f / 192.f) + 1e-5f);
#pragma unroll
        for (int u = 0; u < 6; u++) {
            int c = l + 32 * u;
            float x1v = __half2float(smA[u * 2560 + n * 40 + l]);
            out[row + c] = x1v + (vv[u] - mean) * rstd * g2[c] + bb2[c];
        }
    }
}

// ======================= host =======================
extern "C" void kernel_launch(void* const* d_in, const int* in_sizes, int n_in,
                              void* d_out, int out_size)
{
    const float* x    = (const float*)d_in[0];
    const float* feat = (const float*)d_in[1];
    const int*   ridx = (const int*)  d_in[3];
    const float* rtab = (const float*)d_in[4];
    const float* q_w  = (const float*)d_in[5];
    const float* q_b  = (const float*)d_in[6];
    const float* kv_w = (const float*)d_in[7];
    const float* kv_b = (const float*)d_in[8];
    const float* p_w  = (const float*)d_in[9];
    const float* p_b  = (const float*)d_in[10];
    const float* m_w  = (const float*)d_in[11];
    const float* n1g  = (const float*)d_in[12];
    const float* n1b  = (const float*)d_in[13];
    const float* n2g  = (const float*)d_in[14];
    const float* n2b  = (const float*)d_in[15];
    const float* f1w  = (const float*)d_in[16];
    const float* f1b  = (const float*)d_in[17];
    const float* f2w  = (const float*)d_in[18];
    const float* f2b  = (const float*)d_in[19];
    float* out = (float*)d_out;

    __half *dxth, *dfth;
    cudaGetSymbolAddress((void**)&dxth, g_xth);
    cudaGetSymbolAddress((void**)&dfth, g_fth);

    const int smMega = 52224 * 2;                        // 104448
    cudaFuncSetAttribute(k_mega, cudaFuncAttributeMaxDynamicSharedMemorySize, smMega);

    // launch order arranged so k_mega is launch index 5 (ncu -s 5 -c 1)
    k_prepw<<<1584, 256>>>(q_w, kv_w, f1w, f2w);                      // 0
    k_wcomb<<<144, 256>>>(m_w, p_w, p_b);                             // 1
    k_bias <<<96, 256>>>(ridx, rtab);                                 // 2
    k_transpose<<<dim3(6, 2048, 4), dim3(32, 8)>>>(x, dxth);          // 3
    k_transpose<<<dim3(6, 2048, 4), dim3(32, 8)>>>(feat, dfth);       // 4
    k_mega <<<NWINd, 256, smMega>>>(q_b, kv_b, n1g, n1b, f1b, f2b, n2g, n2b, out);  // 5
}

// round 10
// speedup vs baseline: 9.5138x; 1.0611x over previous
#include <cuda_runtime.h>
#include <cuda_fp16.h>
#include <math.h>
#include <stdint.h>

#define Hd    256
#define Wdim  256
#define HWd   65536
#define Cd    192
#define Bd    4
#define NHd   6
#define HDd   32
#define NWINd 4096
#define MTOKd 262144
#define HIDd  768
#define QSCALE 0.17677669529663687f

// -------- scratch --------
__device__ __half g_xth [(size_t)MTOKd * Cd];           // fp16 WINDOW-order (also the shortcut)
__device__ __half g_fth [(size_t)MTOKd * Cd];           // fp16 WINDOW-order
__device__ __half g_biash[NHd * 64 * 64];
__device__ __half w_qh [36864];
__device__ __half w_kvh[73728];
__device__ __half w_ch [36864];     // combined merge@proj weight
__device__ float  g_bc [192];       // combined bias m_w @ p_b
__device__ __half w_f1h[147456];
__device__ __half w_f2h[147456];

__device__ __forceinline__ float warp_sum(float v) {
#pragma unroll
    for (int o = 16; o; o >>= 1) v += __shfl_xor_sync(0xffffffffu, v, o);
    return v;
}
__device__ __forceinline__ unsigned h2u(__half2 h) {
    return *reinterpret_cast<unsigned*>(&h);
}
__device__ __forceinline__ float gelu_f(float v) {
    return 0.5f * v * (1.f + erff(v * 0.70710678118654752f));
}
__device__ __forceinline__ void mma16(float* c, const unsigned* a, unsigned b0, unsigned b1) {
    asm volatile(
        "mma.sync.aligned.m16n8k16.row.col.f32.f16.f16.f32 "
        "{%0,%1,%2,%3}, {%4,%5,%6,%7}, {%8,%9}, {%0,%1,%2,%3};"
        : "+f"(c[0]), "+f"(c[1]), "+f"(c[2]), "+f"(c[3])
        : "r"(a[0]), "r"(a[1]), "r"(a[2]), "r"(a[3]), "r"(b0), "r"(b1));
}
__device__ __forceinline__ void ldsm4(unsigned* r, const __half* p) {
    uint32_t a = (uint32_t)__cvta_generic_to_shared(p);
    asm volatile("ldmatrix.sync.aligned.m8n8.x4.shared.b16 {%0,%1,%2,%3}, [%4];"
                 : "=r"(r[0]), "=r"(r[1]), "=r"(r[2]), "=r"(r[3]) : "r"(a));
}
__device__ __forceinline__ void ldsm2(unsigned* r, const __half* p) {
    uint32_t a = (uint32_t)__cvta_generic_to_shared(p);
    asm volatile("ldmatrix.sync.aligned.m8n8.x2.shared.b16 {%0,%1}, [%2];"
                 : "=r"(r[0]), "=r"(r[1]) : "r"(a));
}

// ======================= prep kernels =======================
__global__ void k_prepw(const float* __restrict__ qw, const float* __restrict__ kvw,
                        const float* __restrict__ f1w, const float* __restrict__ f2w) {
    int i = blockIdx.x * 256 + threadIdx.x;
    if (i < 36864)        w_qh [i]          = __float2half_rn(qw[i] * QSCALE);
    else if (i < 110592)  w_kvh[i - 36864]  = __float2half_rn(kvw[i - 36864]);
    else if (i < 258048)  w_f1h[i - 110592] = __float2half_rn(f1w[i - 110592]);
    else if (i < 405504)  w_f2h[i - 258048] = __float2half_rn(f2w[i - 258048]);
}
__global__ void k_bias(const int* __restrict__ relidx, const float* __restrict__ table) {
    int idx = blockIdx.x * 256 + threadIdx.x;
    if (idx < NHd * 4096) {
        int h = idx >> 12, r = idx & 4095;
        g_biash[idx] = __float2half_rn(table[relidx[r] * NHd + h]);
    }
}
__global__ void k_wcomb(const float* __restrict__ mw, const float* __restrict__ pw,
                        const float* __restrict__ pb) {
    int e = blockIdx.x * 256 + threadIdx.x;
    if (e < 36864) {
        int i = e / 192, j = e - (e / 192) * 192;
        float acc = 0.f;
        for (int k = 0; k < 192; k++) acc += mw[i * 192 + k] * pw[k * 192 + j];
        w_ch[e] = __float2half_rn(acc);
    }
    if (e < 192) {
        float acc = 0.f;
        for (int k = 0; k < 192; k++) acc += mw[e * 192 + k] * pb[k];
        g_bc[e] = acc;
    }
}

// ======================= K0: transpose one tensor -> fp16 WINDOW order =======================
__global__ void k_transpose(const float* __restrict__ src0, __half* __restrict__ dst0) {
    __shared__ float t[32][33];
    int b  = blockIdx.z;
    int c0 = blockIdx.x << 5;
    int p0 = blockIdx.y << 5;
    const float* src = src0 + (size_t)b * Cd * HWd;
    int tx = threadIdx.x, ty = threadIdx.y;
#pragma unroll
    for (int i = ty; i < 32; i += 8)
        t[i][tx] = src[(size_t)(c0 + i) * HWd + p0 + tx];
    __syncthreads();
    int h  = p0 >> 8;
    int h2 = (h - 4) & 255;
    int whp = ((h2 >> 3) << 5);
    int nh8 = (h2 & 7) << 3;
    __half* dh = dst0 + (size_t)b * HWd * Cd;
#pragma unroll
    for (int i = ty; i < 32; i += 8) {
        int wv = ((p0 & 255) + i);
        int w2 = (wv - 4) & 255;
        int tok = ((whp + (w2 >> 3)) << 6) + nh8 + (w2 & 7);
        dh[(size_t)tok * Cd + c0 + tx] = __float2half_rn(t[tx][i]);
    }
}

// ======================= MEGA kernel =======================
// smem halves (52224 total = 104448 B):
//   phase A: smA [0,15360) | Kh [15360,30720) | Vt [30720,44544) | smB [44544,52224)
//   phase B (proj GEMM): Wc dbuf overlays Kh; St fp32 overlays halves [15360,40960)
//   phase C (MLP): smA = x1h | B1 dbuf [15360,23040) | H [23040,30720) | B2 dbuf [30720,46080)
__global__ void __launch_bounds__(256, 2) k_mega(
    const float* __restrict__ q_b, const float* __restrict__ kv_b,
    const float* __restrict__ n1g, const float* __restrict__ n1b,
    const float* __restrict__ b1h, const float* __restrict__ b2,
    const float* __restrict__ g2, const float* __restrict__ bb2,
    float* __restrict__ out)
{
    extern __shared__ float smf[];
    __half* smA = (__half*)smf;
    __half* Kh  = smA + 15360;
    __half* Vt  = smA + 30720;
    __half* smB = smA + 44544;
    __half* smB2 = Kh;
    float*  St  = smf + 7680;
    __half* smB1m = smA + 15360;
    __half* smHm  = smA + 23040;
    __half* smB2m = smA + 30720;
    int win = blockIdx.x;
    int tid = threadIdx.x;
    int lane = tid & 31, w = tid >> 5;
    int g = lane >> 2, tg = lane & 3;
    int mi = w & 3, hp = w >> 2;
    const int r0 = tid >> 3, c4 = 4 * (tid & 7);
    const int stsO = r0 * 40 + c4;
    const int wr = (w & 1) * 32, wc = (w >> 1) * 48;
    const int wc1 = (w >> 1) * 24;

    // ldmatrix per-lane offsets (halves)
    const int aoff  = (lane & 15) * 40 + (lane >> 4) * 8;                           // A/H, pitch 40
    const int boff  = ((lane & 7) + ((lane >> 4) & 1) * 8) * 40 + ((lane >> 3) & 1) * 8;  // B, pitch 40
    const int b2off = (lane & 7) * 40 + ((lane >> 3) & 1) * 8;                      // B x2, pitch 40
    const int voff  = ((lane & 7) + ((lane >> 4) & 1) * 8) * 72 + ((lane >> 3) & 1) * 8;  // V, pitch 72

    int bI = win >> 10, wh = (win >> 5) & 31, ww = win & 31;

    // ---------- load xw; stage Wq chunk 0 ----------
    const __half* xsrc = g_xth + (size_t)win * 64 * 192;
#pragma unroll
    for (int c = 0; c < 6; c++)
#pragma unroll
        for (int i = 0; i < 2; i++) {
            uint2 v = *(const uint2*)(xsrc + (size_t)(r0 + 32 * i) * 192 + c * 32 + c4);
            *(uint2*)(smA + c * 2560 + stsO + 1280 * i) = v;
        }
    uint2 rb[6];
#pragma unroll
    for (int i = 0; i < 6; i++)
        rb[i] = *(const uint2*)(w_qh + (size_t)(r0 + 32 * i) * 192 + c4);
#pragma unroll
    for (int i = 0; i < 6; i++) *(uint2*)(smB + stsO + 1280 * i) = rb[i];
    __syncthreads();

    // ---------- Q GEMM: rows 16mi..+16, heads {hp,2+hp,4+hp} ----------
    float qacc[3][4][4];
#pragma unroll
    for (int t = 0; t < 3; t++)
#pragma unroll
        for (int nq = 0; nq < 4; nq++)
#pragma unroll
            for (int e = 0; e < 4; e++) qacc[t][nq][e] = 0.f;
#pragma unroll 1
    for (int kc = 0; kc < 6; kc++) {
        if (kc + 1 < 6)
#pragma unroll
            for (int i = 0; i < 6; i++)
                rb[i] = *(const uint2*)(w_qh + (size_t)(r0 + 32 * i) * 192 + (kc + 1) * 32 + c4);
#pragma unroll
        for (int kk = 0; kk < 32; kk += 16) {
            unsigned af[4];
            ldsm4(af, smA + kc * 2560 + 16 * mi * 40 + kk + aoff);
#pragma unroll
            for (int t = 0; t < 3; t++) {
                unsigned bq0[4], bq1[4];
                ldsm4(bq0, smB + (32 * (2 * t + hp)) * 40 + kk + boff);
                ldsm4(bq1, smB + (32 * (2 * t + hp) + 16) * 40 + kk + boff);
                mma16(qacc[t][0], af, bq0[0], bq0[1]);
                mma16(qacc[t][1], af, bq0[2], bq0[3]);
                mma16(qacc[t][2], af, bq1[0], bq1[1]);
                mma16(qacc[t][3], af, bq1[2], bq1[3]);
            }
        }
        __syncthreads();
        if (kc + 1 < 6) {
#pragma unroll
            for (int i = 0; i < 6; i++)
                *(uint2*)(smB + stsO + 1280 * i) = rb[i];
            __syncthreads();
        }
    }

    // ---------- repack Q: C-frag -> A-frag, + scaled bias ----------
    unsigned aq[3][2][4];
#pragma unroll
    for (int t = 0; t < 3; t++) {
        int h = 2 * t + hp;
#pragma unroll
        for (int ks = 0; ks < 2; ks++) {
            float2 b0 = *(const float2*)(q_b + 32 * h + 16 * ks + 2 * tg);
            float2 b1 = *(const float2*)(q_b + 32 * h + 16 * ks + 8 + 2 * tg);
            b0.x *= QSCALE; b0.y *= QSCALE; b1.x *= QSCALE; b1.y *= QSCALE;
            aq[t][ks][0] = h2u(__floats2half2_rn(qacc[t][2*ks][0] + b0.x, qacc[t][2*ks][1] + b0.y));
            aq[t][ks][1] = h2u(__floats2half2_rn(qacc[t][2*ks][2] + b0.x, qacc[t][2*ks][3] + b0.y));
            aq[t][ks][2] = h2u(__floats2half2_rn(qacc[t][2*ks+1][0] + b1.x, qacc[t][2*ks+1][1] + b1.y));
            aq[t][ks][3] = h2u(__floats2half2_rn(qacc[t][2*ks+1][2] + b1.x, qacc[t][2*ks+1][3] + b1.y));
        }
    }

    // ---------- load fw (overwrite smA); stage Wk chunk 0 ----------
    const __half* fsrc = g_fth + (size_t)win * 64 * 192;
#pragma unroll
    for (int c = 0; c < 6; c++)
#pragma unroll
        for (int i = 0; i < 2; i++) {
            uint2 v = *(const uint2*)(fsrc + (size_t)(r0 + 32 * i) * 192 + c * 32 + c4);
            *(uint2*)(smA + c * 2560 + stsO + 1280 * i) = v;
        }
#pragma unroll
    for (int i = 0; i < 6; i++)
        rb[i] = *(const uint2*)(w_kvh + (size_t)(r0 + 32 * i) * 192 + c4);
#pragma unroll
    for (int i = 0; i < 6; i++) *(uint2*)(smB + stsO + 1280 * i) = rb[i];
    __syncthreads();

    // ---------- K GEMM -> Kh, then V GEMM -> Vt ----------
#pragma unroll 1
    for (int kv = 0; kv < 2; kv++) {
        const __half* W = w_kvh + (size_t)kv * 36864;
        float acc[2][6][4];
#pragma unroll
        for (int a = 0; a < 2; a++)
#pragma unroll
            for (int b_ = 0; b_ < 6; b_++)
#pragma unroll
                for (int e = 0; e < 4; e++) acc[a][b_][e] = 0.f;
#pragma unroll 1
        for (int kc = 0; kc < 6; kc++) {
            if (kc + 1 < 6) {
#pragma unroll
                for (int i = 0; i < 6; i++)
                    rb[i] = *(const uint2*)(W + (size_t)(r0 + 32 * i) * 192 + (kc + 1) * 32 + c4);
            } else if (kv == 0) {
#pragma unroll
                for (int i = 0; i < 6; i++)
                    rb[i] = *(const uint2*)(w_kvh + 36864 + (size_t)(r0 + 32 * i) * 192 + c4);
            }
#pragma unroll
            for (int kk = 0; kk < 32; kk += 16) {
                unsigned af[2][4], bb[3][4];
                ldsm4(af[0], smA + kc * 2560 + wr * 40 + kk + aoff);
                ldsm4(af[1], smA + kc * 2560 + (wr + 16) * 40 + kk + aoff);
#pragma unroll
                for (int p = 0; p < 3; p++)
                    ldsm4(bb[p], smB + (wc + 16 * p) * 40 + kk + boff);
#pragma unroll
                for (int m2 = 0; m2 < 2; m2++)
#pragma unroll
                    for (int ni = 0; ni < 6; ni++)
                        mma16(acc[m2][ni], af[m2], bb[ni >> 1][(ni & 1) * 2], bb[ni >> 1][(ni & 1) * 2 + 1]);
            }
            __syncthreads();
            if (kc + 1 < 6 || kv == 0) {
#pragma unroll
                for (int i = 0; i < 6; i++)
                    *(uint2*)(smB + stsO + 1280 * i) = rb[i];
                __syncthreads();
            }
        }
#pragma unroll
        for (int m2 = 0; m2 < 2; m2++)
#pragma unroll
            for (int ni = 0; ni < 6; ni++) {
                int c = wc + 8 * ni + 2 * tg;
                int h = c >> 5, d = c & 31;
                float2 bv = *(const float2*)(kv_b + kv * 192 + c);
                int row = wr + 16 * m2 + g;
                if (kv == 0) {
                    *(__half2*)(Kh + h * 2560 + row * 40 + d) =
                        __floats2half2_rn(acc[m2][ni][0] + bv.x, acc[m2][ni][1] + bv.y);
                    *(__half2*)(Kh + h * 2560 + (row + 8) * 40 + d) =
                        __floats2half2_rn(acc[m2][ni][2] + bv.x, acc[m2][ni][3] + bv.y);
                } else {
                    __half* vb = Vt + h * 2304 + d * 72;
                    vb[row]          = __float2half_rn(acc[m2][ni][0] + bv.x);
                    vb[72 + row]     = __float2half_rn(acc[m2][ni][1] + bv.y);
                    vb[row + 8]      = __float2half_rn(acc[m2][ni][2] + bv.x);
                    vb[72 + row + 8] = __float2half_rn(acc[m2][ni][3] + bv.y);
                }
            }
    }
    __syncthreads();

    // ---------- attention ----------
    int i0 = 16 * mi + g;
    int w10 = win & 1023;
    bool eh = ((w10 >> 5) == 31), ew = ((w10 & 31) == 31);
    bool edge = eh || ew;
    int ri0 = 0, ri1 = 0, rj0a[8], rj1a[8];
    if (edge) {
        auto region = [&](int n) {
            int a = eh ? (((n >> 3) >= 4) ? 2 : 1) : 0;
            int b = ew ? (((n & 7)  >= 4) ? 2 : 1) : 0;
            return a * 3 + b;
        };
        ri0 = region(i0); ri1 = region(i0 + 8);
#pragma unroll
        for (int ni = 0; ni < 8; ni++) {
            int j0 = 8 * ni + 2 * tg;
            rj0a[ni] = region(j0);
            rj1a[ni] = region(j0 + 1);
        }
    }

#pragma unroll 1
    for (int t = 0; t < 3; t++) {
        int h = 2 * t + hp;
        float s[8][4];
#pragma unroll
        for (int ni = 0; ni < 8; ni++)
#pragma unroll
            for (int e = 0; e < 4; e++) s[ni][e] = 0.f;
        const __half* Khh = Kh + h * 2560;
#pragma unroll
        for (int p = 0; p < 4; p++) {
            unsigned kb0[4], kb1[4];
            ldsm4(kb0, Khh + (16 * p) * 40 + boff);
            ldsm4(kb1, Khh + (16 * p) * 40 + 16 + boff);
            mma16(s[2*p],     aq[t][0], kb0[0], kb0[1]);
            mma16(s[2*p],     aq[t][1], kb1[0], kb1[1]);
            mma16(s[2*p + 1], aq[t][0], kb0[2], kb0[3]);
            mma16(s[2*p + 1], aq[t][1], kb1[2], kb1[3]);
        }
        const __half* bb0 = g_biash + (h * 64 + i0) * 64;
#pragma unroll
        for (int ni = 0; ni < 8; ni++) {
            int j0 = 8 * ni + 2 * tg;
            float2 f0 = __half22float2(*(const __half2*)(bb0 + j0));
            float2 f1 = __half22float2(*(const __half2*)(bb0 + 512 + j0));
            s[ni][0] += f0.x; s[ni][1] += f0.y;
            s[ni][2] += f1.x; s[ni][3] += f1.y;
        }
        if (edge) {
#pragma unroll
            for (int ni = 0; ni < 8; ni++) {
                if (rj0a[ni] != ri0) s[ni][0] -= 100.f;
                if (rj1a[ni] != ri0) s[ni][1] -= 100.f;
                if (rj0a[ni] != ri1) s[ni][2] -= 100.f;
                if (rj1a[ni] != ri1) s[ni][3] -= 100.f;
            }
        }
        float m0 = -1e30f, m1 = -1e30f;
#pragma unroll
        for (int ni = 0; ni < 8; ni++) {
            m0 = fmaxf(m0, fmaxf(s[ni][0], s[ni][1]));
            m1 = fmaxf(m1, fmaxf(s[ni][2], s[ni][3]));
        }
        m0 = fmaxf(m0, __shfl_xor_sync(0xffffffffu, m0, 1));
        m0 = fmaxf(m0, __shfl_xor_sync(0xffffffffu, m0, 2));
        m1 = fmaxf(m1, __shfl_xor_sync(0xffffffffu, m1, 1));
        m1 = fmaxf(m1, __shfl_xor_sync(0xffffffffu, m1, 2));
        float s0 = 0.f, s1 = 0.f;
#pragma unroll
        for (int ni = 0; ni < 8; ni++) {
            s[ni][0] = __expf(s[ni][0] - m0); s0 += s[ni][0];
            s[ni][1] = __expf(s[ni][1] - m0); s0 += s[ni][1];
            s[ni][2] = __expf(s[ni][2] - m1); s1 += s[ni][2];
            s[ni][3] = __expf(s[ni][3] - m1); s1 += s[ni][3];
        }
        s0 += __shfl_xor_sync(0xffffffffu, s0, 1);
        s0 += __shfl_xor_sync(0xffffffffu, s0, 2);
        s1 += __shfl_xor_sync(0xffffffffu, s1, 1);
        s1 += __shfl_xor_sync(0xffffffffu, s1, 2);
        float inv0 = 1.f / s0, inv1 = 1.f / s1;
        unsigned pv[4][4];
#pragma unroll
        for (int js = 0; js < 4; js++) {
            pv[js][0] = h2u(__floats2half2_rn(s[2*js][0]   * inv0, s[2*js][1]   * inv0));
            pv[js][1] = h2u(__floats2half2_rn(s[2*js][2]   * inv1, s[2*js][3]   * inv1));
            pv[js][2] = h2u(__floats2half2_rn(s[2*js+1][0] * inv0, s[2*js+1][1] * inv0));
            pv[js][3] = h2u(__floats2half2_rn(s[2*js+1][2] * inv1, s[2*js+1][3] * inv1));
        }
        float o[4][4];
#pragma unroll
        for (int nd = 0; nd < 4; nd++)
#pragma unroll
            for (int e = 0; e < 4; e++) o[nd][e] = 0.f;
        const __half* Vth = Vt + h * 2304;
#pragma unroll
        for (int p = 0; p < 2; p++)
#pragma unroll
            for (int js = 0; js < 4; js++) {
                unsigned vb[4];
                ldsm4(vb, Vth + (16 * p) * 72 + 16 * js + voff);
                mma16(o[2*p],     pv[js], vb[0], vb[1]);
                mma16(o[2*p + 1], pv[js], vb[2], vb[3]);
            }
#pragma unroll
        for (int nd = 0; nd < 4; nd++) {
            int d0 = 8 * nd + 2 * tg;
            *(__half2*)(smA + h * 2560 + i0 * 40 + d0) =
                __floats2half2_rn(o[nd][0], o[nd][1]);
            *(__half2*)(smA + h * 2560 + (i0 + 8) * 40 + d0) =
                __floats2half2_rn(o[nd][2], o[nd][3]);
        }
    }

    // ---------- fused proj+merge GEMM: 64x192 = smA @ Wc^T ----------
#pragma unroll
    for (int i = 0; i < 6; i++)
        rb[i] = *(const uint2*)(w_ch + (size_t)(r0 + 32 * i) * 192 + c4);
    __syncthreads();
#pragma unroll
    for (int i = 0; i < 6; i++)
        *(uint2*)(smB2 + stsO + 1280 * i) = rb[i];
    __syncthreads();

    {
        float acc[2][6][4];
#pragma unroll
        for (int a = 0; a < 2; a++)
#pragma unroll
            for (int b_ = 0; b_ < 6; b_++)
#pragma unroll
                for (int e = 0; e < 4; e++) acc[a][b_][e] = 0.f;

#pragma unroll 1
        for (int kc = 0; kc < 6; kc++) {
            if (kc + 1 < 6)
#pragma unroll
                for (int i = 0; i < 6; i++)
                    rb[i] = *(const uint2*)(w_ch + (size_t)(r0 + 32 * i) * 192 + (kc + 1) * 32 + c4);
            const __half* Ab = smA + kc * 2560;
            const __half* Bb = smB2 + (kc & 1) * 7680;
#pragma unroll
            for (int kk = 0; kk < 32; kk += 16) {
                unsigned af[2][4], bb[3][4];
                ldsm4(af[0], Ab + wr * 40 + kk + aoff);
                ldsm4(af[1], Ab + (wr + 16) * 40 + kk + aoff);
#pragma unroll
                for (int p = 0; p < 3; p++)
                    ldsm4(bb[p], Bb + (wc + 16 * p) * 40 + kk + boff);
#pragma unroll
                for (int m2 = 0; m2 < 2; m2++)
#pragma unroll
                    for (int ni = 0; ni < 6; ni++)
                        mma16(acc[m2][ni], af[m2], bb[ni >> 1][(ni & 1) * 2], bb[ni >> 1][(ni & 1) * 2 + 1]);
            }
            if (kc + 1 < 6)
#pragma unroll
                for (int i = 0; i < 6; i++)
                    *(uint2*)(smB2 + ((kc + 1) & 1) * 7680 + stsO + 1280 * i) = rb[i];
            __syncthreads();
        }

#pragma unroll
        for (int m2 = 0; m2 < 2; m2++)
#pragma unroll
            for (int ni = 0; ni < 6; ni++) {
                int row = wr + 16 * m2 + g;
                int col = wc + 8 * ni + 2 * tg;
                St[row * 200 + col]           = acc[m2][ni][0];
                St[row * 200 + col + 1]       = acc[m2][ni][1];
                St[(row + 8) * 200 + col]     = acc[m2][ni][2];
                St[(row + 8) * 200 + col + 1] = acc[m2][ni][3];
            }
    }
    __syncthreads();

    // ---------- LN1 + shortcut(from g_xth) -> x1h into smA (fc1 A-layout) ----------
    int wp = tid >> 5, l = tid & 31;
#pragma unroll 1
    for (int rr = 0; rr < 8; rr++) {
        int n = wp * 8 + rr;
        float vv[6]; float su = 0.f;
#pragma unroll
        for (int u = 0; u < 6; u++) {
            int c = l + 32 * u;
            vv[u] = St[n * 200 + c] + g_bc[c];
            su += vv[u];
        }
        su = warp_sum(su);
        float mean = su * (1.f / 192.f);
        float sq = 0.f;
#pragma unroll
        for (int u = 0; u < 6; u++) { float d = vv[u] - mean; sq += d * d; }
        sq = warp_sum(sq);
        float rstd = rsqrtf(sq * (1.f / 192.f) + 1e-5f);
#pragma unroll
        for (int u = 0; u < 6; u++) {
            int c = l + 32 * u;
            float y = (vv[u] - mean) * rstd * n1g[c] + n1b[c]
                      + __half2float(xsrc[(size_t)n * 192 + c]);
            smA[u * 2560 + n * 40 + l] = __float2half_rn(y);
        }
    }
    __syncthreads();

    // ---------- MLP: fc1 + GELU + fc2 (A = x1h in smA) ----------
    float acc2[2][6][4];
#pragma unroll
    for (int a = 0; a < 2; a++)
#pragma unroll
        for (int b_ = 0; b_ < 6; b_++)
#pragma unroll
            for (int cc = 0; cc < 4; cc++) acc2[a][b_][cc] = 0.f;

#pragma unroll 1
    for (int oc = 0; oc < 8; oc++) {
        const __half* W1 = w_f1h + (size_t)(oc * 96) * 192;
        uint2 rb1[3];
#pragma unroll
        for (int i = 0; i < 3; i++)
            rb1[i] = *(const uint2*)(W1 + (size_t)(r0 + 32 * i) * 192 + c4);
#pragma unroll
        for (int i = 0; i < 3; i++)
            *(uint2*)(smB1m + stsO + 1280 * i) = rb1[i];
        __syncthreads();

        float acc1[2][3][4];
#pragma unroll
        for (int a = 0; a < 2; a++)
#pragma unroll
            for (int b_ = 0; b_ < 3; b_++)
#pragma unroll
                for (int cc = 0; cc < 4; cc++) acc1[a][b_][cc] = 0.f;

#pragma unroll 1
        for (int kc = 0; kc < 6; kc++) {
            if (kc + 1 < 6)
#pragma unroll
                for (int i = 0; i < 3; i++)
                    rb1[i] = *(const uint2*)(W1 + (size_t)(r0 + 32 * i) * 192 + (kc + 1) * 32 + c4);
            const __half* Ab = smA + kc * 2560;
            const __half* Bb = smB1m + (kc & 1) * 3840;
#pragma unroll
            for (int kk = 0; kk < 32; kk += 16) {
                unsigned af[2][4], b1r[4], b1s[2];
                ldsm4(af[0], Ab + wr * 40 + kk + aoff);
                ldsm4(af[1], Ab + (wr + 16) * 40 + kk + aoff);
                ldsm4(b1r, Bb + wc1 * 40 + kk + boff);
                ldsm2(b1s, Bb + (wc1 + 16) * 40 + kk + b2off);
#pragma unroll
                for (int m2 = 0; m2 < 2; m2++) {
                    mma16(acc1[m2][0], af[m2], b1r[0], b1r[1]);
                    mma16(acc1[m2][1], af[m2], b1r[2], b1r[3]);
                    mma16(acc1[m2][2], af[m2], b1s[0], b1s[1]);
                }
            }
            if (kc + 1 < 6)
#pragma unroll
                for (int i = 0; i < 3; i++)
                    *(uint2*)(smB1m + ((kc + 1) & 1) * 3840 + stsO + 1280 * i) = rb1[i];
            __syncthreads();
        }

#pragma unroll
        for (int m2 = 0; m2 < 2; m2++)
#pragma unroll
            for (int ni = 0; ni < 3; ni++) {
                int row = wr + 16 * m2 + g;
                int col = wc1 + 8 * ni + 2 * tg;
                float2 bv = *(const float2*)(b1h + oc * 96 + col);
                __half* hp0 = smHm + (col >> 5) * 2560 + row * 40 + (col & 31);
                *(__half2*)hp0 = __floats2half2_rn(
                    gelu_f(acc1[m2][ni][0] + bv.x), gelu_f(acc1[m2][ni][1] + bv.y));
                *(__half2*)(hp0 + 320) = __floats2half2_rn(
                    gelu_f(acc1[m2][ni][2] + bv.x), gelu_f(acc1[m2][ni][3] + bv.y));
            }

        const __half* W2 = w_f2h;
        uint2 rb2[6];
#pragma unroll
        for (int i = 0; i < 6; i++)
            rb2[i] = *(const uint2*)(W2 + (size_t)(r0 + 32 * i) * 768 + oc * 96 + c4);
#pragma unroll
        for (int i = 0; i < 6; i++)
            *(uint2*)(smB2m + stsO + 1280 * i) = rb2[i];
        __syncthreads();

#pragma unroll 1
        for (int kc = 0; kc < 3; kc++) {
            if (kc + 1 < 3)
#pragma unroll
                for (int i = 0; i < 6; i++)
                    rb2[i] = *(const uint2*)(W2 + (size_t)(r0 + 32 * i) * 768 + oc * 96 + (kc + 1) * 32 + c4);
            const __half* Ab = smHm + kc * 2560;
            const __half* Bb = smB2m + (kc & 1) * 7680;
#pragma unroll
            for (int kk = 0; kk < 32; kk += 16) {
                unsigned af[2][4], bb[3][4];
                ldsm4(af[0], Ab + wr * 40 + kk + aoff);
                ldsm4(af[1], Ab + (wr + 16) * 40 + kk + aoff);
#pragma unroll
                for (int p = 0; p < 3; p++)
                    ldsm4(bb[p], Bb + (wc + 16 * p) * 40 + kk + boff);
#pragma unroll
                for (int m2 = 0; m2 < 2; m2++)
#pragma unroll
                    for (int ni = 0; ni < 6; ni++)
                        mma16(acc2[m2][ni], af[m2], bb[ni >> 1][(ni & 1) * 2], bb[ni >> 1][(ni & 1) * 2 + 1]);
            }
            if (kc + 1 < 3)
#pragma unroll
                for (int i = 0; i < 6; i++)
                    *(uint2*)(smB2m + ((kc + 1) & 1) * 7680 + stsO + 1280 * i) = rb2[i];
            __syncthreads();
        }
    }

    // ---------- final: bias + LN2 + residual(x1h) + pixel scatter ----------
#pragma unroll
    for (int m2 = 0; m2 < 2; m2++)
#pragma unroll
        for (int ni = 0; ni < 6; ni++) {
            int row = wr + 16 * m2 + g;
            int col = wc + 8 * ni + 2 * tg;
            St[row * 200 + col]           = acc2[m2][ni][0];
            St[row * 200 + col + 1]       = acc2[m2][ni][1];
            St[(row + 8) * 200 + col]     = acc2[m2][ni][2];
            St[(row + 8) * 200 + col + 1] = acc2[m2][ni][3];
        }
    __syncthreads();
#pragma unroll 1
    for (int rr = 0; rr < 8; rr++) {
        int n = wp * 8 + rr;
        int hpx = (wh * 8 + (n >> 3) + 4) & 255;
        int wpx = (ww * 8 + (n & 7) + 4) & 255;
        size_t row = ((size_t)bI * HWd + hpx * Wdim + wpx) * Cd;
        float vv[6]; float su = 0.f;
#pragma unroll
        for (int u = 0; u < 6; u++) {
            int c = l + 32 * u;
            vv[u] = St[n * 200 + c] + b2[c];
            su += vv[u];
        }
        su = warp_sum(su);
        float mean = su * (1.f / 192.f);
        float sq = 0.f;
#pragma unroll
        for (int u = 0; u < 6; u++) { float d = vv[u] - mean; sq += d * d; }
        sq = warp_sum(sq);
        float rstd = rsqrtf(sq * (1.f / 192.f) + 1e-5f);
#pragma unroll
        for (int u = 0; u < 6; u++) {
            int c = l + 32 * u;
            float x1v = __half2float(smA[u * 2560 + n * 40 + l]);
            out[row + c] = x1v + (vv[u] - mean) * rstd * g2[c] + bb2[c];
        }
    }
}

// ======================= host =======================
extern "C" void kernel_launch(void* const* d_in, const int* in_sizes, int n_in,
                              void* d_out, int out_size)
{
    const float* x    = (const float*)d_in[0];
    const float* feat = (const float*)d_in[1];
    const int*   ridx = (const int*)  d_in[3];
    const float* rtab = (const float*)d_in[4];
    const float* q_w  = (const float*)d_in[5];
    const float* q_b  = (const float*)d_in[6];
    const float* kv_w = (const float*)d_in[7];
    const float* kv_b = (const float*)d_in[8];
    const float* p_w  = (const float*)d_in[9];
    const float* p_b  = (const float*)d_in[10];
    const float* m_w  = (const float*)d_in[11];
    const float* n1g  = (const float*)d_in[12];
    const float* n1b  = (const float*)d_in[13];
    const float* n2g  = (const float*)d_in[14];
    const float* n2b  = (const float*)d_in[15];
    const float* f1w  = (const float*)d_in[16];
    const float* f1b  = (const float*)d_in[17];
    const float* f2w  = (const float*)d_in[18];
    const float* f2b  = (const float*)d_in[19];
    float* out = (float*)d_out;

    __half *dxth, *dfth;
    cudaGetSymbolAddress((void**)&dxth, g_xth);
    cudaGetSymbolAddress((void**)&dfth, g_fth);

    const int smMega = 52224 * 2;                        // 104448
    cudaFuncSetAttribute(k_mega, cudaFuncAttributeMaxDynamicSharedMemorySize, smMega);

    k_prepw<<<1584, 256>>>(q_w, kv_w, f1w, f2w);                      // 0
    k_wcomb<<<144, 256>>>(m_w, p_w, p_b);                             // 1
    k_bias <<<96, 256>>>(ridx, rtab);                                 // 2
    k_transpose<<<dim3(6, 2048, 4), dim3(32, 8)>>>(x, dxth);          // 3
    k_transpose<<<dim3(6, 2048, 4), dim3(32, 8)>>>(feat, dfth);       // 4
    k_mega <<<NWINd, 256, smMega>>>(q_b, kv_b, n1g, n1b, f1b, f2b, n2g, n2b, out);  // 5
}